// round 1
// baseline (speedup 1.0000x reference)
#include <cuda_runtime.h>
#include <math.h>

// ---------------- problem constants ----------------
#define DIMM   1024
#define NHEADS 8
#define DHEAD  128
#define NTOK   2049          // 2048 + cls
#define BATCH  2
#define MROWS  (BATCH*NTOK)  // 4098
#define HID    4096          // 4*DIM
#define L_HEAD 4
#define L_TAIL 4

// ---------------- scratch (device globals: no allocation allowed) ----------------
__device__ float g_x  [(size_t)MROWS*DIMM];      // 16.8 MB
__device__ float g_qkv[(size_t)MROWS*3*DIMM];    // 50.3 MB
__device__ float g_att[(size_t)MROWS*DIMM];      // 16.8 MB
__device__ float g_h  [(size_t)MROWS*HID];       // 67.1 MB
__device__ float g_cls[(size_t)BATCH*DIMM];

// ---------------- concat cls + x ----------------
__global__ void concat_kernel(const float* __restrict__ x,
                              const float* __restrict__ cls,
                              float* __restrict__ gx)
{
    int idx = blockIdx.x * blockDim.x + threadIdx.x;
    int total = MROWS * DIMM;
    if (idx >= total) return;
    int d = idx % DIMM;
    int row = idx / DIMM;          // b*NTOK + n
    int n = row % NTOK;
    int b = row / NTOK;
    float v;
    if (n == 0) v = cls[d];
    else        v = x[((size_t)b*(NTOK-1) + (n-1))*DIMM + d];
    gx[idx] = v;
}

// ---------------- generic fp32 SGEMM with fused epilogue ----------------
// C[M,N] = A[M,K] @ W[K,N]  (+bias[N]) (GELU) (+R[M,N])
#define BM 128
#define BN 64
#define BKT 16

template<bool BIAS, bool RESID, bool DOGELU>
__global__ __launch_bounds__(256)
void sgemm_kernel(const float* __restrict__ A, const float* __restrict__ W,
                  const float* __restrict__ bias, const float* __restrict__ R,
                  float* __restrict__ C, int M, int K, int N)
{
    __shared__ float As[BKT][BM + 4];
    __shared__ float Bs[BKT][BN + 4];

    const int t  = threadIdx.x;
    const int tx = t & 15;       // N direction, 4 cols each
    const int ty = t >> 4;       // M direction, 8 rows each
    const int bm = blockIdx.y * BM;
    const int bn = blockIdx.x * BN;

    float acc[8][4];
#pragma unroll
    for (int i = 0; i < 8; i++)
#pragma unroll
        for (int j = 0; j < 4; j++) acc[i][j] = 0.f;

    // A tile load mapping: 128x16 floats = 512 float4, 2 per thread
    const int arow0 = t >> 2,          ak0 = (t & 3) * 4;
    const int arow1 = (t + 256) >> 2,  ak1 = (t & 3) * 4;  // (t+256)&3 == t&3
    // B tile load mapping: 16x64 floats = 256 float4, 1 per thread
    const int bkr = t >> 4, bnc = (t & 15) * 4;

    for (int k0 = 0; k0 < K; k0 += BKT) {
        // load A (guarded rows, store transposed)
        {
            int gr = bm + arow0;
            float4 v = make_float4(0.f, 0.f, 0.f, 0.f);
            if (gr < M) v = *(const float4*)(A + (size_t)gr * K + k0 + ak0);
            As[ak0+0][arow0] = v.x; As[ak0+1][arow0] = v.y;
            As[ak0+2][arow0] = v.z; As[ak0+3][arow0] = v.w;

            gr = bm + arow1;
            float4 u = make_float4(0.f, 0.f, 0.f, 0.f);
            if (gr < M) u = *(const float4*)(A + (size_t)gr * K + k0 + ak1);
            As[ak1+0][arow1] = u.x; As[ak1+1][arow1] = u.y;
            As[ak1+2][arow1] = u.z; As[ak1+3][arow1] = u.w;
        }
        // load B
        {
            float4 v = *(const float4*)(W + (size_t)(k0 + bkr) * N + bn + bnc);
            *(float4*)&Bs[bkr][bnc] = v;
        }
        __syncthreads();

#pragma unroll
        for (int kk = 0; kk < BKT; kk++) {
            float4 a0 = *(const float4*)&As[kk][ty * 8];
            float4 a1 = *(const float4*)&As[kk][ty * 8 + 4];
            float4 b  = *(const float4*)&Bs[kk][tx * 4];
            float av[8] = {a0.x, a0.y, a0.z, a0.w, a1.x, a1.y, a1.z, a1.w};
            float bv[4] = {b.x, b.y, b.z, b.w};
#pragma unroll
            for (int i = 0; i < 8; i++)
#pragma unroll
                for (int j = 0; j < 4; j++)
                    acc[i][j] = fmaf(av[i], bv[j], acc[i][j]);
        }
        __syncthreads();
    }

#pragma unroll
    for (int i = 0; i < 8; i++) {
        int gr = bm + ty * 8 + i;
        if (gr >= M) continue;
#pragma unroll
        for (int j = 0; j < 4; j++) {
            int gc = bn + tx * 4 + j;
            float v = acc[i][j];
            if (BIAS)   v += bias[gc];
            if (DOGELU) v = 0.5f * v * (1.f + erff(v * 0.70710678118f));
            if (RESID)  v += R[(size_t)gr * N + gc];
            C[(size_t)gr * N + gc] = v;
        }
    }
}

// ---------------- attention: one warp per (b, h, query row) ----------------
// qkv rows: [3][HEADS][DHEAD] per token; scale = DIM^-0.5 = 1/32 (reference uses full dim!)
__global__ __launch_bounds__(256)
void attn_kernel(const float* __restrict__ qkv, float* __restrict__ out)
{
    const int warp = (blockIdx.x * blockDim.x + threadIdx.x) >> 5;
    const int lane = threadIdx.x & 31;
    const int total = BATCH * NHEADS * NTOK;
    if (warp >= total) return;

    const int i  = warp % NTOK;
    const int bh = warp / NTOK;
    const int h  = bh % NHEADS;
    const int b  = bh / NHEADS;

    const float scale = 0.03125f;  // 1024^-0.5

    const float* qp = qkv + ((size_t)(b * NTOK + i)) * 3072 + h * DHEAD + lane * 4;
    float4 q = *(const float4*)qp;
    q.x *= scale; q.y *= scale; q.z *= scale; q.w *= scale;

    const float* kbase = qkv + ((size_t)b * NTOK) * 3072 + 1024 + h * DHEAD + lane * 4;
    const float* vbase = kbase + 1024;

    float m = -INFINITY, l = 0.f;
    float4 acc = make_float4(0.f, 0.f, 0.f, 0.f);

    for (int j = 0; j <= i; j++) {
        const size_t off = (size_t)j * 3072;
        float4 kk = *(const float4*)(kbase + off);
        float s = q.x * kk.x + q.y * kk.y + q.z * kk.z + q.w * kk.w;
        s += __shfl_xor_sync(0xFFFFFFFFu, s, 16);
        s += __shfl_xor_sync(0xFFFFFFFFu, s, 8);
        s += __shfl_xor_sync(0xFFFFFFFFu, s, 4);
        s += __shfl_xor_sync(0xFFFFFFFFu, s, 2);
        s += __shfl_xor_sync(0xFFFFFFFFu, s, 1);

        float4 vv = *(const float4*)(vbase + off);
        float mn = fmaxf(m, s);
        float p    = __expf(s - mn);
        float corr = __expf(m - mn);   // first iter: exp(-inf)=0
        l = l * corr + p;
        acc.x = acc.x * corr + p * vv.x;
        acc.y = acc.y * corr + p * vv.y;
        acc.z = acc.z * corr + p * vv.z;
        acc.w = acc.w * corr + p * vv.w;
        m = mn;
    }

    const float inv = 1.f / l;
    float* op = out + ((size_t)(b * NTOK + i)) * DIMM + h * DHEAD + lane * 4;
    op[0] = acc.x * inv; op[1] = acc.y * inv; op[2] = acc.z * inv; op[3] = acc.w * inv;
}

// ---------------- save cls tokens after head stack ----------------
__global__ void save_cls_kernel(const float* __restrict__ gx, float* __restrict__ gcls)
{
    int idx = blockIdx.x * blockDim.x + threadIdx.x;
    if (idx >= BATCH * DIMM) return;
    int b = idx / DIMM, d = idx % DIMM;
    gcls[idx] = gx[((size_t)b * NTOK) * DIMM + d];
}

// ---------------- write final output: [x_tail | cls] ----------------
__global__ void write_out_kernel(const float* __restrict__ gx,
                                 const float* __restrict__ gcls,
                                 float* __restrict__ out)
{
    const int totalx = MROWS * DIMM;
    const int totalc = BATCH * DIMM;
    int idx = blockIdx.x * blockDim.x + threadIdx.x;
    if (idx < totalx)               out[idx] = gx[idx];
    else if (idx < totalx + totalc) out[idx] = gcls[idx - totalx];
}

// ---------------- host orchestration ----------------
static void run_layer(const float* Wqkv, const float* Wo, const float* bo,
                      const float* W1, const float* b1,
                      const float* W2, const float* b2,
                      float* x, float* qkv, float* att, float* hbuf)
{
    const int gy = (MROWS + BM - 1) / BM;  // 33
    // qkv = x @ Wqkv
    sgemm_kernel<false,false,false><<<dim3(3*DIMM/BN, gy), 256>>>(
        x, Wqkv, nullptr, nullptr, qkv, MROWS, DIMM, 3*DIMM);
    // attention
    {
        int warps = BATCH * NHEADS * NTOK;
        int blocks = (warps + 7) / 8;
        attn_kernel<<<blocks, 256>>>(qkv, att);
    }
    // x = x + att @ Wo + bo
    sgemm_kernel<true,true,false><<<dim3(DIMM/BN, gy), 256>>>(
        att, Wo, bo, x, x, MROWS, DIMM, DIMM);
    // h = gelu(x @ W1 + b1)
    sgemm_kernel<true,false,true><<<dim3(HID/BN, gy), 256>>>(
        x, W1, b1, nullptr, hbuf, MROWS, DIMM, HID);
    // x = x + h @ W2 + b2
    sgemm_kernel<true,true,false><<<dim3(DIMM/BN, gy), 256>>>(
        hbuf, W2, b2, x, x, MROWS, HID, DIMM);
}

extern "C" void kernel_launch(void* const* d_in, const int* in_sizes, int n_in,
                              void* d_out, int out_size)
{
    const float* x_in = (const float*)d_in[0];
    const float* cls  = (const float*)d_in[1];
    const float* hW[7];
    const float* tW[7];
    for (int i = 0; i < 7; i++) hW[i] = (const float*)d_in[2 + i];
    for (int i = 0; i < 7; i++) tW[i] = (const float*)d_in[9 + i];

    float *gx, *gqkv, *gatt, *gh, *gcls;
    cudaGetSymbolAddress((void**)&gx,   g_x);
    cudaGetSymbolAddress((void**)&gqkv, g_qkv);
    cudaGetSymbolAddress((void**)&gatt, g_att);
    cudaGetSymbolAddress((void**)&gh,   g_h);
    cudaGetSymbolAddress((void**)&gcls, g_cls);

    // concat cls + x -> g_x
    {
        int total = MROWS * DIMM;
        concat_kernel<<<(total + 255) / 256, 256>>>(x_in, cls, gx);
    }

    // per-layer weight strides (elements)
    const size_t sQKV = (size_t)DIMM * 3 * DIMM;
    const size_t sWO  = (size_t)DIMM * DIMM;
    const size_t sBO  = DIMM;
    const size_t sW1  = (size_t)DIMM * HID;
    const size_t sB1  = HID;
    const size_t sW2  = (size_t)HID * DIMM;
    const size_t sB2  = DIMM;

    for (int l = 0; l < L_HEAD; l++)
        run_layer(hW[0] + l*sQKV, hW[1] + l*sWO, hW[2] + l*sBO,
                  hW[3] + l*sW1,  hW[4] + l*sB1, hW[5] + l*sW2, hW[6] + l*sB2,
                  gx, gqkv, gatt, gh);

    save_cls_kernel<<<(BATCH*DIMM + 255)/256, 256>>>(gx, gcls);

    for (int l = 0; l < L_TAIL; l++)
        run_layer(tW[0] + l*sQKV, tW[1] + l*sWO, tW[2] + l*sBO,
                  tW[3] + l*sW1,  tW[4] + l*sB1, tW[5] + l*sW2, tW[6] + l*sB2,
                  gx, gqkv, gatt, gh);

    {
        int total = MROWS * DIMM + BATCH * DIMM;
        write_out_kernel<<<(total + 255)/256, 256>>>(gx, gcls, (float*)d_out);
    }
}

// round 2
// speedup vs baseline: 1.3313x; 1.3313x over previous
#include <cuda_runtime.h>
#include <cuda_bf16.h>
#include <math.h>

// ---------------- problem constants ----------------
#define DIMM   1024
#define NHEADS 8
#define DHEAD  128
#define NTOK   2049          // 2048 + cls
#define BATCH  2
#define MROWS  (BATCH*NTOK)  // 4098
#define HID    4096          // 4*DIM
#define L_HEAD 4
#define L_TAIL 4

// ---------------- scratch (device globals: no allocation allowed) ----------------
__device__ float g_x  [(size_t)MROWS*DIMM];
__device__ float g_qkv[(size_t)MROWS*3*DIMM];
__device__ float g_att[(size_t)MROWS*DIMM];
__device__ float g_h  [(size_t)MROWS*HID];
__device__ float g_cls[(size_t)BATCH*DIMM];

// ---------------- concat cls + x ----------------
__global__ void concat_kernel(const float* __restrict__ x,
                              const float* __restrict__ cls,
                              float* __restrict__ gx)
{
    int idx = blockIdx.x * blockDim.x + threadIdx.x;
    int total = MROWS * DIMM;
    if (idx >= total) return;
    int d = idx % DIMM;
    int row = idx / DIMM;
    int n = row % NTOK;
    int b = row / NTOK;
    float v;
    if (n == 0) v = cls[d];
    else        v = x[((size_t)b*(NTOK-1) + (n-1))*DIMM + d];
    gx[idx] = v;
}

// ---------------- bf16 helpers ----------------
__device__ __forceinline__ unsigned short f2bf(float x) {
    __nv_bfloat16 h = __float2bfloat16(x);
    return *reinterpret_cast<unsigned short*>(&h);
}
__device__ __forceinline__ float bf2f(unsigned short s) {
    __nv_bfloat16 h = *reinterpret_cast<__nv_bfloat16*>(&s);
    return __bfloat162float(h);
}
__device__ __forceinline__ void split_bf16(float x, unsigned short& hi, unsigned short& lo) {
    hi = f2bf(x);
    lo = f2bf(x - bf2f(hi));
}

__device__ __forceinline__ void mma_bf16(float* c, const unsigned* a, const unsigned* b) {
    asm("mma.sync.aligned.m16n8k16.row.col.f32.bf16.bf16.f32 "
        "{%0,%1,%2,%3}, {%4,%5,%6,%7}, {%8,%9}, {%0,%1,%2,%3};"
        : "+f"(c[0]), "+f"(c[1]), "+f"(c[2]), "+f"(c[3])
        : "r"(a[0]), "r"(a[1]), "r"(a[2]), "r"(a[3]),
          "r"(b[0]), "r"(b[1]));
}

// ---------------- tensor-core GEMM (3xBF16 hi/lo split) ----------------
// C[M,N] = A[M,K] @ W[K,N]  (+bias[N]) (GELU) (+R[M,N])
// BM=128 BN=128 BK=32, 256 threads, warp tile 64x32 (2x4 warp grid)
#define TBM 128
#define TBN 128
#define TBK 32
#define PA  40    // shorts per A smem row (BK + 8 pad)  -> conflict-free frag LDS
#define BROW 136  // words per B k2-row (BN + 8 pad)     -> conflict-free frag LDS

// per-buffer smem (bytes):
//   AsH: 128*40*2 = 10240, AsL: 10240, BsH: 16*136*4 = 8704, BsL: 8704  => 37888
#define SM_AH 0
#define SM_AL 10240
#define SM_BH 20480
#define SM_BL 29184
#define SM_BUF 37888
#define SM_TOTAL (2*SM_BUF)   // 75776

template<bool BIAS, bool RESID, bool DOGELU>
__global__ __launch_bounds__(256, 1)
void tgemm_kernel(const float* __restrict__ A, const float* __restrict__ W,
                  const float* __restrict__ bias, const float* __restrict__ R,
                  float* __restrict__ C, int M, int K, int N)
{
    extern __shared__ char smem[];

    const int t    = threadIdx.x;
    const int warp = t >> 5;
    const int lane = t & 31;
    const int g    = lane >> 2;   // group 0..7
    const int q    = lane & 3;    // 0..3
    const int wm   = warp & 1;    // 0..1 -> 64-row slab
    const int wn   = warp >> 1;   // 0..3 -> 32-col slab
    const int bm   = blockIdx.y * TBM;
    const int bn   = blockIdx.x * TBN;

    float acc[4][4][4];
#pragma unroll
    for (int i = 0; i < 4; i++)
#pragma unroll
        for (int j = 0; j < 4; j++)
#pragma unroll
            for (int e = 0; e < 4; e++) acc[i][j][e] = 0.f;

    // load mappings (per thread: 4 float4 of A, 4 float4 of B)
    int arow[4], akc[4], bkr[4], bnc[4];
#pragma unroll
    for (int i = 0; i < 4; i++) {
        int idx = i * 256 + t;
        arow[i] = idx >> 3;          // 0..127
        akc[i]  = (idx & 7) * 4;     // 0..28
        bkr[i]  = idx >> 5;          // 0..31
        bnc[i]  = (idx & 31) * 4;    // 0..124
    }

    const int steps = K / TBK;
    float4 ar[4], br[4];

    // prologue: load tile 0
#pragma unroll
    for (int i = 0; i < 4; i++) {
        int gr = bm + arow[i];
        ar[i] = make_float4(0.f, 0.f, 0.f, 0.f);
        if (gr < M) ar[i] = *(const float4*)(A + (size_t)gr * K + akc[i]);
        br[i] = *(const float4*)(W + (size_t)bkr[i] * N + bn + bnc[i]);
    }

    int p = 0;
    for (int s = 0; s < steps; s++) {
        // ---- stage regs -> smem buffer p ----
        {
            char* buf = smem + p * SM_BUF;
            unsigned* AH = (unsigned*)(buf + SM_AH);
            unsigned* AL = (unsigned*)(buf + SM_AL);
            unsigned short* BH = (unsigned short*)(buf + SM_BH);
            unsigned short* BL = (unsigned short*)(buf + SM_BL);
#pragma unroll
            for (int i = 0; i < 4; i++) {
                float av[4] = {ar[i].x, ar[i].y, ar[i].z, ar[i].w};
                unsigned short h[4], l[4];
#pragma unroll
                for (int e = 0; e < 4; e++) split_bf16(av[e], h[e], l[e]);
                int wi = (arow[i] * PA + akc[i]) >> 1;
                AH[wi]     = (unsigned)h[0] | ((unsigned)h[1] << 16);
                AH[wi + 1] = (unsigned)h[2] | ((unsigned)h[3] << 16);
                AL[wi]     = (unsigned)l[0] | ((unsigned)l[1] << 16);
                AL[wi + 1] = (unsigned)l[2] | ((unsigned)l[3] << 16);

                float bv[4] = {br[i].x, br[i].y, br[i].z, br[i].w};
                int half = bkr[i] & 1;
                int wb   = (bkr[i] >> 1) * BROW + bnc[i];
#pragma unroll
                for (int e = 0; e < 4; e++) {
                    unsigned short bh, bl;
                    split_bf16(bv[e], bh, bl);
                    BH[(wb + e) * 2 + half] = bh;
                    BL[(wb + e) * 2 + half] = bl;
                }
            }
        }
        __syncthreads();

        // ---- prefetch next tile into regs ----
        if (s + 1 < steps) {
            int k0 = (s + 1) * TBK;
#pragma unroll
            for (int i = 0; i < 4; i++) {
                int gr = bm + arow[i];
                ar[i] = make_float4(0.f, 0.f, 0.f, 0.f);
                if (gr < M) ar[i] = *(const float4*)(A + (size_t)gr * K + k0 + akc[i]);
                br[i] = *(const float4*)(W + (size_t)(k0 + bkr[i]) * N + bn + bnc[i]);
            }
        }

        // ---- compute on buffer p ----
        {
            const char* buf = smem + p * SM_BUF;
            const unsigned* AH = (const unsigned*)(buf + SM_AH);
            const unsigned* AL = (const unsigned*)(buf + SM_AL);
            const unsigned* BHw = (const unsigned*)(buf + SM_BH);
            const unsigned* BLw = (const unsigned*)(buf + SM_BL);
            const int m0 = wm * 64;
            const int nb0 = wn * 32 + g;
#pragma unroll
            for (int ko = 0; ko < 2; ko++) {     // k offsets 0,16
                const int kofs = ko * 16;
                unsigned bh[4][2], bl[4][2];
#pragma unroll
                for (int ni = 0; ni < 4; ni++) {
                    int nb = nb0 + ni * 8;
                    bh[ni][0] = BHw[(q + ko * 8) * BROW + nb];
                    bh[ni][1] = BHw[(q + 4 + ko * 8) * BROW + nb];
                    bl[ni][0] = BLw[(q + ko * 8) * BROW + nb];
                    bl[ni][1] = BLw[(q + 4 + ko * 8) * BROW + nb];
                }
#pragma unroll
                for (int mi = 0; mi < 4; mi++) {
                    int r0 = m0 + mi * 16 + g;
                    unsigned ah[4], al[4];
                    int w0 = (r0 * PA + 2 * q + kofs) >> 1;
                    int w1 = ((r0 + 8) * PA + 2 * q + kofs) >> 1;
                    ah[0] = AH[w0];     ah[1] = AH[w1];
                    ah[2] = AH[w0 + 4]; ah[3] = AH[w1 + 4];
                    al[0] = AL[w0];     al[1] = AL[w1];
                    al[2] = AL[w0 + 4]; al[3] = AL[w1 + 4];
#pragma unroll
                    for (int ni = 0; ni < 4; ni++) {
                        mma_bf16(acc[mi][ni], ah, bh[ni]);
                        mma_bf16(acc[mi][ni], ah, bl[ni]);
                        mma_bf16(acc[mi][ni], al, bh[ni]);
                    }
                }
            }
        }
        p ^= 1;
    }

    // ---- epilogue ----
#pragma unroll
    for (int mi = 0; mi < 4; mi++) {
        int rbase = bm + wm * 64 + mi * 16 + g;
#pragma unroll
        for (int ni = 0; ni < 4; ni++) {
            int cbase = bn + wn * 32 + ni * 8 + 2 * q;
#pragma unroll
            for (int e = 0; e < 4; e++) {
                int gr = rbase + (e >= 2 ? 8 : 0);
                int gc = cbase + (e & 1);
                if (gr >= M) continue;
                float v = acc[mi][ni][e];
                if (BIAS)   v += bias[gc];
                if (DOGELU) v = 0.5f * v * (1.f + erff(v * 0.70710678118f));
                if (RESID)  v += R[(size_t)gr * N + gc];
                C[(size_t)gr * N + gc] = v;
            }
        }
    }
}

// ---------------- attention: one warp per (b, h, query row) ----------------
__global__ __launch_bounds__(256)
void attn_kernel(const float* __restrict__ qkv, float* __restrict__ out)
{
    const int warp = (blockIdx.x * blockDim.x + threadIdx.x) >> 5;
    const int lane = threadIdx.x & 31;
    const int total = BATCH * NHEADS * NTOK;
    if (warp >= total) return;

    const int i  = warp % NTOK;
    const int bh = warp / NTOK;
    const int h  = bh % NHEADS;
    const int b  = bh / NHEADS;

    const float scale = 0.03125f;  // 1024^-0.5

    const float* qp = qkv + ((size_t)(b * NTOK + i)) * 3072 + h * DHEAD + lane * 4;
    float4 q = *(const float4*)qp;
    q.x *= scale; q.y *= scale; q.z *= scale; q.w *= scale;

    const float* kbase = qkv + ((size_t)b * NTOK) * 3072 + 1024 + h * DHEAD + lane * 4;
    const float* vbase = kbase + 1024;

    float m = -INFINITY, l = 0.f;
    float4 acc = make_float4(0.f, 0.f, 0.f, 0.f);

    for (int j = 0; j <= i; j++) {
        const size_t off = (size_t)j * 3072;
        float4 kk = *(const float4*)(kbase + off);
        float s = q.x * kk.x + q.y * kk.y + q.z * kk.z + q.w * kk.w;
        s += __shfl_xor_sync(0xFFFFFFFFu, s, 16);
        s += __shfl_xor_sync(0xFFFFFFFFu, s, 8);
        s += __shfl_xor_sync(0xFFFFFFFFu, s, 4);
        s += __shfl_xor_sync(0xFFFFFFFFu, s, 2);
        s += __shfl_xor_sync(0xFFFFFFFFu, s, 1);

        float4 vv = *(const float4*)(vbase + off);
        float mn = fmaxf(m, s);
        float p    = __expf(s - mn);
        float corr = __expf(m - mn);
        l = l * corr + p;
        acc.x = acc.x * corr + p * vv.x;
        acc.y = acc.y * corr + p * vv.y;
        acc.z = acc.z * corr + p * vv.z;
        acc.w = acc.w * corr + p * vv.w;
        m = mn;
    }

    const float inv = 1.f / l;
    float* op = out + ((size_t)(b * NTOK + i)) * DIMM + h * DHEAD + lane * 4;
    op[0] = acc.x * inv; op[1] = acc.y * inv; op[2] = acc.z * inv; op[3] = acc.w * inv;
}

// ---------------- save cls tokens after head stack ----------------
__global__ void save_cls_kernel(const float* __restrict__ gx, float* __restrict__ gcls)
{
    int idx = blockIdx.x * blockDim.x + threadIdx.x;
    if (idx >= BATCH * DIMM) return;
    int b = idx / DIMM, d = idx % DIMM;
    gcls[idx] = gx[((size_t)b * NTOK) * DIMM + d];
}

// ---------------- write final output: [x_tail | cls] ----------------
__global__ void write_out_kernel(const float* __restrict__ gx,
                                 const float* __restrict__ gcls,
                                 float* __restrict__ out)
{
    const int totalx = MROWS * DIMM;
    const int totalc = BATCH * DIMM;
    int idx = blockIdx.x * blockDim.x + threadIdx.x;
    if (idx < totalx)               out[idx] = gx[idx];
    else if (idx < totalx + totalc) out[idx] = gcls[idx - totalx];
}

// ---------------- host orchestration ----------------
static void run_layer(const float* Wqkv, const float* Wo, const float* bo,
                      const float* W1, const float* b1,
                      const float* W2, const float* b2,
                      float* x, float* qkv, float* att, float* hbuf)
{
    const int gy = (MROWS + TBM - 1) / TBM;  // 33
    // qkv = x @ Wqkv
    tgemm_kernel<false,false,false><<<dim3(3*DIMM/TBN, gy), 256, SM_TOTAL>>>(
        x, Wqkv, nullptr, nullptr, qkv, MROWS, DIMM, 3*DIMM);
    // attention
    {
        int warps = BATCH * NHEADS * NTOK;
        int blocks = (warps + 7) / 8;
        attn_kernel<<<blocks, 256>>>(qkv, att);
    }
    // x = x + att @ Wo + bo
    tgemm_kernel<true,true,false><<<dim3(DIMM/TBN, gy), 256, SM_TOTAL>>>(
        att, Wo, bo, x, x, MROWS, DIMM, DIMM);
    // h = gelu(x @ W1 + b1)
    tgemm_kernel<true,false,true><<<dim3(HID/TBN, gy), 256, SM_TOTAL>>>(
        x, W1, b1, nullptr, hbuf, MROWS, DIMM, HID);
    // x = x + h @ W2 + b2
    tgemm_kernel<true,true,false><<<dim3(DIMM/TBN, gy), 256, SM_TOTAL>>>(
        hbuf, W2, b2, x, x, MROWS, HID, DIMM);
}

extern "C" void kernel_launch(void* const* d_in, const int* in_sizes, int n_in,
                              void* d_out, int out_size)
{
    const float* x_in = (const float*)d_in[0];
    const float* cls  = (const float*)d_in[1];
    const float* hW[7];
    const float* tW[7];
    for (int i = 0; i < 7; i++) hW[i] = (const float*)d_in[2 + i];
    for (int i = 0; i < 7; i++) tW[i] = (const float*)d_in[9 + i];

    // opt-in large dynamic smem (idempotent; not a stream op)
    cudaFuncSetAttribute(tgemm_kernel<false,false,false>,
                         cudaFuncAttributeMaxDynamicSharedMemorySize, SM_TOTAL);
    cudaFuncSetAttribute(tgemm_kernel<true,true,false>,
                         cudaFuncAttributeMaxDynamicSharedMemorySize, SM_TOTAL);
    cudaFuncSetAttribute(tgemm_kernel<true,false,true>,
                         cudaFuncAttributeMaxDynamicSharedMemorySize, SM_TOTAL);

    float *gx, *gqkv, *gatt, *gh, *gcls;
    cudaGetSymbolAddress((void**)&gx,   g_x);
    cudaGetSymbolAddress((void**)&gqkv, g_qkv);
    cudaGetSymbolAddress((void**)&gatt, g_att);
    cudaGetSymbolAddress((void**)&gh,   g_h);
    cudaGetSymbolAddress((void**)&gcls, g_cls);

    {
        int total = MROWS * DIMM;
        concat_kernel<<<(total + 255) / 256, 256>>>(x_in, cls, gx);
    }

    const size_t sQKV = (size_t)DIMM * 3 * DIMM;
    const size_t sWO  = (size_t)DIMM * DIMM;
    const size_t sBO  = DIMM;
    const size_t sW1  = (size_t)DIMM * HID;
    const size_t sB1  = HID;
    const size_t sW2  = (size_t)HID * DIMM;
    const size_t sB2  = DIMM;

    for (int l = 0; l < L_HEAD; l++)
        run_layer(hW[0] + l*sQKV, hW[1] + l*sWO, hW[2] + l*sBO,
                  hW[3] + l*sW1,  hW[4] + l*sB1, hW[5] + l*sW2, hW[6] + l*sB2,
                  gx, gqkv, gatt, gh);

    save_cls_kernel<<<(BATCH*DIMM + 255)/256, 256>>>(gx, gcls);

    for (int l = 0; l < L_TAIL; l++)
        run_layer(tW[0] + l*sQKV, tW[1] + l*sWO, tW[2] + l*sBO,
                  tW[3] + l*sW1,  tW[4] + l*sB1, tW[5] + l*sW2, tW[6] + l*sB2,
                  gx, gqkv, gatt, gh);

    {
        int total = MROWS * DIMM + BATCH * DIMM;
        write_out_kernel<<<(total + 255)/256, 256>>>(gx, gcls, (float*)d_out);
    }
}

// round 3
// speedup vs baseline: 2.8486x; 2.1397x over previous
#include <cuda_runtime.h>
#include <cuda_bf16.h>
#include <math.h>

// ---------------- problem constants ----------------
#define DIMM   1024
#define NHEADS 8
#define DHEAD  128
#define NTOK   2049          // 2048 + cls
#define BATCH  2
#define MROWS  (BATCH*NTOK)  // 4098
#define HID    4096          // 4*DIM
#define L_HEAD 4
#define L_TAIL 4

// ---------------- scratch (device globals: no allocation allowed) ----------------
__device__ float g_x  [(size_t)MROWS*DIMM];
__device__ float g_qkv[(size_t)MROWS*3*DIMM];
__device__ float g_att[(size_t)MROWS*DIMM];
__device__ float g_h  [(size_t)MROWS*HID];
__device__ float g_cls[(size_t)BATCH*DIMM];

// ---------------- concat cls + x ----------------
__global__ void concat_kernel(const float* __restrict__ x,
                              const float* __restrict__ cls,
                              float* __restrict__ gx)
{
    int idx = blockIdx.x * blockDim.x + threadIdx.x;
    int total = MROWS * DIMM;
    if (idx >= total) return;
    int d = idx % DIMM;
    int row = idx / DIMM;
    int n = row % NTOK;
    int b = row / NTOK;
    float v;
    if (n == 0) v = cls[d];
    else        v = x[((size_t)b*(NTOK-1) + (n-1))*DIMM + d];
    gx[idx] = v;
}

// ---------------- bf16 helpers ----------------
__device__ __forceinline__ unsigned short f2bf(float x) {
    __nv_bfloat16 h = __float2bfloat16(x);
    return *reinterpret_cast<unsigned short*>(&h);
}
__device__ __forceinline__ float bf2f(unsigned short s) {
    __nv_bfloat16 h = *reinterpret_cast<__nv_bfloat16*>(&s);
    return __bfloat162float(h);
}
__device__ __forceinline__ void split_bf16(float x, unsigned short& hi, unsigned short& lo) {
    hi = f2bf(x);
    lo = f2bf(x - bf2f(hi));
}

__device__ __forceinline__ void mma_bf16(float* c, const unsigned* a, const unsigned* b) {
    asm("mma.sync.aligned.m16n8k16.row.col.f32.bf16.bf16.f32 "
        "{%0,%1,%2,%3}, {%4,%5,%6,%7}, {%8,%9}, {%0,%1,%2,%3};"
        : "+f"(c[0]), "+f"(c[1]), "+f"(c[2]), "+f"(c[3])
        : "r"(a[0]), "r"(a[1]), "r"(a[2]), "r"(a[3]),
          "r"(b[0]), "r"(b[1]));
}

// ---------------- tensor-core GEMM (3xBF16 hi/lo split) ----------------
#define TBM 128
#define TBN 128
#define TBK 32
#define PA  40
#define BROW 136

#define SM_AH 0
#define SM_AL 10240
#define SM_BH 20480
#define SM_BL 29184
#define SM_BUF 37888
#define SM_TOTAL (2*SM_BUF)

template<bool BIAS, bool RESID, bool DOGELU>
__global__ __launch_bounds__(256, 1)
void tgemm_kernel(const float* __restrict__ A, const float* __restrict__ W,
                  const float* __restrict__ bias, const float* __restrict__ R,
                  float* __restrict__ C, int M, int K, int N)
{
    extern __shared__ char smem[];

    const int t    = threadIdx.x;
    const int warp = t >> 5;
    const int lane = t & 31;
    const int g    = lane >> 2;
    const int q    = lane & 3;
    const int wm   = warp & 1;
    const int wn   = warp >> 1;
    const int bm   = blockIdx.y * TBM;
    const int bn   = blockIdx.x * TBN;

    float acc[4][4][4];
#pragma unroll
    for (int i = 0; i < 4; i++)
#pragma unroll
        for (int j = 0; j < 4; j++)
#pragma unroll
            for (int e = 0; e < 4; e++) acc[i][j][e] = 0.f;

    int arow[4], akc[4], bkr[4], bnc[4];
#pragma unroll
    for (int i = 0; i < 4; i++) {
        int idx = i * 256 + t;
        arow[i] = idx >> 3;
        akc[i]  = (idx & 7) * 4;
        bkr[i]  = idx >> 5;
        bnc[i]  = (idx & 31) * 4;
    }

    const int steps = K / TBK;
    float4 ar[4], br[4];

#pragma unroll
    for (int i = 0; i < 4; i++) {
        int gr = bm + arow[i];
        ar[i] = make_float4(0.f, 0.f, 0.f, 0.f);
        if (gr < M) ar[i] = *(const float4*)(A + (size_t)gr * K + akc[i]);
        br[i] = *(const float4*)(W + (size_t)bkr[i] * N + bn + bnc[i]);
    }

    int p = 0;
    for (int s = 0; s < steps; s++) {
        {
            char* buf = smem + p * SM_BUF;
            unsigned* AH = (unsigned*)(buf + SM_AH);
            unsigned* AL = (unsigned*)(buf + SM_AL);
            unsigned short* BH = (unsigned short*)(buf + SM_BH);
            unsigned short* BL = (unsigned short*)(buf + SM_BL);
#pragma unroll
            for (int i = 0; i < 4; i++) {
                float av[4] = {ar[i].x, ar[i].y, ar[i].z, ar[i].w};
                unsigned short h[4], l[4];
#pragma unroll
                for (int e = 0; e < 4; e++) split_bf16(av[e], h[e], l[e]);
                int wi = (arow[i] * PA + akc[i]) >> 1;
                AH[wi]     = (unsigned)h[0] | ((unsigned)h[1] << 16);
                AH[wi + 1] = (unsigned)h[2] | ((unsigned)h[3] << 16);
                AL[wi]     = (unsigned)l[0] | ((unsigned)l[1] << 16);
                AL[wi + 1] = (unsigned)l[2] | ((unsigned)l[3] << 16);

                float bv[4] = {br[i].x, br[i].y, br[i].z, br[i].w};
                int half = bkr[i] & 1;
                int wb   = (bkr[i] >> 1) * BROW + bnc[i];
#pragma unroll
                for (int e = 0; e < 4; e++) {
                    unsigned short bh, bl;
                    split_bf16(bv[e], bh, bl);
                    BH[(wb + e) * 2 + half] = bh;
                    BL[(wb + e) * 2 + half] = bl;
                }
            }
        }
        __syncthreads();

        if (s + 1 < steps) {
            int k0 = (s + 1) * TBK;
#pragma unroll
            for (int i = 0; i < 4; i++) {
                int gr = bm + arow[i];
                ar[i] = make_float4(0.f, 0.f, 0.f, 0.f);
                if (gr < M) ar[i] = *(const float4*)(A + (size_t)gr * K + k0 + akc[i]);
                br[i] = *(const float4*)(W + (size_t)(k0 + bkr[i]) * N + bn + bnc[i]);
            }
        }

        {
            const char* buf = smem + p * SM_BUF;
            const unsigned* AH = (const unsigned*)(buf + SM_AH);
            const unsigned* AL = (const unsigned*)(buf + SM_AL);
            const unsigned* BHw = (const unsigned*)(buf + SM_BH);
            const unsigned* BLw = (const unsigned*)(buf + SM_BL);
            const int m0 = wm * 64;
            const int nb0 = wn * 32 + g;
#pragma unroll
            for (int ko = 0; ko < 2; ko++) {
                const int kofs = ko * 16;
                unsigned bh[4][2], bl[4][2];
#pragma unroll
                for (int ni = 0; ni < 4; ni++) {
                    int nb = nb0 + ni * 8;
                    bh[ni][0] = BHw[(q + ko * 8) * BROW + nb];
                    bh[ni][1] = BHw[(q + 4 + ko * 8) * BROW + nb];
                    bl[ni][0] = BLw[(q + ko * 8) * BROW + nb];
                    bl[ni][1] = BLw[(q + 4 + ko * 8) * BROW + nb];
                }
#pragma unroll
                for (int mi = 0; mi < 4; mi++) {
                    int r0 = m0 + mi * 16 + g;
                    unsigned ah[4], al[4];
                    int w0 = (r0 * PA + 2 * q + kofs) >> 1;
                    int w1 = ((r0 + 8) * PA + 2 * q + kofs) >> 1;
                    ah[0] = AH[w0];     ah[1] = AH[w1];
                    ah[2] = AH[w0 + 4]; ah[3] = AH[w1 + 4];
                    al[0] = AL[w0];     al[1] = AL[w1];
                    al[2] = AL[w0 + 4]; al[3] = AL[w1 + 4];
#pragma unroll
                    for (int ni = 0; ni < 4; ni++) {
                        mma_bf16(acc[mi][ni], ah, bh[ni]);
                        mma_bf16(acc[mi][ni], ah, bl[ni]);
                        mma_bf16(acc[mi][ni], al, bh[ni]);
                    }
                }
            }
        }
        p ^= 1;
    }

#pragma unroll
    for (int mi = 0; mi < 4; mi++) {
        int rbase = bm + wm * 64 + mi * 16 + g;
#pragma unroll
        for (int ni = 0; ni < 4; ni++) {
            int cbase = bn + wn * 32 + ni * 8 + 2 * q;
#pragma unroll
            for (int e = 0; e < 4; e++) {
                int gr = rbase + (e >= 2 ? 8 : 0);
                int gc = cbase + (e & 1);
                if (gr >= M) continue;
                float v = acc[mi][ni][e];
                if (BIAS)   v += bias[gc];
                if (DOGELU) v = 0.5f * v * (1.f + erff(v * 0.70710678118f));
                if (RESID)  v += R[(size_t)gr * N + gc];
                C[(size_t)gr * N + gc] = v;
            }
        }
    }
}

// ---------------- flash attention with mma (3xBF16 split) ----------------
// CTA: 64 queries x one (b,h); 4 warps, each 16 query rows; key tiles of 64.
// smem word layout: QH[4352] QL[4352] KH[4608] KL[4608] VH[4352] VL[4352]
#define ATT_QW 4352   // 64 rows * 68 words (136 shorts: 128 dh + 8 pad)
#define ATT_KW 4608   // 64 dh-pairs * 72 words (64 keys + 8 pad)
#define ATT_VW 4352   // 32 key-pairs * 136 words (128 dh + 8 pad)
#define ATT_SMEM ((2*ATT_QW + 2*ATT_KW + 2*ATT_VW) * 4)   // 106496 bytes

__global__ __launch_bounds__(128, 1)
void fattn_kernel(const float* __restrict__ qkv, float* __restrict__ out)
{
    extern __shared__ unsigned smw[];
    unsigned* QH = smw;
    unsigned* QL = QH + ATT_QW;
    unsigned* KH = QL + ATT_QW;
    unsigned* KL = KH + ATT_KW;
    unsigned* VH = KL + ATT_KW;
    unsigned* VL = VH + ATT_VW;

    const int t    = threadIdx.x;
    const int lane = t & 31;
    const int w    = t >> 5;
    const int g    = lane >> 2;
    const int q    = lane & 3;
    const int qt   = 32 - blockIdx.x;     // long CTAs first
    const int bh   = blockIdx.y;
    const int h    = bh & 7;
    const int b    = bh >> 3;
    const float scale = 0.03125f;         // 1024^-0.5

    const float* base = qkv + (size_t)b * NTOK * 3072;

    // ---- stage Q tile (scaled, split hi/lo, A-frag layout) ----
#pragma unroll
    for (int i = 0; i < 16; i++) {
        int idx = i * 128 + t;          // 0..2047
        int row = idx >> 5;             // 0..63
        int c4  = (idx & 31) * 4;       // 0..124
        int grow = qt * 64 + row;
        float4 v = make_float4(0.f, 0.f, 0.f, 0.f);
        if (grow < NTOK) v = *(const float4*)(base + (size_t)grow * 3072 + h * DHEAD + c4);
        float av[4] = {v.x * scale, v.y * scale, v.z * scale, v.w * scale};
        unsigned short hh[4], ll[4];
#pragma unroll
        for (int e = 0; e < 4; e++) split_bf16(av[e], hh[e], ll[e]);
        int wi = row * 68 + (c4 >> 1);
        QH[wi]     = (unsigned)hh[0] | ((unsigned)hh[1] << 16);
        QH[wi + 1] = (unsigned)hh[2] | ((unsigned)hh[3] << 16);
        QL[wi]     = (unsigned)ll[0] | ((unsigned)ll[1] << 16);
        QL[wi + 1] = (unsigned)ll[2] | ((unsigned)ll[3] << 16);
    }

    float o[16][4];
#pragma unroll
    for (int ni = 0; ni < 16; ni++)
#pragma unroll
        for (int e = 0; e < 4; e++) o[ni][e] = 0.f;
    float mrow[2] = {-1e30f, -1e30f};
    float lrow[2] = {0.f, 0.f};

    for (int jt = 0; jt <= qt; jt++) {
        __syncthreads();   // previous compute done (and Q staged on first iter)

        // ---- stage K, V tiles ----
#pragma unroll
        for (int i = 0; i < 16; i++) {
            int idx = i * 128 + t;
            int key = idx >> 5;
            int c4  = (idx & 31) * 4;
            int gkey = jt * 64 + key;
            float4 kv = make_float4(0.f, 0.f, 0.f, 0.f);
            float4 vv = make_float4(0.f, 0.f, 0.f, 0.f);
            if (gkey < NTOK) {
                const float* rp = base + (size_t)gkey * 3072 + h * DHEAD + c4;
                kv = *(const float4*)(rp + 1024);
                vv = *(const float4*)(rp + 2048);
            }
            // K: B-layout for QK^T (k dim = dh)
            {
                float av[4] = {kv.x, kv.y, kv.z, kv.w};
                unsigned short hh[4], ll[4];
#pragma unroll
                for (int e = 0; e < 4; e++) split_bf16(av[e], hh[e], ll[e]);
                int wi = (c4 >> 1) * 72 + key;
                KH[wi]      = (unsigned)hh[0] | ((unsigned)hh[1] << 16);
                KH[wi + 72] = (unsigned)hh[2] | ((unsigned)hh[3] << 16);
                KL[wi]      = (unsigned)ll[0] | ((unsigned)ll[1] << 16);
                KL[wi + 72] = (unsigned)ll[2] | ((unsigned)ll[3] << 16);
            }
            // V: B-layout for PV (k dim = keys) -> 2-byte scattered writes
            {
                float av[4] = {vv.x, vv.y, vv.z, vv.w};
                int half = key & 1;
                int wb = (key >> 1) * 136 + c4;
                unsigned short* VHs = (unsigned short*)VH;
                unsigned short* VLs = (unsigned short*)VL;
#pragma unroll
                for (int e = 0; e < 4; e++) {
                    unsigned short hh, ll;
                    split_bf16(av[e], hh, ll);
                    VHs[(wb + e) * 2 + half] = hh;
                    VLs[(wb + e) * 2 + half] = ll;
                }
            }
        }
        __syncthreads();

        // ---- S = Q @ K^T (3-pass split), fp32 frags ----
        float s[8][4];
#pragma unroll
        for (int ni = 0; ni < 8; ni++)
#pragma unroll
            for (int e = 0; e < 4; e++) s[ni][e] = 0.f;

        const int r0 = w * 16 + g;
#pragma unroll
        for (int ko = 0; ko < 8; ko++) {
            unsigned qh[4], ql[4];
            int w0 = r0 * 68 + q + ko * 8;
            int w1 = (r0 + 8) * 68 + q + ko * 8;
            qh[0] = QH[w0];     qh[1] = QH[w1];
            qh[2] = QH[w0 + 4]; qh[3] = QH[w1 + 4];
            ql[0] = QL[w0];     ql[1] = QL[w1];
            ql[2] = QL[w0 + 4]; ql[3] = QL[w1 + 4];
#pragma unroll
            for (int ni = 0; ni < 8; ni++) {
                int nb = ni * 8 + g;
                unsigned bh[2], bl[2];
                bh[0] = KH[(q + ko * 8) * 72 + nb];
                bh[1] = KH[(q + 4 + ko * 8) * 72 + nb];
                bl[0] = KL[(q + ko * 8) * 72 + nb];
                bl[1] = KL[(q + 4 + ko * 8) * 72 + nb];
                mma_bf16(s[ni], qh, bh);
                mma_bf16(s[ni], qh, bl);
                mma_bf16(s[ni], ql, bh);
            }
        }

        // ---- causal mask on diagonal tile ----
        if (jt == qt) {
            int rbase = qt * 64 + w * 16 + g;
#pragma unroll
            for (int ni = 0; ni < 8; ni++) {
                int cbase = jt * 64 + ni * 8 + 2 * q;
#pragma unroll
                for (int e = 0; e < 4; e++) {
                    int row = rbase + (e >= 2 ? 8 : 0);
                    int col = cbase + (e & 1);
                    if (col > row) s[ni][e] = -1e30f;
                }
            }
        }

        // ---- online softmax update ----
        float mt[2] = {-1e30f, -1e30f};
#pragma unroll
        for (int ni = 0; ni < 8; ni++) {
            mt[0] = fmaxf(mt[0], fmaxf(s[ni][0], s[ni][1]));
            mt[1] = fmaxf(mt[1], fmaxf(s[ni][2], s[ni][3]));
        }
#pragma unroll
        for (int d = 1; d <= 2; d <<= 1) {
            mt[0] = fmaxf(mt[0], __shfl_xor_sync(0xFFFFFFFFu, mt[0], d));
            mt[1] = fmaxf(mt[1], __shfl_xor_sync(0xFFFFFFFFu, mt[1], d));
        }
        float mn[2] = {fmaxf(mrow[0], mt[0]), fmaxf(mrow[1], mt[1])};
        float corr[2] = {__expf(mrow[0] - mn[0]), __expf(mrow[1] - mn[1])};

        float rs[2] = {0.f, 0.f};
#pragma unroll
        for (int ni = 0; ni < 8; ni++) {
#pragma unroll
            for (int e = 0; e < 4; e++) {
                float pv = __expf(s[ni][e] - mn[e >> 1]);
                s[ni][e] = pv;
                rs[e >> 1] += pv;
            }
        }
#pragma unroll
        for (int d = 1; d <= 2; d <<= 1) {
            rs[0] += __shfl_xor_sync(0xFFFFFFFFu, rs[0], d);
            rs[1] += __shfl_xor_sync(0xFFFFFFFFu, rs[1], d);
        }
        lrow[0] = lrow[0] * corr[0] + rs[0];
        lrow[1] = lrow[1] * corr[1] + rs[1];
        mrow[0] = mn[0];
        mrow[1] = mn[1];
#pragma unroll
        for (int ni = 0; ni < 16; ni++) {
            o[ni][0] *= corr[0]; o[ni][1] *= corr[0];
            o[ni][2] *= corr[1]; o[ni][3] *= corr[1];
        }

        // ---- O += P @ V (P frags built in registers from S C-frags) ----
#pragma unroll
        for (int kp = 0; kp < 4; kp++) {
            unsigned ph[4], pl[4];
            {
                float* s0 = s[2 * kp];
                float* s1 = s[2 * kp + 1];
                unsigned short h0, h1, l0, l1;
                split_bf16(s0[0], h0, l0); split_bf16(s0[1], h1, l1);
                ph[0] = (unsigned)h0 | ((unsigned)h1 << 16);
                pl[0] = (unsigned)l0 | ((unsigned)l1 << 16);
                split_bf16(s0[2], h0, l0); split_bf16(s0[3], h1, l1);
                ph[1] = (unsigned)h0 | ((unsigned)h1 << 16);
                pl[1] = (unsigned)l0 | ((unsigned)l1 << 16);
                split_bf16(s1[0], h0, l0); split_bf16(s1[1], h1, l1);
                ph[2] = (unsigned)h0 | ((unsigned)h1 << 16);
                pl[2] = (unsigned)l0 | ((unsigned)l1 << 16);
                split_bf16(s1[2], h0, l0); split_bf16(s1[3], h1, l1);
                ph[3] = (unsigned)h0 | ((unsigned)h1 << 16);
                pl[3] = (unsigned)l0 | ((unsigned)l1 << 16);
            }
#pragma unroll
            for (int ni = 0; ni < 16; ni++) {
                int nb = ni * 8 + g;
                unsigned bh[2], bl[2];
                bh[0] = VH[(q + kp * 8) * 136 + nb];
                bh[1] = VH[(q + 4 + kp * 8) * 136 + nb];
                bl[0] = VL[(q + kp * 8) * 136 + nb];
                bl[1] = VL[(q + 4 + kp * 8) * 136 + nb];
                mma_bf16(o[ni], ph, bh);
                mma_bf16(o[ni], ph, bl);
                mma_bf16(o[ni], pl, bh);
            }
        }
    }

    // ---- epilogue ----
    float inv[2] = {1.f / lrow[0], 1.f / lrow[1]};
    int rbase = qt * 64 + w * 16 + g;
#pragma unroll
    for (int ni = 0; ni < 16; ni++) {
        int cbase = h * DHEAD + ni * 8 + 2 * q;
#pragma unroll
        for (int e = 0; e < 4; e++) {
            int row = rbase + (e >= 2 ? 8 : 0);
            if (row >= NTOK) continue;
            out[((size_t)b * NTOK + row) * DIMM + cbase + (e & 1)] = o[ni][e] * inv[e >> 1];
        }
    }
}

// ---------------- save cls tokens after head stack ----------------
__global__ void save_cls_kernel(const float* __restrict__ gx, float* __restrict__ gcls)
{
    int idx = blockIdx.x * blockDim.x + threadIdx.x;
    if (idx >= BATCH * DIMM) return;
    int b = idx / DIMM, d = idx % DIMM;
    gcls[idx] = gx[((size_t)b * NTOK) * DIMM + d];
}

// ---------------- write final output: [x_tail | cls] ----------------
__global__ void write_out_kernel(const float* __restrict__ gx,
                                 const float* __restrict__ gcls,
                                 float* __restrict__ out)
{
    const int totalx = MROWS * DIMM;
    const int totalc = BATCH * DIMM;
    int idx = blockIdx.x * blockDim.x + threadIdx.x;
    if (idx < totalx)               out[idx] = gx[idx];
    else if (idx < totalx + totalc) out[idx] = gcls[idx - totalx];
}

// ---------------- host orchestration ----------------
static void run_layer(const float* Wqkv, const float* Wo, const float* bo,
                      const float* W1, const float* b1,
                      const float* W2, const float* b2,
                      float* x, float* qkv, float* att, float* hbuf)
{
    const int gy = (MROWS + TBM - 1) / TBM;  // 33
    tgemm_kernel<false,false,false><<<dim3(3*DIMM/TBN, gy), 256, SM_TOTAL>>>(
        x, Wqkv, nullptr, nullptr, qkv, MROWS, DIMM, 3*DIMM);
    fattn_kernel<<<dim3(33, BATCH*NHEADS), 128, ATT_SMEM>>>(qkv, att);
    tgemm_kernel<true,true,false><<<dim3(DIMM/TBN, gy), 256, SM_TOTAL>>>(
        att, Wo, bo, x, x, MROWS, DIMM, DIMM);
    tgemm_kernel<true,false,true><<<dim3(HID/TBN, gy), 256, SM_TOTAL>>>(
        x, W1, b1, nullptr, hbuf, MROWS, DIMM, HID);
    tgemm_kernel<true,true,false><<<dim3(DIMM/TBN, gy), 256, SM_TOTAL>>>(
        hbuf, W2, b2, x, x, MROWS, HID, DIMM);
}

extern "C" void kernel_launch(void* const* d_in, const int* in_sizes, int n_in,
                              void* d_out, int out_size)
{
    const float* x_in = (const float*)d_in[0];
    const float* cls  = (const float*)d_in[1];
    const float* hW[7];
    const float* tW[7];
    for (int i = 0; i < 7; i++) hW[i] = (const float*)d_in[2 + i];
    for (int i = 0; i < 7; i++) tW[i] = (const float*)d_in[9 + i];

    cudaFuncSetAttribute(tgemm_kernel<false,false,false>,
                         cudaFuncAttributeMaxDynamicSharedMemorySize, SM_TOTAL);
    cudaFuncSetAttribute(tgemm_kernel<true,true,false>,
                         cudaFuncAttributeMaxDynamicSharedMemorySize, SM_TOTAL);
    cudaFuncSetAttribute(tgemm_kernel<true,false,true>,
                         cudaFuncAttributeMaxDynamicSharedMemorySize, SM_TOTAL);
    cudaFuncSetAttribute(fattn_kernel,
                         cudaFuncAttributeMaxDynamicSharedMemorySize, ATT_SMEM);

    float *gx, *gqkv, *gatt, *gh, *gcls;
    cudaGetSymbolAddress((void**)&gx,   g_x);
    cudaGetSymbolAddress((void**)&gqkv, g_qkv);
    cudaGetSymbolAddress((void**)&gatt, g_att);
    cudaGetSymbolAddress((void**)&gh,   g_h);
    cudaGetSymbolAddress((void**)&gcls, g_cls);

    {
        int total = MROWS * DIMM;
        concat_kernel<<<(total + 255) / 256, 256>>>(x_in, cls, gx);
    }

    const size_t sQKV = (size_t)DIMM * 3 * DIMM;
    const size_t sWO  = (size_t)DIMM * DIMM;
    const size_t sBO  = DIMM;
    const size_t sW1  = (size_t)DIMM * HID;
    const size_t sB1  = HID;
    const size_t sW2  = (size_t)HID * DIMM;
    const size_t sB2  = DIMM;

    for (int l = 0; l < L_HEAD; l++)
        run_layer(hW[0] + l*sQKV, hW[1] + l*sWO, hW[2] + l*sBO,
                  hW[3] + l*sW1,  hW[4] + l*sB1, hW[5] + l*sW2, hW[6] + l*sB2,
                  gx, gqkv, gatt, gh);

    save_cls_kernel<<<(BATCH*DIMM + 255)/256, 256>>>(gx, gcls);

    for (int l = 0; l < L_TAIL; l++)
        run_layer(tW[0] + l*sQKV, tW[1] + l*sWO, tW[2] + l*sBO,
                  tW[3] + l*sW1,  tW[4] + l*sB1, tW[5] + l*sW2, tW[6] + l*sB2,
                  gx, gqkv, gatt, gh);

    {
        int total = MROWS * DIMM + BATCH * DIMM;
        write_out_kernel<<<(total + 255)/256, 256>>>(gx, gcls, (float*)d_out);
    }
}

// round 5
// speedup vs baseline: 3.2572x; 1.1434x over previous
#include <cuda_runtime.h>
#include <cuda_bf16.h>
#include <math.h>

// ---------------- problem constants ----------------
#define DIMM   1024
#define NHEADS 8
#define DHEAD  128
#define NTOK   2049
#define BATCH  2
#define MROWS  (BATCH*NTOK)  // 4098
#define HID    4096
#define L_HEAD 4
#define L_TAIL 4

// ---------------- scratch (device globals) ----------------
__device__ float g_x  [(size_t)MROWS*DIMM];
__device__ float g_qkv[(size_t)MROWS*3*DIMM];
__device__ float g_cls[(size_t)BATCH*DIMM];

// activation hi/lo splits (word = 2 shorts along N)
__device__ unsigned g_xs_h[(size_t)MROWS*DIMM/2];
__device__ unsigned g_xs_l[(size_t)MROWS*DIMM/2];
__device__ unsigned g_as_h[(size_t)MROWS*DIMM/2];
__device__ unsigned g_as_l[(size_t)MROWS*DIMM/2];
__device__ unsigned g_hs_h[(size_t)MROWS*HID/2];
__device__ unsigned g_hs_l[(size_t)MROWS*HID/2];

// weight splits, pre-tiled: word idx = k2*N + n holds (k even, k odd) shorts for col n
#define WQKV_L (512*3072)
#define WO_L   (512*1024)
#define W1_L   (512*4096)
#define W2_L   (2048*1024)
__device__ unsigned g_wqkv_h[8*(size_t)WQKV_L];
__device__ unsigned g_wqkv_l[8*(size_t)WQKV_L];
__device__ unsigned g_wo_h[8*(size_t)WO_L];
__device__ unsigned g_wo_l[8*(size_t)WO_L];
__device__ unsigned g_w1_h[8*(size_t)W1_L];
__device__ unsigned g_w1_l[8*(size_t)W1_L];
__device__ unsigned g_w2_h[8*(size_t)W2_L];
__device__ unsigned g_w2_l[8*(size_t)W2_L];

// ---------------- bf16 helpers ----------------
__device__ __forceinline__ unsigned short f2bf(float x) {
    __nv_bfloat16 h = __float2bfloat16(x);
    return *reinterpret_cast<unsigned short*>(&h);
}
__device__ __forceinline__ float bf2f(unsigned short s) {
    __nv_bfloat16 h = *reinterpret_cast<__nv_bfloat16*>(&s);
    return __bfloat162float(h);
}
__device__ __forceinline__ void split_bf16(float x, unsigned short& hi, unsigned short& lo) {
    hi = f2bf(x);
    lo = f2bf(x - bf2f(hi));
}
// pack split of pair (a,b) -> hi word, lo word
__device__ __forceinline__ void split_pair(float a, float b, unsigned& hw, unsigned& lw) {
    unsigned short ah, al, bh, bl;
    split_bf16(a, ah, al);
    split_bf16(b, bh, bl);
    hw = (unsigned)ah | ((unsigned)bh << 16);
    lw = (unsigned)al | ((unsigned)bl << 16);
}

__device__ __forceinline__ void mma_bf16(float* c, const unsigned* a, const unsigned* b) {
    asm("mma.sync.aligned.m16n8k16.row.col.f32.bf16.bf16.f32 "
        "{%0,%1,%2,%3}, {%4,%5,%6,%7}, {%8,%9}, {%0,%1,%2,%3};"
        : "+f"(c[0]), "+f"(c[1]), "+f"(c[2]), "+f"(c[3])
        : "r"(a[0]), "r"(a[1]), "r"(a[2]), "r"(a[3]),
          "r"(b[0]), "r"(b[1]));
}

__device__ __forceinline__ void ldsm4(unsigned* r, const void* p) {
    unsigned a = (unsigned)__cvta_generic_to_shared(p);
    asm volatile("ldmatrix.sync.aligned.m8n8.x4.shared.b16 {%0,%1,%2,%3}, [%4];"
        : "=r"(r[0]), "=r"(r[1]), "=r"(r[2]), "=r"(r[3]) : "r"(a));
}

__device__ __forceinline__ void cpa16(void* dst, const void* src, int sz) {
    unsigned d = (unsigned)__cvta_generic_to_shared(dst);
    asm volatile("cp.async.cg.shared.global [%0], [%1], 16, %2;" :: "r"(d), "l"(src), "r"(sz));
}
__device__ __forceinline__ void cp_commit() { asm volatile("cp.async.commit_group;"); }
template<int N> __device__ __forceinline__ void cp_wait() {
    asm volatile("cp.async.wait_group %0;" :: "n"(N));
}

// ---------------- weight pre-split kernel ----------------
__global__ void split_w_kernel(const float* __restrict__ Wh, const float* __restrict__ Wt,
                               unsigned* __restrict__ oH, unsigned* __restrict__ oL,
                               int npairs, int N)
{
    int l = blockIdx.y;   // 0..7
    const float* W = (l < 4) ? (Wh + (size_t)l * npairs * 2)
                             : (Wt + (size_t)(l - 4) * npairs * 2);
    int idx = blockIdx.x * blockDim.x + threadIdx.x;
    if (idx >= npairs) return;
    int k2 = idx / N, n = idx % N;
    float a = W[(size_t)(2 * k2) * N + n];
    float b = W[(size_t)(2 * k2 + 1) * N + n];
    unsigned hw, lw;
    split_pair(a, b, hw, lw);
    size_t o = (size_t)l * npairs + idx;
    oH[o] = hw;
    oL[o] = lw;
}

// ---------------- concat cls + x -> fp32 x + split ----------------
__global__ void concat_kernel(const float* __restrict__ x, const float* __restrict__ cls,
                              float* __restrict__ gx,
                              unsigned* __restrict__ xh, unsigned* __restrict__ xl)
{
    int idx = blockIdx.x * blockDim.x + threadIdx.x;   // pair index
    int total = MROWS * DIMM / 2;
    if (idx >= total) return;
    int c2  = idx % (DIMM / 2);
    int row = idx / (DIMM / 2);
    int n = row % NTOK, b = row / NTOK;
    float v0, v1;
    if (n == 0) { v0 = cls[c2 * 2]; v1 = cls[c2 * 2 + 1]; }
    else {
        const float* p = x + ((size_t)b * (NTOK - 1) + (n - 1)) * DIMM + c2 * 2;
        v0 = p[0]; v1 = p[1];
    }
    gx[idx * 2] = v0; gx[idx * 2 + 1] = v1;
    unsigned hw, lw;
    split_pair(v0, v1, hw, lw);
    xh[idx] = hw; xl[idx] = lw;
}

// ---------------- tensor-core GEMM, pre-split inputs, cp.async 3-stage ----------------
// C[M,N] = A[M,K] @ W[K,N]  (+bias) (GELU) (+R);  A,B given as bf16 hi/lo
#define AST_B 80                   // bytes per A smem row (32 shorts data + 8 pad)
#define STG_A (128*AST_B)          // 10240 per plane
#define BROW  136                  // words per B k2-row (128 data + 8 pad)
#define STG_B (16*BROW*4)          // 8704 per plane
#define STG_BYTES (2*STG_A + 2*STG_B)   // 37888
#define NSTAGE 3
#define SM_TOTAL (NSTAGE*STG_BYTES)     // 113664

template<bool BIAS, bool RESID, bool DOGELU, bool W32, bool WS>
__global__ __launch_bounds__(256, 1)
void tgemm_kernel(const unsigned* __restrict__ AH, const unsigned* __restrict__ AL,
                  const unsigned* __restrict__ BH, const unsigned* __restrict__ BL,
                  const float* __restrict__ bias, const float* __restrict__ R,
                  float* __restrict__ C,
                  unsigned* __restrict__ OH, unsigned* __restrict__ OL,
                  int M, int K, int N)
{
    extern __shared__ char smem[];

    const int t    = threadIdx.x;
    const int warp = t >> 5;
    const int lane = t & 31;
    const int g    = lane >> 2;
    const int q    = lane & 3;
    const int wm   = warp & 1;
    const int wn   = warp >> 1;
    const int bm   = blockIdx.y * 128;
    const int bn   = blockIdx.x * 128;
    const int steps = K >> 5;

    float acc[4][4][4];
#pragma unroll
    for (int i = 0; i < 4; i++)
#pragma unroll
        for (int j = 0; j < 4; j++)
#pragma unroll
            for (int e = 0; e < 4; e++) acc[i][j][e] = 0.f;

    // cp.async mappings
    // A: per plane 512 chunks: row=idx>>2 (0..127), chunk=idx&3
    // B: per plane 512 chunks: r=idx>>5 (0..15),   chunk=idx&31
    const int ar0 = t >> 2,  ac0 = (t & 3);
    const int ar1 = (t + 256) >> 2, ac1 = (t & 3);
    const int br0 = t >> 5,  bc0 = (t & 31);
    const int br1 = (t + 256) >> 5, bc1 = (t & 31);

    // AH/AL as short-index base (global row-major [M][K] shorts)
    const unsigned short* AHg = (const unsigned short*)AH;
    const unsigned short* ALg = (const unsigned short*)AL;

    auto issue = [&](int s) {
        char* buf = smem + (s % NSTAGE) * STG_BYTES;
        char* AHs = buf;
        char* ALs = buf + STG_A;
        char* BHs = buf + 2 * STG_A;
        char* BLs = buf + 2 * STG_A + STG_B;
        int k0 = s * 32;
        {
            int gr = bm + ar0;
            int sz = (gr < M) ? 16 : 0;
            size_t so = (size_t)(gr < M ? gr : 0) * K + k0 + ac0 * 8;
            cpa16(AHs + ar0 * AST_B + ac0 * 16, AHg + so, sz);
            cpa16(ALs + ar0 * AST_B + ac0 * 16, ALg + so, sz);
            gr = bm + ar1;
            sz = (gr < M) ? 16 : 0;
            so = (size_t)(gr < M ? gr : 0) * K + k0 + ac1 * 8;
            cpa16(AHs + ar1 * AST_B + ac1 * 16, AHg + so, sz);
            cpa16(ALs + ar1 * AST_B + ac1 * 16, ALg + so, sz);
        }
        {
            size_t gw = ((size_t)(k0 / 2 + br0)) * N + bn;   // word index
            cpa16(BHs + br0 * (BROW * 4) + bc0 * 16, (const char*)BH + gw * 4 + bc0 * 16, 16);
            cpa16(BLs + br0 * (BROW * 4) + bc0 * 16, (const char*)BL + gw * 4 + bc0 * 16, 16);
            gw = ((size_t)(k0 / 2 + br1)) * N + bn;
            cpa16(BHs + br1 * (BROW * 4) + bc1 * 16, (const char*)BH + gw * 4 + bc1 * 16, 16);
            cpa16(BLs + br1 * (BROW * 4) + bc1 * 16, (const char*)BL + gw * 4 + bc1 * 16, 16);
        }
        cp_commit();
    };

    issue(0);
    issue(1);

    // ldmatrix lane base offset within A plane
    const int lanebase = (wm * 64 + (lane & 7) + ((lane >> 3) & 1) * 8) * AST_B + (lane >> 4) * 16;

    for (int s = 0; s < steps; s++) {
        if (s + 2 < steps) issue(s + 2);
        if (s + 2 < steps)      cp_wait<2>();
        else if (s + 1 < steps) cp_wait<1>();
        else                    cp_wait<0>();
        __syncthreads();

        const char* buf = smem + (s % NSTAGE) * STG_BYTES;
        const char* AHs = buf;
        const char* ALs = buf + STG_A;
        const unsigned* BHw = (const unsigned*)(buf + 2 * STG_A);
        const unsigned* BLw = (const unsigned*)(buf + 2 * STG_A + STG_B);

#pragma unroll
        for (int ko = 0; ko < 2; ko++) {
            unsigned bh[4][2], bl[4][2];
#pragma unroll
            for (int ni = 0; ni < 4; ni++) {
                int nb = wn * 32 + g + ni * 8;
                bh[ni][0] = BHw[(q + ko * 8) * BROW + nb];
                bh[ni][1] = BHw[(q + 4 + ko * 8) * BROW + nb];
                bl[ni][0] = BLw[(q + ko * 8) * BROW + nb];
                bl[ni][1] = BLw[(q + 4 + ko * 8) * BROW + nb];
            }
#pragma unroll
            for (int mi = 0; mi < 4; mi++) {
                unsigned ah[4], al[4];
                ldsm4(ah, AHs + lanebase + mi * (16 * AST_B) + ko * 32);
                ldsm4(al, ALs + lanebase + mi * (16 * AST_B) + ko * 32);
#pragma unroll
                for (int ni = 0; ni < 4; ni++) {
                    mma_bf16(acc[mi][ni], ah, bh[ni]);
                    mma_bf16(acc[mi][ni], ah, bl[ni]);
                    mma_bf16(acc[mi][ni], al, bh[ni]);
                }
            }
        }
        __syncthreads();
    }

    // ---- epilogue ----
    const int Nw = N >> 1;
#pragma unroll
    for (int mi = 0; mi < 4; mi++) {
        int r0 = bm + wm * 64 + mi * 16 + g;
#pragma unroll
        for (int ni = 0; ni < 4; ni++) {
            int cb = bn + wn * 32 + ni * 8 + 2 * q;
            float v[4];
#pragma unroll
            for (int e = 0; e < 4; e++) {
                v[e] = acc[mi][ni][e];
                if (BIAS) v[e] += bias[cb + (e & 1)];
                if (DOGELU) v[e] = 0.5f * v[e] * (1.f + erff(v[e] * 0.70710678118f));
            }
#pragma unroll
            for (int half = 0; half < 2; half++) {
                int gr = r0 + half * 8;
                if (gr >= M) continue;
                float a = v[half * 2], b = v[half * 2 + 1];
                if (RESID) {
                    a += R[(size_t)gr * N + cb];
                    b += R[(size_t)gr * N + cb + 1];
                }
                if (W32) {
                    C[(size_t)gr * N + cb]     = a;
                    C[(size_t)gr * N + cb + 1] = b;
                }
                if (WS) {
                    unsigned hw, lw;
                    split_pair(a, b, hw, lw);
                    size_t wi = (size_t)gr * Nw + (cb >> 1);
                    OH[wi] = hw;
                    OL[wi] = lw;
                }
            }
        }
    }
}

// ---------------- flash attention (3xBF16 mma), split output ----------------
#define ATT_QW 4352
#define ATT_KW 4608
#define ATT_VW 4352
#define ATT_SMEM ((2*ATT_QW + 2*ATT_KW + 2*ATT_VW) * 4)

__global__ __launch_bounds__(128, 1)
void fattn_kernel(const float* __restrict__ qkv,
                  unsigned* __restrict__ OH, unsigned* __restrict__ OL)
{
    extern __shared__ unsigned smw[];
    unsigned* QH = smw;
    unsigned* QL = QH + ATT_QW;
    unsigned* KH = QL + ATT_QW;
    unsigned* KL = KH + ATT_KW;
    unsigned* VH = KL + ATT_KW;
    unsigned* VL = VH + ATT_VW;

    const int t    = threadIdx.x;
    const int lane = t & 31;
    const int w    = t >> 5;
    const int g    = lane >> 2;
    const int q    = lane & 3;
    const int qt   = 32 - blockIdx.x;
    const int bh   = blockIdx.y;
    const int h    = bh & 7;
    const int b    = bh >> 3;
    const float scale = 0.03125f;

    const float* base = qkv + (size_t)b * NTOK * 3072;

#pragma unroll
    for (int i = 0; i < 16; i++) {
        int idx = i * 128 + t;
        int row = idx >> 5;
        int c4  = (idx & 31) * 4;
        int grow = qt * 64 + row;
        float4 v = make_float4(0.f, 0.f, 0.f, 0.f);
        if (grow < NTOK) v = *(const float4*)(base + (size_t)grow * 3072 + h * DHEAD + c4);
        int wi = row * 68 + (c4 >> 1);
        unsigned hw, lw;
        split_pair(v.x * scale, v.y * scale, hw, lw);
        QH[wi] = hw; QL[wi] = lw;
        split_pair(v.z * scale, v.w * scale, hw, lw);
        QH[wi + 1] = hw; QL[wi + 1] = lw;
    }

    float o[16][4];
#pragma unroll
    for (int ni = 0; ni < 16; ni++)
#pragma unroll
        for (int e = 0; e < 4; e++) o[ni][e] = 0.f;
    float mrow[2] = {-1e30f, -1e30f};
    float lrow[2] = {0.f, 0.f};

    for (int jt = 0; jt <= qt; jt++) {
        __syncthreads();

#pragma unroll
        for (int i = 0; i < 16; i++) {
            int idx = i * 128 + t;
            int key = idx >> 5;
            int c4  = (idx & 31) * 4;
            int gkey = jt * 64 + key;
            float4 kv = make_float4(0.f, 0.f, 0.f, 0.f);
            float4 vv = make_float4(0.f, 0.f, 0.f, 0.f);
            if (gkey < NTOK) {
                const float* rp = base + (size_t)gkey * 3072 + h * DHEAD + c4;
                kv = *(const float4*)(rp + 1024);
                vv = *(const float4*)(rp + 2048);
            }
            {
                int wi = (c4 >> 1) * 72 + key;
                unsigned short hh[4], ll[4];
                split_bf16(kv.x, hh[0], ll[0]); split_bf16(kv.y, hh[1], ll[1]);
                split_bf16(kv.z, hh[2], ll[2]); split_bf16(kv.w, hh[3], ll[3]);
                KH[wi]      = (unsigned)hh[0] | ((unsigned)hh[1] << 16);
                KH[wi + 72] = (unsigned)hh[2] | ((unsigned)hh[3] << 16);
                KL[wi]      = (unsigned)ll[0] | ((unsigned)ll[1] << 16);
                KL[wi + 72] = (unsigned)ll[2] | ((unsigned)ll[3] << 16);
            }
            {
                float av[4] = {vv.x, vv.y, vv.z, vv.w};
                int half = key & 1;
                int wb = (key >> 1) * 136 + c4;
                unsigned short* VHs = (unsigned short*)VH;
                unsigned short* VLs = (unsigned short*)VL;
#pragma unroll
                for (int e = 0; e < 4; e++) {
                    unsigned short hh, ll;
                    split_bf16(av[e], hh, ll);
                    VHs[(wb + e) * 2 + half] = hh;
                    VLs[(wb + e) * 2 + half] = ll;
                }
            }
        }
        __syncthreads();

        float s[8][4];
#pragma unroll
        for (int ni = 0; ni < 8; ni++)
#pragma unroll
            for (int e = 0; e < 4; e++) s[ni][e] = 0.f;

        const int r0 = w * 16 + g;
#pragma unroll
        for (int ko = 0; ko < 8; ko++) {
            unsigned qh[4], ql[4];
            int w0 = r0 * 68 + q + ko * 8;
            int w1 = (r0 + 8) * 68 + q + ko * 8;
            qh[0] = QH[w0];     qh[1] = QH[w1];
            qh[2] = QH[w0 + 4]; qh[3] = QH[w1 + 4];
            ql[0] = QL[w0];     ql[1] = QL[w1];
            ql[2] = QL[w0 + 4]; ql[3] = QL[w1 + 4];
#pragma unroll
            for (int ni = 0; ni < 8; ni++) {
                int nb = ni * 8 + g;
                unsigned bhf[2], blf[2];
                bhf[0] = KH[(q + ko * 8) * 72 + nb];
                bhf[1] = KH[(q + 4 + ko * 8) * 72 + nb];
                blf[0] = KL[(q + ko * 8) * 72 + nb];
                blf[1] = KL[(q + 4 + ko * 8) * 72 + nb];
                mma_bf16(s[ni], qh, bhf);
                mma_bf16(s[ni], qh, blf);
                mma_bf16(s[ni], ql, bhf);
            }
        }

        if (jt == qt) {
            int rbase = qt * 64 + w * 16 + g;
#pragma unroll
            for (int ni = 0; ni < 8; ni++) {
                int cbase = jt * 64 + ni * 8 + 2 * q;
#pragma unroll
                for (int e = 0; e < 4; e++) {
                    int row = rbase + (e >= 2 ? 8 : 0);
                    int col = cbase + (e & 1);
                    if (col > row) s[ni][e] = -1e30f;
                }
            }
        }

        float mt[2] = {-1e30f, -1e30f};
#pragma unroll
        for (int ni = 0; ni < 8; ni++) {
            mt[0] = fmaxf(mt[0], fmaxf(s[ni][0], s[ni][1]));
            mt[1] = fmaxf(mt[1], fmaxf(s[ni][2], s[ni][3]));
        }
#pragma unroll
        for (int d = 1; d <= 2; d <<= 1) {
            mt[0] = fmaxf(mt[0], __shfl_xor_sync(0xFFFFFFFFu, mt[0], d));
            mt[1] = fmaxf(mt[1], __shfl_xor_sync(0xFFFFFFFFu, mt[1], d));
        }
        float mn[2] = {fmaxf(mrow[0], mt[0]), fmaxf(mrow[1], mt[1])};
        float corr[2] = {__expf(mrow[0] - mn[0]), __expf(mrow[1] - mn[1])};

        float rs[2] = {0.f, 0.f};
#pragma unroll
        for (int ni = 0; ni < 8; ni++) {
#pragma unroll
            for (int e = 0; e < 4; e++) {
                float pv = __expf(s[ni][e] - mn[e >> 1]);
                s[ni][e] = pv;
                rs[e >> 1] += pv;
            }
        }
#pragma unroll
        for (int d = 1; d <= 2; d <<= 1) {
            rs[0] += __shfl_xor_sync(0xFFFFFFFFu, rs[0], d);
            rs[1] += __shfl_xor_sync(0xFFFFFFFFu, rs[1], d);
        }
        lrow[0] = lrow[0] * corr[0] + rs[0];
        lrow[1] = lrow[1] * corr[1] + rs[1];
        mrow[0] = mn[0];
        mrow[1] = mn[1];
#pragma unroll
        for (int ni = 0; ni < 16; ni++) {
            o[ni][0] *= corr[0]; o[ni][1] *= corr[0];
            o[ni][2] *= corr[1]; o[ni][3] *= corr[1];
        }

#pragma unroll
        for (int kp = 0; kp < 4; kp++) {
            unsigned ph[4], pl[4];
            split_pair(s[2*kp][0],   s[2*kp][1],   ph[0], pl[0]);
            split_pair(s[2*kp][2],   s[2*kp][3],   ph[1], pl[1]);
            split_pair(s[2*kp+1][0], s[2*kp+1][1], ph[2], pl[2]);
            split_pair(s[2*kp+1][2], s[2*kp+1][3], ph[3], pl[3]);
#pragma unroll
            for (int ni = 0; ni < 16; ni++) {
                int nb = ni * 8 + g;
                unsigned bhf[2], blf[2];
                bhf[0] = VH[(q + kp * 8) * 136 + nb];
                bhf[1] = VH[(q + 4 + kp * 8) * 136 + nb];
                blf[0] = VL[(q + kp * 8) * 136 + nb];
                blf[1] = VL[(q + 4 + kp * 8) * 136 + nb];
                mma_bf16(o[ni], ph, bhf);
                mma_bf16(o[ni], ph, blf);
                mma_bf16(o[ni], pl, bhf);
            }
        }
    }

    float inv[2] = {1.f / lrow[0], 1.f / lrow[1]};
    int rbase = qt * 64 + w * 16 + g;
#pragma unroll
    for (int ni = 0; ni < 16; ni++) {
        int cb = h * DHEAD + ni * 8 + 2 * q;
#pragma unroll
        for (int half = 0; half < 2; half++) {
            int row = rbase + half * 8;
            if (row >= NTOK) continue;
            unsigned hw, lw;
            split_pair(o[ni][half*2] * inv[half], o[ni][half*2+1] * inv[half], hw, lw);
            size_t wi = (size_t)(b * NTOK + row) * (DIMM / 2) + (cb >> 1);
            OH[wi] = hw;
            OL[wi] = lw;
        }
    }
}

// ---------------- small kernels ----------------
__global__ void save_cls_kernel(const float* __restrict__ gx, float* __restrict__ gcls)
{
    int idx = blockIdx.x * blockDim.x + threadIdx.x;
    if (idx >= BATCH * DIMM) return;
    int b = idx / DIMM, d = idx % DIMM;
    gcls[idx] = gx[((size_t)b * NTOK) * DIMM + d];
}

__global__ void write_out_kernel(const float* __restrict__ gx,
                                 const float* __restrict__ gcls,
                                 float* __restrict__ out)
{
    const int totalx = MROWS * DIMM;
    const int totalc = BATCH * DIMM;
    int idx = blockIdx.x * blockDim.x + threadIdx.x;
    if (idx < totalx)               out[idx] = gx[idx];
    else if (idx < totalx + totalc) out[idx] = gcls[idx - totalx];
}

// ---------------- host orchestration ----------------
struct DevPtrs {
    float *gx, *gqkv, *gcls;
    unsigned *xsh, *xsl, *ash, *asl, *hsh, *hsl;
    unsigned *wqh, *wql, *woh, *wol, *w1h, *w1l, *w2h, *w2l;
};

static void run_layer(int l, const DevPtrs& P,
                      const float* bo, const float* b1, const float* b2)
{
    const int gy = (MROWS + 127) / 128;  // 33
    // qkv = x @ Wqkv  (fp32 out only)
    tgemm_kernel<false,false,false,true,false><<<dim3(24, gy), 256, SM_TOTAL>>>(
        P.xsh, P.xsl, P.wqh + (size_t)l*WQKV_L, P.wql + (size_t)l*WQKV_L,
        nullptr, nullptr, P.gqkv, nullptr, nullptr, MROWS, DIMM, 3*DIMM);
    // attention -> split att
    fattn_kernel<<<dim3(33, BATCH*NHEADS), 128, ATT_SMEM>>>(P.gqkv, P.ash, P.asl);
    // x = x + att @ Wo + bo  (fp32 + split)
    tgemm_kernel<true,true,false,true,true><<<dim3(8, gy), 256, SM_TOTAL>>>(
        P.ash, P.asl, P.woh + (size_t)l*WO_L, P.wol + (size_t)l*WO_L,
        bo, P.gx, P.gx, P.xsh, P.xsl, MROWS, DIMM, DIMM);
    // h = gelu(x @ W1 + b1)  (split only)
    tgemm_kernel<true,false,true,false,true><<<dim3(32, gy), 256, SM_TOTAL>>>(
        P.xsh, P.xsl, P.w1h + (size_t)l*W1_L, P.w1l + (size_t)l*W1_L,
        b1, nullptr, nullptr, P.hsh, P.hsl, MROWS, DIMM, HID);
    // x = x + h @ W2 + b2  (fp32 + split)
    tgemm_kernel<true,true,false,true,true><<<dim3(8, gy), 256, SM_TOTAL>>>(
        P.hsh, P.hsl, P.w2h + (size_t)l*W2_L, P.w2l + (size_t)l*W2_L,
        b2, P.gx, P.gx, P.xsh, P.xsl, MROWS, HID, DIMM);
}

extern "C" void kernel_launch(void* const* d_in, const int* in_sizes, int n_in,
                              void* d_out, int out_size)
{
    const float* x_in = (const float*)d_in[0];
    const float* cls  = (const float*)d_in[1];
    const float* hW[7];
    const float* tW[7];
    for (int i = 0; i < 7; i++) hW[i] = (const float*)d_in[2 + i];
    for (int i = 0; i < 7; i++) tW[i] = (const float*)d_in[9 + i];

    cudaFuncSetAttribute(tgemm_kernel<false,false,false,true,false>,
                         cudaFuncAttributeMaxDynamicSharedMemorySize, SM_TOTAL);
    cudaFuncSetAttribute(tgemm_kernel<true,true,false,true,true>,
                         cudaFuncAttributeMaxDynamicSharedMemorySize, SM_TOTAL);
    cudaFuncSetAttribute(tgemm_kernel<true,false,true,false,true>,
                         cudaFuncAttributeMaxDynamicSharedMemorySize, SM_TOTAL);
    cudaFuncSetAttribute(fattn_kernel,
                         cudaFuncAttributeMaxDynamicSharedMemorySize, ATT_SMEM);

    DevPtrs P;
    cudaGetSymbolAddress((void**)&P.gx,   g_x);
    cudaGetSymbolAddress((void**)&P.gqkv, g_qkv);
    cudaGetSymbolAddress((void**)&P.gcls, g_cls);
    cudaGetSymbolAddress((void**)&P.xsh,  g_xs_h);
    cudaGetSymbolAddress((void**)&P.xsl,  g_xs_l);
    cudaGetSymbolAddress((void**)&P.ash,  g_as_h);
    cudaGetSymbolAddress((void**)&P.asl,  g_as_l);
    cudaGetSymbolAddress((void**)&P.hsh,  g_hs_h);
    cudaGetSymbolAddress((void**)&P.hsl,  g_hs_l);
    cudaGetSymbolAddress((void**)&P.wqh,  g_wqkv_h);
    cudaGetSymbolAddress((void**)&P.wql,  g_wqkv_l);
    cudaGetSymbolAddress((void**)&P.woh,  g_wo_h);
    cudaGetSymbolAddress((void**)&P.wol,  g_wo_l);
    cudaGetSymbolAddress((void**)&P.w1h,  g_w1_h);
    cudaGetSymbolAddress((void**)&P.w1l,  g_w1_l);
    cudaGetSymbolAddress((void**)&P.w2h,  g_w2_h);
    cudaGetSymbolAddress((void**)&P.w2l,  g_w2_l);

    // pre-split all weights (once per launch)
    split_w_kernel<<<dim3((WQKV_L + 255)/256, 8), 256>>>(hW[0], tW[0], P.wqh, P.wql, WQKV_L, 3*DIMM);
    split_w_kernel<<<dim3((WO_L   + 255)/256, 8), 256>>>(hW[1], tW[1], P.woh, P.wol, WO_L,   DIMM);
    split_w_kernel<<<dim3((W1_L   + 255)/256, 8), 256>>>(hW[3], tW[3], P.w1h, P.w1l, W1_L,   HID);
    split_w_kernel<<<dim3((W2_L   + 255)/256, 8), 256>>>(hW[5], tW[5], P.w2h, P.w2l, W2_L,   DIMM);

    // concat cls + x
    {
        int total = MROWS * DIMM / 2;
        concat_kernel<<<(total + 255) / 256, 256>>>(x_in, cls, P.gx, P.xsh, P.xsl);
    }

    for (int l = 0; l < L_HEAD; l++)
        run_layer(l, P, hW[2] + (size_t)l*DIMM, hW[4] + (size_t)l*HID, hW[6] + (size_t)l*DIMM);

    save_cls_kernel<<<(BATCH*DIMM + 255)/256, 256>>>(P.gx, P.gcls);

    for (int l = 0; l < L_TAIL; l++)
        run_layer(4 + l, P, tW[2] + (size_t)l*DIMM, tW[4] + (size_t)l*HID, tW[6] + (size_t)l*DIMM);

    {
        int total = MROWS * DIMM + BATCH * DIMM;
        write_out_kernel<<<(total + 255)/256, 256>>>(P.gx, P.gcls, (float*)d_out);
    }
}

// round 8
// speedup vs baseline: 3.8972x; 1.1965x over previous
#include <cuda_runtime.h>
#include <cuda_bf16.h>
#include <math.h>

// ---------------- problem constants ----------------
#define DIMM   1024
#define NHEADS 8
#define DHEAD  128
#define NTOK   2049
#define BATCH  2
#define MROWS  (BATCH*NTOK)  // 4098
#define HID    4096
#define L_HEAD 4
#define L_TAIL 4

// ---------------- scratch (device globals) ----------------
__device__ float g_x  [(size_t)MROWS*DIMM];
__device__ float g_qkv[(size_t)MROWS*3*DIMM];
__device__ float g_cls[(size_t)BATCH*DIMM];

__device__ unsigned g_xs_h[(size_t)MROWS*DIMM/2];
__device__ unsigned g_xs_l[(size_t)MROWS*DIMM/2];
__device__ unsigned g_as_h[(size_t)MROWS*DIMM/2];
__device__ unsigned g_as_l[(size_t)MROWS*DIMM/2];
__device__ unsigned g_hs_h[(size_t)MROWS*HID/2];
__device__ unsigned g_hs_l[(size_t)MROWS*HID/2];

#define WQKV_L (512*3072)
#define WO_L   (512*1024)
#define W1_L   (512*4096)
#define W2_L   (2048*1024)
__device__ unsigned g_wqkv_h[8*(size_t)WQKV_L];
__device__ unsigned g_wqkv_l[8*(size_t)WQKV_L];
__device__ unsigned g_wo_h[8*(size_t)WO_L];
__device__ unsigned g_wo_l[8*(size_t)WO_L];
__device__ unsigned g_w1_h[8*(size_t)W1_L];
__device__ unsigned g_w1_l[8*(size_t)W1_L];
__device__ unsigned g_w2_h[8*(size_t)W2_L];
__device__ unsigned g_w2_l[8*(size_t)W2_L];

// ---------------- bf16 helpers ----------------
__device__ __forceinline__ unsigned short f2bf(float x) {
    __nv_bfloat16 h = __float2bfloat16(x);
    return *reinterpret_cast<unsigned short*>(&h);
}
__device__ __forceinline__ float bf2f(unsigned short s) {
    __nv_bfloat16 h = *reinterpret_cast<__nv_bfloat16*>(&s);
    return __bfloat162float(h);
}
__device__ __forceinline__ void split_bf16(float x, unsigned short& hi, unsigned short& lo) {
    hi = f2bf(x);
    lo = f2bf(x - bf2f(hi));
}
__device__ __forceinline__ void split_pair(float a, float b, unsigned& hw, unsigned& lw) {
    unsigned short ah, al, bh, bl;
    split_bf16(a, ah, al);
    split_bf16(b, bh, bl);
    hw = (unsigned)ah | ((unsigned)bh << 16);
    lw = (unsigned)al | ((unsigned)bl << 16);
}

__device__ __forceinline__ void mma_bf16(float* c, const unsigned* a, const unsigned* b) {
    asm("mma.sync.aligned.m16n8k16.row.col.f32.bf16.bf16.f32 "
        "{%0,%1,%2,%3}, {%4,%5,%6,%7}, {%8,%9}, {%0,%1,%2,%3};"
        : "+f"(c[0]), "+f"(c[1]), "+f"(c[2]), "+f"(c[3])
        : "r"(a[0]), "r"(a[1]), "r"(a[2]), "r"(a[3]),
          "r"(b[0]), "r"(b[1]));
}

__device__ __forceinline__ void ldsm4(unsigned* r, const void* p) {
    unsigned a = (unsigned)__cvta_generic_to_shared(p);
    asm volatile("ldmatrix.sync.aligned.m8n8.x4.shared.b16 {%0,%1,%2,%3}, [%4];"
        : "=r"(r[0]), "=r"(r[1]), "=r"(r[2]), "=r"(r[3]) : "r"(a));
}

__device__ __forceinline__ void cpa16(void* dst, const void* src, int sz) {
    unsigned d = (unsigned)__cvta_generic_to_shared(dst);
    asm volatile("cp.async.cg.shared.global [%0], [%1], 16, %2;" :: "r"(d), "l"(src), "r"(sz));
}
__device__ __forceinline__ void cp_commit() { asm volatile("cp.async.commit_group;"); }
template<int N> __device__ __forceinline__ void cp_wait() {
    asm volatile("cp.async.wait_group %0;" :: "n"(N));
}

// ---------------- weight pre-split kernel ----------------
__global__ void split_w_kernel(const float* __restrict__ Wh, const float* __restrict__ Wt,
                               unsigned* __restrict__ oH, unsigned* __restrict__ oL,
                               int npairs, int N)
{
    int l = blockIdx.y;
    const float* W = (l < 4) ? (Wh + (size_t)l * npairs * 2)
                             : (Wt + (size_t)(l - 4) * npairs * 2);
    int idx = blockIdx.x * blockDim.x + threadIdx.x;
    if (idx >= npairs) return;
    int k2 = idx / N, n = idx % N;
    float a = W[(size_t)(2 * k2) * N + n];
    float b = W[(size_t)(2 * k2 + 1) * N + n];
    unsigned hw, lw;
    split_pair(a, b, hw, lw);
    size_t o = (size_t)l * npairs + idx;
    oH[o] = hw;
    oL[o] = lw;
}

// ---------------- concat cls + x ----------------
__global__ void concat_kernel(const float* __restrict__ x, const float* __restrict__ cls,
                              float* __restrict__ gx,
                              unsigned* __restrict__ xh, unsigned* __restrict__ xl)
{
    int idx = blockIdx.x * blockDim.x + threadIdx.x;
    int total = MROWS * DIMM / 2;
    if (idx >= total) return;
    int c2  = idx % (DIMM / 2);
    int row = idx / (DIMM / 2);
    int n = row % NTOK, b = row / NTOK;
    float v0, v1;
    if (n == 0) { v0 = cls[c2 * 2]; v1 = cls[c2 * 2 + 1]; }
    else {
        const float* p = x + ((size_t)b * (NTOK - 1) + (n - 1)) * DIMM + c2 * 2;
        v0 = p[0]; v1 = p[1];
    }
    gx[idx * 2] = v0; gx[idx * 2 + 1] = v1;
    unsigned hw, lw;
    split_pair(v0, v1, hw, lw);
    xh[idx] = hw; xl[idx] = lw;
}

// ---------------- tensor-core GEMM: pre-split inputs, 2-stage cp.async, 2 CTAs/SM --------
#define AST_B 80
#define STG_A (128*AST_B)          // 10240 per plane
#define BROW  136
#define STG_B (16*BROW*4)          // 8704 per plane
#define STG_BYTES (2*STG_A + 2*STG_B)   // 37888
#define NSTAGE 2
#define SM_TOTAL (NSTAGE*STG_BYTES)     // 75776

template<bool BIAS, bool RESID, bool DOGELU, bool W32, bool WS>
__global__ __launch_bounds__(256, 2)
void tgemm_kernel(const unsigned* __restrict__ AH, const unsigned* __restrict__ AL,
                  const unsigned* __restrict__ BH, const unsigned* __restrict__ BL,
                  const float* __restrict__ bias, const float* __restrict__ R,
                  float* __restrict__ C,
                  unsigned* __restrict__ OH, unsigned* __restrict__ OL,
                  int M, int K, int N)
{
    extern __shared__ char smem[];

    const int t    = threadIdx.x;
    const int warp = t >> 5;
    const int lane = t & 31;
    const int g    = lane >> 2;
    const int q    = lane & 3;
    const int wm   = warp & 1;
    const int wn   = warp >> 1;
    const int bm   = blockIdx.y * 128;
    const int bn   = blockIdx.x * 128;
    const int steps = K >> 5;

    float acc[4][4][4];
#pragma unroll
    for (int i = 0; i < 4; i++)
#pragma unroll
        for (int j = 0; j < 4; j++)
#pragma unroll
            for (int e = 0; e < 4; e++) acc[i][j][e] = 0.f;

    const int ar0 = t >> 2,  ac0 = (t & 3);
    const int ar1 = (t + 256) >> 2, ac1 = (t & 3);
    const int br0 = t >> 5,  bc0 = (t & 31);
    const int br1 = (t + 256) >> 5, bc1 = (t & 31);

    const unsigned short* AHg = (const unsigned short*)AH;
    const unsigned short* ALg = (const unsigned short*)AL;

    auto issue = [&](int s) {
        char* buf = smem + (s & 1) * STG_BYTES;
        char* AHs = buf;
        char* ALs = buf + STG_A;
        char* BHs = buf + 2 * STG_A;
        char* BLs = buf + 2 * STG_A + STG_B;
        int k0 = s * 32;
        {
            int gr = bm + ar0;
            int sz = (gr < M) ? 16 : 0;
            size_t so = (size_t)(gr < M ? gr : 0) * K + k0 + ac0 * 8;
            cpa16(AHs + ar0 * AST_B + ac0 * 16, AHg + so, sz);
            cpa16(ALs + ar0 * AST_B + ac0 * 16, ALg + so, sz);
            gr = bm + ar1;
            sz = (gr < M) ? 16 : 0;
            so = (size_t)(gr < M ? gr : 0) * K + k0 + ac1 * 8;
            cpa16(AHs + ar1 * AST_B + ac1 * 16, AHg + so, sz);
            cpa16(ALs + ar1 * AST_B + ac1 * 16, ALg + so, sz);
        }
        {
            size_t gw = ((size_t)(k0 / 2 + br0)) * N + bn;
            cpa16(BHs + br0 * (BROW * 4) + bc0 * 16, (const char*)BH + gw * 4 + bc0 * 16, 16);
            cpa16(BLs + br0 * (BROW * 4) + bc0 * 16, (const char*)BL + gw * 4 + bc0 * 16, 16);
            gw = ((size_t)(k0 / 2 + br1)) * N + bn;
            cpa16(BHs + br1 * (BROW * 4) + bc1 * 16, (const char*)BH + gw * 4 + bc1 * 16, 16);
            cpa16(BLs + br1 * (BROW * 4) + bc1 * 16, (const char*)BL + gw * 4 + bc1 * 16, 16);
        }
        cp_commit();
    };

    issue(0);

    const int lanebase = (wm * 64 + (lane & 7) + ((lane >> 3) & 1) * 8) * AST_B + (lane >> 4) * 16;

    for (int s = 0; s < steps; s++) {
        if (s + 1 < steps) { issue(s + 1); cp_wait<1>(); }
        else               { cp_wait<0>(); }
        __syncthreads();

        const char* buf = smem + (s & 1) * STG_BYTES;
        const char* AHs = buf;
        const char* ALs = buf + STG_A;
        const unsigned* BHw = (const unsigned*)(buf + 2 * STG_A);
        const unsigned* BLw = (const unsigned*)(buf + 2 * STG_A + STG_B);

#pragma unroll
        for (int ko = 0; ko < 2; ko++) {
            unsigned bh[4][2], bl[4][2];
#pragma unroll
            for (int ni = 0; ni < 4; ni++) {
                int nb = wn * 32 + g + ni * 8;
                bh[ni][0] = BHw[(q + ko * 8) * BROW + nb];
                bh[ni][1] = BHw[(q + 4 + ko * 8) * BROW + nb];
                bl[ni][0] = BLw[(q + ko * 8) * BROW + nb];
                bl[ni][1] = BLw[(q + 4 + ko * 8) * BROW + nb];
            }
#pragma unroll
            for (int mi = 0; mi < 4; mi++) {
                unsigned ah[4], al[4];
                ldsm4(ah, AHs + lanebase + mi * (16 * AST_B) + ko * 32);
                ldsm4(al, ALs + lanebase + mi * (16 * AST_B) + ko * 32);
#pragma unroll
                for (int ni = 0; ni < 4; ni++) {
                    mma_bf16(acc[mi][ni], ah, bh[ni]);
                    mma_bf16(acc[mi][ni], ah, bl[ni]);
                    mma_bf16(acc[mi][ni], al, bh[ni]);
                }
            }
        }
        __syncthreads();
    }

    // ---- epilogue ----
    const int Nw = N >> 1;
#pragma unroll
    for (int mi = 0; mi < 4; mi++) {
        int r0 = bm + wm * 64 + mi * 16 + g;
#pragma unroll
        for (int ni = 0; ni < 4; ni++) {
            int cb = bn + wn * 32 + ni * 8 + 2 * q;
            float v[4];
#pragma unroll
            for (int e = 0; e < 4; e++) {
                v[e] = acc[mi][ni][e];
                if (BIAS) v[e] += bias[cb + (e & 1)];
                if (DOGELU) v[e] = 0.5f * v[e] * (1.f + erff(v[e] * 0.70710678118f));
            }
#pragma unroll
            for (int half = 0; half < 2; half++) {
                int gr = r0 + half * 8;
                if (gr >= M) continue;
                float a = v[half * 2], b = v[half * 2 + 1];
                if (RESID) {
                    a += R[(size_t)gr * N + cb];
                    b += R[(size_t)gr * N + cb + 1];
                }
                if (W32) {
                    C[(size_t)gr * N + cb]     = a;
                    C[(size_t)gr * N + cb + 1] = b;
                }
                if (WS) {
                    unsigned hw, lw;
                    split_pair(a, b, hw, lw);
                    size_t wi = (size_t)gr * Nw + (cb >> 1);
                    OH[wi] = hw;
                    OL[wi] = lw;
                }
            }
        }
    }
}

// ---------------- flash attention (3xBF16 mma) ----------------
#define ATT_QW 4352
#define ATT_KW 4608
#define ATT_VW 4352
#define ATT_SMEM ((2*ATT_QW + 2*ATT_KW + 2*ATT_VW) * 4)

__global__ __launch_bounds__(128, 1)
void fattn_kernel(const float* __restrict__ qkv,
                  unsigned* __restrict__ OH, unsigned* __restrict__ OL)
{
    extern __shared__ unsigned smw[];
    unsigned* QH = smw;
    unsigned* QL = QH + ATT_QW;
    unsigned* KH = QL + ATT_QW;
    unsigned* KL = KH + ATT_KW;
    unsigned* VH = KL + ATT_KW;
    unsigned* VL = VH + ATT_VW;

    const int t    = threadIdx.x;
    const int lane = t & 31;
    const int w    = t >> 5;
    const int g    = lane >> 2;
    const int q    = lane & 3;
    const int qt   = 32 - blockIdx.x;
    const int bh   = blockIdx.y;
    const int h    = bh & 7;
    const int b    = bh >> 3;
    const float scale = 0.03125f;

    const float* base = qkv + (size_t)b * NTOK * 3072;

#pragma unroll
    for (int i = 0; i < 16; i++) {
        int idx = i * 128 + t;
        int row = idx >> 5;
        int c4  = (idx & 31) * 4;
        int grow = qt * 64 + row;
        float4 v = make_float4(0.f, 0.f, 0.f, 0.f);
        if (grow < NTOK) v = *(const float4*)(base + (size_t)grow * 3072 + h * DHEAD + c4);
        int wi = row * 68 + (c4 >> 1);
        unsigned hw, lw;
        split_pair(v.x * scale, v.y * scale, hw, lw);
        QH[wi] = hw; QL[wi] = lw;
        split_pair(v.z * scale, v.w * scale, hw, lw);
        QH[wi + 1] = hw; QL[wi + 1] = lw;
    }

    float o[16][4];
#pragma unroll
    for (int ni = 0; ni < 16; ni++)
#pragma unroll
        for (int e = 0; e < 4; e++) o[ni][e] = 0.f;
    float mrow[2] = {-1e30f, -1e30f};
    float lrow[2] = {0.f, 0.f};

    for (int jt = 0; jt <= qt; jt++) {
        __syncthreads();

#pragma unroll
        for (int i = 0; i < 16; i++) {
            int idx = i * 128 + t;
            int key = idx >> 5;
            int c4  = (idx & 31) * 4;
            int gkey = jt * 64 + key;
            float4 kv = make_float4(0.f, 0.f, 0.f, 0.f);
            float4 vv = make_float4(0.f, 0.f, 0.f, 0.f);
            if (gkey < NTOK) {
                const float* rp = base + (size_t)gkey * 3072 + h * DHEAD + c4;
                kv = *(const float4*)(rp + 1024);
                vv = *(const float4*)(rp + 2048);
            }
            {
                int wi = (c4 >> 1) * 72 + key;
                unsigned short hh[4], ll[4];
                split_bf16(kv.x, hh[0], ll[0]); split_bf16(kv.y, hh[1], ll[1]);
                split_bf16(kv.z, hh[2], ll[2]); split_bf16(kv.w, hh[3], ll[3]);
                KH[wi]      = (unsigned)hh[0] | ((unsigned)hh[1] << 16);
                KH[wi + 72] = (unsigned)hh[2] | ((unsigned)hh[3] << 16);
                KL[wi]      = (unsigned)ll[0] | ((unsigned)ll[1] << 16);
                KL[wi + 72] = (unsigned)ll[2] | ((unsigned)ll[3] << 16);
            }
            {
                float av[4] = {vv.x, vv.y, vv.z, vv.w};
                int half = key & 1;
                int wb = (key >> 1) * 136 + c4;
                unsigned short* VHs = (unsigned short*)VH;
                unsigned short* VLs = (unsigned short*)VL;
#pragma unroll
                for (int e = 0; e < 4; e++) {
                    unsigned short hh, ll;
                    split_bf16(av[e], hh, ll);
                    VHs[(wb + e) * 2 + half] = hh;
                    VLs[(wb + e) * 2 + half] = ll;
                }
            }
        }
        __syncthreads();

        float s[8][4];
#pragma unroll
        for (int ni = 0; ni < 8; ni++)
#pragma unroll
            for (int e = 0; e < 4; e++) s[ni][e] = 0.f;

        const int r0 = w * 16 + g;
#pragma unroll
        for (int ko = 0; ko < 8; ko++) {
            unsigned qh[4], ql[4];
            int w0 = r0 * 68 + q + ko * 8;
            int w1 = (r0 + 8) * 68 + q + ko * 8;
            qh[0] = QH[w0];     qh[1] = QH[w1];
            qh[2] = QH[w0 + 4]; qh[3] = QH[w1 + 4];
            ql[0] = QL[w0];     ql[1] = QL[w1];
            ql[2] = QL[w0 + 4]; ql[3] = QL[w1 + 4];
#pragma unroll
            for (int ni = 0; ni < 8; ni++) {
                int nb = ni * 8 + g;
                unsigned bhf[2], blf[2];
                bhf[0] = KH[(q + ko * 8) * 72 + nb];
                bhf[1] = KH[(q + 4 + ko * 8) * 72 + nb];
                blf[0] = KL[(q + ko * 8) * 72 + nb];
                blf[1] = KL[(q + 4 + ko * 8) * 72 + nb];
                mma_bf16(s[ni], qh, bhf);
                mma_bf16(s[ni], qh, blf);
                mma_bf16(s[ni], ql, bhf);
            }
        }

        if (jt == qt) {
            int rbase = qt * 64 + w * 16 + g;
#pragma unroll
            for (int ni = 0; ni < 8; ni++) {
                int cbase = jt * 64 + ni * 8 + 2 * q;
#pragma unroll
                for (int e = 0; e < 4; e++) {
                    int row = rbase + (e >= 2 ? 8 : 0);
                    int col = cbase + (e & 1);
                    if (col > row) s[ni][e] = -1e30f;
                }
            }
        }

        float mt[2] = {-1e30f, -1e30f};
#pragma unroll
        for (int ni = 0; ni < 8; ni++) {
            mt[0] = fmaxf(mt[0], fmaxf(s[ni][0], s[ni][1]));
            mt[1] = fmaxf(mt[1], fmaxf(s[ni][2], s[ni][3]));
        }
#pragma unroll
        for (int d = 1; d <= 2; d <<= 1) {
            mt[0] = fmaxf(mt[0], __shfl_xor_sync(0xFFFFFFFFu, mt[0], d));
            mt[1] = fmaxf(mt[1], __shfl_xor_sync(0xFFFFFFFFu, mt[1], d));
        }
        float mn[2] = {fmaxf(mrow[0], mt[0]), fmaxf(mrow[1], mt[1])};
        float corr[2] = {__expf(mrow[0] - mn[0]), __expf(mrow[1] - mn[1])};

        float rs[2] = {0.f, 0.f};
#pragma unroll
        for (int ni = 0; ni < 8; ni++) {
#pragma unroll
            for (int e = 0; e < 4; e++) {
                float pv = __expf(s[ni][e] - mn[e >> 1]);
                s[ni][e] = pv;
                rs[e >> 1] += pv;
            }
        }
#pragma unroll
        for (int d = 1; d <= 2; d <<= 1) {
            rs[0] += __shfl_xor_sync(0xFFFFFFFFu, rs[0], d);
            rs[1] += __shfl_xor_sync(0xFFFFFFFFu, rs[1], d);
        }
        lrow[0] = lrow[0] * corr[0] + rs[0];
        lrow[1] = lrow[1] * corr[1] + rs[1];
        mrow[0] = mn[0];
        mrow[1] = mn[1];
#pragma unroll
        for (int ni = 0; ni < 16; ni++) {
            o[ni][0] *= corr[0]; o[ni][1] *= corr[0];
            o[ni][2] *= corr[1]; o[ni][3] *= corr[1];
        }

#pragma unroll
        for (int kp = 0; kp < 4; kp++) {
            unsigned ph[4], pl[4];
            split_pair(s[2*kp][0],   s[2*kp][1],   ph[0], pl[0]);
            split_pair(s[2*kp][2],   s[2*kp][3],   ph[1], pl[1]);
            split_pair(s[2*kp+1][0], s[2*kp+1][1], ph[2], pl[2]);
            split_pair(s[2*kp+1][2], s[2*kp+1][3], ph[3], pl[3]);
#pragma unroll
            for (int ni = 0; ni < 16; ni++) {
                int nb = ni * 8 + g;
                unsigned bhf[2], blf[2];
                bhf[0] = VH[(q + kp * 8) * 136 + nb];
                bhf[1] = VH[(q + 4 + kp * 8) * 136 + nb];
                blf[0] = VL[(q + kp * 8) * 136 + nb];
                blf[1] = VL[(q + 4 + kp * 8) * 136 + nb];
                mma_bf16(o[ni], ph, bhf);
                mma_bf16(o[ni], ph, blf);
                mma_bf16(o[ni], pl, bhf);
            }
        }
    }

    float inv[2] = {1.f / lrow[0], 1.f / lrow[1]};
    int rbase = qt * 64 + w * 16 + g;
#pragma unroll
    for (int ni = 0; ni < 16; ni++) {
        int cb = h * DHEAD + ni * 8 + 2 * q;
#pragma unroll
        for (int half = 0; half < 2; half++) {
            int row = rbase + half * 8;
            if (row >= NTOK) continue;
            unsigned hw, lw;
            split_pair(o[ni][half*2] * inv[half], o[ni][half*2+1] * inv[half], hw, lw);
            size_t wi = (size_t)(b * NTOK + row) * (DIMM / 2) + (cb >> 1);
            OH[wi] = hw;
            OL[wi] = lw;
        }
    }
}

// ---------------- small kernels ----------------
__global__ void save_cls_kernel(const float* __restrict__ gx, float* __restrict__ gcls)
{
    int idx = blockIdx.x * blockDim.x + threadIdx.x;
    if (idx >= BATCH * DIMM) return;
    int b = idx / DIMM, d = idx % DIMM;
    gcls[idx] = gx[((size_t)b * NTOK) * DIMM + d];
}

__global__ void write_out_kernel(const float* __restrict__ gx,
                                 const float* __restrict__ gcls,
                                 float* __restrict__ out)
{
    const int totalx = MROWS * DIMM;
    const int totalc = BATCH * DIMM;
    int idx = blockIdx.x * blockDim.x + threadIdx.x;
    if (idx < totalx)               out[idx] = gx[idx];
    else if (idx < totalx + totalc) out[idx] = gcls[idx - totalx];
}

// ---------------- host orchestration ----------------
struct DevPtrs {
    float *gx, *gqkv, *gcls;
    unsigned *xsh, *xsl, *ash, *asl, *hsh, *hsl;
    unsigned *wqh, *wql, *woh, *wol, *w1h, *w1l, *w2h, *w2l;
};

static void run_layer(int l, const DevPtrs& P,
                      const float* bo, const float* b1, const float* b2)
{
    const int gy = (MROWS + 127) / 128;  // 33
    tgemm_kernel<false,false,false,true,false><<<dim3(24, gy), 256, SM_TOTAL>>>(
        P.xsh, P.xsl, P.wqh + (size_t)l*WQKV_L, P.wql + (size_t)l*WQKV_L,
        nullptr, nullptr, P.gqkv, nullptr, nullptr, MROWS, DIMM, 3*DIMM);
    fattn_kernel<<<dim3(33, BATCH*NHEADS), 128, ATT_SMEM>>>(P.gqkv, P.ash, P.asl);
    tgemm_kernel<true,true,false,true,true><<<dim3(8, gy), 256, SM_TOTAL>>>(
        P.ash, P.asl, P.woh + (size_t)l*WO_L, P.wol + (size_t)l*WO_L,
        bo, P.gx, P.gx, P.xsh, P.xsl, MROWS, DIMM, DIMM);
    tgemm_kernel<true,false,true,false,true><<<dim3(32, gy), 256, SM_TOTAL>>>(
        P.xsh, P.xsl, P.w1h + (size_t)l*W1_L, P.w1l + (size_t)l*W1_L,
        b1, nullptr, nullptr, P.hsh, P.hsl, MROWS, DIMM, HID);
    tgemm_kernel<true,true,false,true,true><<<dim3(8, gy), 256, SM_TOTAL>>>(
        P.hsh, P.hsl, P.w2h + (size_t)l*W2_L, P.w2l + (size_t)l*W2_L,
        b2, P.gx, P.gx, P.xsh, P.xsl, MROWS, HID, DIMM);
}

extern "C" void kernel_launch(void* const* d_in, const int* in_sizes, int n_in,
                              void* d_out, int out_size)
{
    const float* x_in = (const float*)d_in[0];
    const float* cls  = (const float*)d_in[1];
    const float* hW[7];
    const float* tW[7];
    for (int i = 0; i < 7; i++) hW[i] = (const float*)d_in[2 + i];
    for (int i = 0; i < 7; i++) tW[i] = (const float*)d_in[9 + i];

    cudaFuncSetAttribute(tgemm_kernel<false,false,false,true,false>,
                         cudaFuncAttributeMaxDynamicSharedMemorySize, SM_TOTAL);
    cudaFuncSetAttribute(tgemm_kernel<true,true,false,true,true>,
                         cudaFuncAttributeMaxDynamicSharedMemorySize, SM_TOTAL);
    cudaFuncSetAttribute(tgemm_kernel<true,false,true,false,true>,
                         cudaFuncAttributeMaxDynamicSharedMemorySize, SM_TOTAL);
    cudaFuncSetAttribute(fattn_kernel,
                         cudaFuncAttributeMaxDynamicSharedMemorySize, ATT_SMEM);

    DevPtrs P;
    cudaGetSymbolAddress((void**)&P.gx,   g_x);
    cudaGetSymbolAddress((void**)&P.gqkv, g_qkv);
    cudaGetSymbolAddress((void**)&P.gcls, g_cls);
    cudaGetSymbolAddress((void**)&P.xsh,  g_xs_h);
    cudaGetSymbolAddress((void**)&P.xsl,  g_xs_l);
    cudaGetSymbolAddress((void**)&P.ash,  g_as_h);
    cudaGetSymbolAddress((void**)&P.asl,  g_as_l);
    cudaGetSymbolAddress((void**)&P.hsh,  g_hs_h);
    cudaGetSymbolAddress((void**)&P.hsl,  g_hs_l);
    cudaGetSymbolAddress((void**)&P.wqh,  g_wqkv_h);
    cudaGetSymbolAddress((void**)&P.wql,  g_wqkv_l);
    cudaGetSymbolAddress((void**)&P.woh,  g_wo_h);
    cudaGetSymbolAddress((void**)&P.wol,  g_wo_l);
    cudaGetSymbolAddress((void**)&P.w1h,  g_w1_h);
    cudaGetSymbolAddress((void**)&P.w1l,  g_w1_l);
    cudaGetSymbolAddress((void**)&P.w2h,  g_w2_h);
    cudaGetSymbolAddress((void**)&P.w2l,  g_w2_l);

    split_w_kernel<<<dim3((WQKV_L + 255)/256, 8), 256>>>(hW[0], tW[0], P.wqh, P.wql, WQKV_L, 3*DIMM);
    split_w_kernel<<<dim3((WO_L   + 255)/256, 8), 256>>>(hW[1], tW[1], P.woh, P.wol, WO_L,   DIMM);
    split_w_kernel<<<dim3((W1_L   + 255)/256, 8), 256>>>(hW[3], tW[3], P.w1h, P.w1l, W1_L,   HID);
    split_w_kernel<<<dim3((W2_L   + 255)/256, 8), 256>>>(hW[5], tW[5], P.w2h, P.w2l, W2_L,   DIMM);

    {
        int total = MROWS * DIMM / 2;
        concat_kernel<<<(total + 255) / 256, 256>>>(x_in, cls, P.gx, P.xsh, P.xsl);
    }

    for (int l = 0; l < L_HEAD; l++)
        run_layer(l, P, hW[2] + (size_t)l*DIMM, hW[4] + (size_t)l*HID, hW[6] + (size_t)l*DIMM);

    save_cls_kernel<<<(BATCH*DIMM + 255)/256, 256>>>(P.gx, P.gcls);

    for (int l = 0; l < L_TAIL; l++)
        run_layer(4 + l, P, tW[2] + (size_t)l*DIMM, tW[4] + (size_t)l*HID, tW[6] + (size_t)l*DIMM);

    {
        int total = MROWS * DIMM + BATCH * DIMM;
        write_out_kernel<<<(total + 255)/256, 256>>>(P.gx, P.gcls, (float*)d_out);
    }
}

// round 12
// speedup vs baseline: 4.2014x; 1.0781x over previous
#include <cuda_runtime.h>
#include <cuda_bf16.h>
#include <math.h>
#include <stdint.h>

// ---------------- problem constants ----------------
#define DIMM   1024
#define NHEADS 8
#define DHEAD  128
#define NTOK   2049
#define BATCH  2
#define MROWS  (BATCH*NTOK)  // 4098
#define HID    4096
#define L_HEAD 4
#define L_TAIL 4

// ---------------- scratch (device globals) ----------------
__device__ __align__(16) float g_x  [(size_t)MROWS*DIMM];
__device__ __align__(16) float g_cls[(size_t)BATCH*DIMM];

// activation hi/lo splits (word = 2 shorts along N)
__device__ __align__(16) unsigned g_xs_h[(size_t)MROWS*DIMM/2];
__device__ __align__(16) unsigned g_xs_l[(size_t)MROWS*DIMM/2];
__device__ __align__(16) unsigned g_as_h[(size_t)MROWS*DIMM/2];
__device__ __align__(16) unsigned g_as_l[(size_t)MROWS*DIMM/2];
__device__ __align__(16) unsigned g_hs_h[(size_t)MROWS*HID/2];
__device__ __align__(16) unsigned g_hs_l[(size_t)MROWS*HID/2];
// qkv split planes: word idx = tok*1536 + colpair
__device__ __align__(16) unsigned g_qs_h[(size_t)MROWS*3*DIMM/2];
__device__ __align__(16) unsigned g_qs_l[(size_t)MROWS*3*DIMM/2];

// weight splits, pre-tiled: word idx = k2*N + n holds (k even, k odd) shorts for col n
#define WQKV_L (512*3072)
#define WO_L   (512*1024)
#define W1_L   (512*4096)
#define W2_L   (2048*1024)
__device__ __align__(16) unsigned g_wqkv_h[8*(size_t)WQKV_L];
__device__ __align__(16) unsigned g_wqkv_l[8*(size_t)WQKV_L];
__device__ __align__(16) unsigned g_wo_h[8*(size_t)WO_L];
__device__ __align__(16) unsigned g_wo_l[8*(size_t)WO_L];
__device__ __align__(16) unsigned g_w1_h[8*(size_t)W1_L];
__device__ __align__(16) unsigned g_w1_l[8*(size_t)W1_L];
__device__ __align__(16) unsigned g_w2_h[8*(size_t)W2_L];
__device__ __align__(16) unsigned g_w2_l[8*(size_t)W2_L];

// ---------------- bf16 helpers ----------------
__device__ __forceinline__ unsigned short f2bf(float x) {
    __nv_bfloat16 h = __float2bfloat16(x);
    return *reinterpret_cast<unsigned short*>(&h);
}
__device__ __forceinline__ float bf2f(unsigned short s) {
    __nv_bfloat16 h = *reinterpret_cast<__nv_bfloat16*>(&s);
    return __bfloat162float(h);
}
__device__ __forceinline__ void split_bf16(float x, unsigned short& hi, unsigned short& lo) {
    hi = f2bf(x);
    lo = f2bf(x - bf2f(hi));
}
__device__ __forceinline__ void split_pair(float a, float b, unsigned& hw, unsigned& lw) {
    unsigned short ah, al, bh, bl;
    split_bf16(a, ah, al);
    split_bf16(b, bh, bl);
    hw = (unsigned)ah | ((unsigned)bh << 16);
    lw = (unsigned)al | ((unsigned)bl << 16);
}

__device__ __forceinline__ void mma_bf16(float* c, const unsigned* a, const unsigned* b) {
    asm("mma.sync.aligned.m16n8k16.row.col.f32.bf16.bf16.f32 "
        "{%0,%1,%2,%3}, {%4,%5,%6,%7}, {%8,%9}, {%0,%1,%2,%3};"
        : "+f"(c[0]), "+f"(c[1]), "+f"(c[2]), "+f"(c[3])
        : "r"(a[0]), "r"(a[1]), "r"(a[2]), "r"(a[3]),
          "r"(b[0]), "r"(b[1]));
}

__device__ __forceinline__ void ldsm4(unsigned* r, const void* p) {
    unsigned a = (unsigned)__cvta_generic_to_shared(p);
    asm volatile("ldmatrix.sync.aligned.m8n8.x4.shared.b16 {%0,%1,%2,%3}, [%4];"
        : "=r"(r[0]), "=r"(r[1]), "=r"(r[2]), "=r"(r[3]) : "r"(a));
}

__device__ __forceinline__ void cpa16(void* dst, const void* src, int sz) {
    unsigned d = (unsigned)__cvta_generic_to_shared(dst);
    asm volatile("cp.async.cg.shared.global [%0], [%1], 16, %2;" :: "r"(d), "l"(src), "r"(sz));
}
__device__ __forceinline__ void cp_commit() { asm volatile("cp.async.commit_group;"); }
template<int N> __device__ __forceinline__ void cp_wait() {
    asm volatile("cp.async.wait_group %0;" :: "n"(N));
}

// ---------------- weight pre-split kernel ----------------
__global__ void split_w_kernel(const float* __restrict__ Wh, const float* __restrict__ Wt,
                               unsigned* __restrict__ oH, unsigned* __restrict__ oL,
                               int npairs, int N)
{
    int l = blockIdx.y;
    const float* W = (l < 4) ? (Wh + (size_t)l * npairs * 2)
                             : (Wt + (size_t)(l - 4) * npairs * 2);
    int idx = blockIdx.x * blockDim.x + threadIdx.x;
    if (idx >= npairs) return;
    int k2 = idx / N, n = idx % N;
    float a = W[(size_t)(2 * k2) * N + n];
    float b = W[(size_t)(2 * k2 + 1) * N + n];
    unsigned hw, lw;
    split_pair(a, b, hw, lw);
    size_t o = (size_t)l * npairs + idx;
    oH[o] = hw;
    oL[o] = lw;
}

// ---------------- concat cls + x ----------------
__global__ void concat_kernel(const float* __restrict__ x, const float* __restrict__ cls,
                              float* __restrict__ gx,
                              unsigned* __restrict__ xh, unsigned* __restrict__ xl)
{
    int idx = blockIdx.x * blockDim.x + threadIdx.x;
    int total = MROWS * DIMM / 2;
    if (idx >= total) return;
    int c2  = idx % (DIMM / 2);
    int row = idx / (DIMM / 2);
    int n = row % NTOK, b = row / NTOK;
    float v0, v1;
    if (n == 0) { v0 = cls[c2 * 2]; v1 = cls[c2 * 2 + 1]; }
    else {
        const float* p = x + ((size_t)b * (NTOK - 1) + (n - 1)) * DIMM + c2 * 2;
        v0 = p[0]; v1 = p[1];
    }
    gx[idx * 2] = v0; gx[idx * 2 + 1] = v1;
    unsigned hw, lw;
    split_pair(v0, v1, hw, lw);
    xh[idx] = hw; xl[idx] = lw;
}

// ---------------- tensor-core GEMM: 3-stage single-barrier cp.async, 2 CTAs/SM ----------
#define AST_B 80
#define STG_A (128*AST_B)          // 10240 per plane
#define BROW  136
#define STG_B (16*BROW*4)          // 8704 per plane
#define STG_BYTES (2*STG_A + 2*STG_B)   // 37888
#define NSTAGE 3
#define SM_TOTAL (NSTAGE*STG_BYTES)     // 113664

template<bool BIAS, bool RESID, bool DOGELU, bool W32, bool WS>
__global__ __launch_bounds__(256, 2)
void tgemm_kernel(const unsigned* __restrict__ AH, const unsigned* __restrict__ AL,
                  const unsigned* __restrict__ BH, const unsigned* __restrict__ BL,
                  const float* __restrict__ bias, const float* __restrict__ R,
                  float* __restrict__ C,
                  unsigned* __restrict__ OH, unsigned* __restrict__ OL,
                  int M, int K, int N)
{
    extern __shared__ char smem[];

    const int t    = threadIdx.x;
    const int warp = t >> 5;
    const int lane = t & 31;
    const int g    = lane >> 2;
    const int q    = lane & 3;
    const int wm   = warp & 1;
    const int wn   = warp >> 1;
    const int bm   = blockIdx.y * 128;
    const int bn   = blockIdx.x * 128;
    const int steps = K >> 5;

    float acc[4][4][4];
#pragma unroll
    for (int i = 0; i < 4; i++)
#pragma unroll
        for (int j = 0; j < 4; j++)
#pragma unroll
            for (int e = 0; e < 4; e++) acc[i][j][e] = 0.f;

    const int ar0 = t >> 2,  ac0 = (t & 3);
    const int ar1 = (t + 256) >> 2, ac1 = (t & 3);
    const int br0 = t >> 5,  bc0 = (t & 31);
    const int br1 = (t + 256) >> 5, bc1 = (t & 31);

    const unsigned short* AHg = (const unsigned short*)AH;
    const unsigned short* ALg = (const unsigned short*)AL;

    auto issue = [&](int s) {
        char* buf = smem + (s % NSTAGE) * STG_BYTES;
        char* AHs = buf;
        char* ALs = buf + STG_A;
        char* BHs = buf + 2 * STG_A;
        char* BLs = buf + 2 * STG_A + STG_B;
        int k0 = s * 32;
        {
            int gr = bm + ar0;
            int sz = (gr < M) ? 16 : 0;
            size_t so = (size_t)(gr < M ? gr : 0) * K + k0 + ac0 * 8;
            cpa16(AHs + ar0 * AST_B + ac0 * 16, AHg + so, sz);
            cpa16(ALs + ar0 * AST_B + ac0 * 16, ALg + so, sz);
            gr = bm + ar1;
            sz = (gr < M) ? 16 : 0;
            so = (size_t)(gr < M ? gr : 0) * K + k0 + ac1 * 8;
            cpa16(AHs + ar1 * AST_B + ac1 * 16, AHg + so, sz);
            cpa16(ALs + ar1 * AST_B + ac1 * 16, ALg + so, sz);
        }
        {
            size_t gw = ((size_t)(k0 / 2 + br0)) * N + bn;
            cpa16(BHs + br0 * (BROW * 4) + bc0 * 16, (const char*)BH + gw * 4 + bc0 * 16, 16);
            cpa16(BLs + br0 * (BROW * 4) + bc0 * 16, (const char*)BL + gw * 4 + bc0 * 16, 16);
            gw = ((size_t)(k0 / 2 + br1)) * N + bn;
            cpa16(BHs + br1 * (BROW * 4) + bc1 * 16, (const char*)BH + gw * 4 + bc1 * 16, 16);
            cpa16(BLs + br1 * (BROW * 4) + bc1 * 16, (const char*)BL + gw * 4 + bc1 * 16, 16);
        }
        cp_commit();
    };

    issue(0);
    if (steps > 1) issue(1);

    const int lanebase = (wm * 64 + (lane & 7) + ((lane >> 3) & 1) * 8) * AST_B + (lane >> 4) * 16;

    for (int s = 0; s < steps; s++) {
        if (s + 1 < steps) cp_wait<1>();
        else               cp_wait<0>();
        __syncthreads();

        const char* buf = smem + (s % NSTAGE) * STG_BYTES;
        const char* AHs = buf;
        const char* ALs = buf + STG_A;
        const unsigned* BHw = (const unsigned*)(buf + 2 * STG_A);
        const unsigned* BLw = (const unsigned*)(buf + 2 * STG_A + STG_B);

#pragma unroll
        for (int ko = 0; ko < 2; ko++) {
            unsigned bh[4][2], bl[4][2];
#pragma unroll
            for (int ni = 0; ni < 4; ni++) {
                int nb = wn * 32 + g + ni * 8;
                bh[ni][0] = BHw[(q + ko * 8) * BROW + nb];
                bh[ni][1] = BHw[(q + 4 + ko * 8) * BROW + nb];
                bl[ni][0] = BLw[(q + ko * 8) * BROW + nb];
                bl[ni][1] = BLw[(q + 4 + ko * 8) * BROW + nb];
            }
#pragma unroll
            for (int mi = 0; mi < 4; mi++) {
                unsigned ah[4], al[4];
                ldsm4(ah, AHs + lanebase + mi * (16 * AST_B) + ko * 32);
                ldsm4(al, ALs + lanebase + mi * (16 * AST_B) + ko * 32);
#pragma unroll
                for (int ni = 0; ni < 4; ni++) {
                    mma_bf16(acc[mi][ni], ah, bh[ni]);
                    mma_bf16(acc[mi][ni], ah, bl[ni]);
                    mma_bf16(acc[mi][ni], al, bh[ni]);
                }
            }
        }

        if (s + 2 < steps) issue(s + 2);   // buffer (s+2)%3: all warps done with it (barrier above)
    }

    // ---- epilogue (register -> global, no smem) ----
    const int Nw = N >> 1;
#pragma unroll
    for (int mi = 0; mi < 4; mi++) {
        int r0 = bm + wm * 64 + mi * 16 + g;
#pragma unroll
        for (int ni = 0; ni < 4; ni++) {
            int cb = bn + wn * 32 + ni * 8 + 2 * q;
            float v[4];
#pragma unroll
            for (int e = 0; e < 4; e++) {
                v[e] = acc[mi][ni][e];
                if (BIAS) v[e] += bias[cb + (e & 1)];
                if (DOGELU) v[e] = 0.5f * v[e] * (1.f + erff(v[e] * 0.70710678118f));
            }
#pragma unroll
            for (int half = 0; half < 2; half++) {
                int gr = r0 + half * 8;
                if (gr >= M) continue;
                float a = v[half * 2], b = v[half * 2 + 1];
                if (RESID) {
                    a += R[(size_t)gr * N + cb];
                    b += R[(size_t)gr * N + cb + 1];
                }
                if (W32) {
                    C[(size_t)gr * N + cb]     = a;
                    C[(size_t)gr * N + cb + 1] = b;
                }
                if (WS) {
                    unsigned hw, lw;
                    split_pair(a, b, hw, lw);
                    size_t wi = (size_t)gr * Nw + (cb >> 1);
                    OH[wi] = hw;
                    OL[wi] = lw;
                }
            }
        }
    }
}

// ---------------- flash attention (3xBF16 mma.sync), pre-split qkv input ----------------
#define ATT_QW 4352
#define ATT_KW 4608
#define ATT_VW 4352
#define ATT_SMEM ((2*ATT_QW + 2*ATT_KW + 2*ATT_VW) * 4)

__global__ __launch_bounds__(128, 1)
void fattn_kernel(const unsigned* __restrict__ QVH, const unsigned* __restrict__ QVL,
                  unsigned* __restrict__ OH, unsigned* __restrict__ OL)
{
    extern __shared__ unsigned smw[];
    unsigned* QH = smw;
    unsigned* QL = QH + ATT_QW;
    unsigned* KH = QL + ATT_QW;
    unsigned* KL = KH + ATT_KW;
    unsigned* VH = KL + ATT_KW;
    unsigned* VL = VH + ATT_VW;

    const int t    = threadIdx.x;
    const int lane = t & 31;
    const int w    = t >> 5;
    const int g    = lane >> 2;
    const int q    = lane & 3;
    const int qt   = 32 - blockIdx.x;
    const int bh   = blockIdx.y;
    const int h    = bh & 7;
    const int b    = bh >> 3;
    const float scale = 0.03125f;

    const unsigned* bHp = QVH + (size_t)b * NTOK * 1536;
    const unsigned* bLp = QVL + (size_t)b * NTOK * 1536;

    // ---- stage Q: direct word copy (layout QH[row*68 + c2]) ----
#pragma unroll
    for (int i = 0; i < 8; i++) {
        int idx = i * 128 + t;          // uint4 units: 64 rows x 16
        int row = idx >> 4;
        int c4w = (idx & 15) * 4;       // word col 0..60
        int grow = qt * 64 + row;
        uint4 vh = make_uint4(0,0,0,0), vl = make_uint4(0,0,0,0);
        if (grow < NTOK) {
            size_t gw = (size_t)grow * 1536 + h * 64 + c4w;
            vh = *(const uint4*)(bHp + gw);
            vl = *(const uint4*)(bLp + gw);
        }
        *(uint4*)(QH + row * 68 + c4w) = vh;
        *(uint4*)(QL + row * 68 + c4w) = vl;
    }

    float o[16][4];
#pragma unroll
    for (int ni = 0; ni < 16; ni++)
#pragma unroll
        for (int e = 0; e < 4; e++) o[ni][e] = 0.f;
    float mrow[2] = {-1e30f, -1e30f};
    float lrow[2] = {0.f, 0.f};

    for (int jt = 0; jt <= qt; jt++) {
        __syncthreads();

        // ---- stage K: word copy with transpose-store (KH[c2*72 + key]) ----
#pragma unroll
        for (int i = 0; i < 8; i++) {
            int idx = i * 128 + t;      // uint4 units: 64 keys x 16
            int key = idx >> 4;
            int c4w = (idx & 15) * 4;
            int gkey = jt * 64 + key;
            uint4 vh = make_uint4(0,0,0,0), vl = make_uint4(0,0,0,0);
            if (gkey < NTOK) {
                size_t gw = (size_t)gkey * 1536 + 512 + h * 64 + c4w;
                vh = *(const uint4*)(bHp + gw);
                vl = *(const uint4*)(bLp + gw);
            }
            KH[(c4w + 0) * 72 + key] = vh.x;
            KH[(c4w + 1) * 72 + key] = vh.y;
            KH[(c4w + 2) * 72 + key] = vh.z;
            KH[(c4w + 3) * 72 + key] = vh.w;
            KL[(c4w + 0) * 72 + key] = vl.x;
            KL[(c4w + 1) * 72 + key] = vl.y;
            KL[(c4w + 2) * 72 + key] = vl.z;
            KL[(c4w + 3) * 72 + key] = vl.w;
        }

        // ---- stage V: 2x2-short transpose via byte_perm (VH[kp*136 + dh]) ----
#pragma unroll
        for (int i = 0; i < 8; i++) {
            int idx = i * 128 + t;      // 32 key-pairs x 32 word-pair groups
            int kp = idx >> 5;
            int cg = idx & 31;          // covers words 2cg, 2cg+1 (dh 4cg..4cg+3)
            int k0g = jt * 64 + 2 * kp;
            uint2 wh = make_uint2(0,0), uh = make_uint2(0,0);
            uint2 wl = make_uint2(0,0), ul = make_uint2(0,0);
            if (k0g < NTOK) {
                size_t gw = (size_t)k0g * 1536 + 1024 + h * 64 + 2 * cg;
                wh = *(const uint2*)(bHp + gw);
                wl = *(const uint2*)(bLp + gw);
            }
            if (k0g + 1 < NTOK) {
                size_t gw = (size_t)(k0g + 1) * 1536 + 1024 + h * 64 + 2 * cg;
                uh = *(const uint2*)(bHp + gw);
                ul = *(const uint2*)(bLp + gw);
            }
            int wb = kp * 136 + 4 * cg;
            VH[wb + 0] = __byte_perm(wh.x, uh.x, 0x5410);
            VH[wb + 1] = __byte_perm(wh.x, uh.x, 0x7632);
            VH[wb + 2] = __byte_perm(wh.y, uh.y, 0x5410);
            VH[wb + 3] = __byte_perm(wh.y, uh.y, 0x7632);
            VL[wb + 0] = __byte_perm(wl.x, ul.x, 0x5410);
            VL[wb + 1] = __byte_perm(wl.x, ul.x, 0x7632);
            VL[wb + 2] = __byte_perm(wl.y, ul.y, 0x5410);
            VL[wb + 3] = __byte_perm(wl.y, ul.y, 0x7632);
        }
        __syncthreads();

        // ---- S = Q @ K^T (3-pass split) ----
        float s[8][4];
#pragma unroll
        for (int ni = 0; ni < 8; ni++)
#pragma unroll
            for (int e = 0; e < 4; e++) s[ni][e] = 0.f;

        const int r0 = w * 16 + g;
#pragma unroll
        for (int ko = 0; ko < 8; ko++) {
            unsigned qh[4], ql[4];
            int w0 = r0 * 68 + q + ko * 8;
            int w1 = (r0 + 8) * 68 + q + ko * 8;
            qh[0] = QH[w0];     qh[1] = QH[w1];
            qh[2] = QH[w0 + 4]; qh[3] = QH[w1 + 4];
            ql[0] = QL[w0];     ql[1] = QL[w1];
            ql[2] = QL[w0 + 4]; ql[3] = QL[w1 + 4];
#pragma unroll
            for (int ni = 0; ni < 8; ni++) {
                int nb = ni * 8 + g;
                unsigned bhf[2], blf[2];
                bhf[0] = KH[(q + ko * 8) * 72 + nb];
                bhf[1] = KH[(q + 4 + ko * 8) * 72 + nb];
                blf[0] = KL[(q + ko * 8) * 72 + nb];
                blf[1] = KL[(q + 4 + ko * 8) * 72 + nb];
                mma_bf16(s[ni], qh, bhf);
                mma_bf16(s[ni], qh, blf);
                mma_bf16(s[ni], ql, bhf);
            }
        }

        // ---- scale (exact power-of-2, commutes with split) ----
#pragma unroll
        for (int ni = 0; ni < 8; ni++)
#pragma unroll
            for (int e = 0; e < 4; e++) s[ni][e] *= scale;

        // ---- causal mask on diagonal tile ----
        if (jt == qt) {
            int rbase = qt * 64 + w * 16 + g;
#pragma unroll
            for (int ni = 0; ni < 8; ni++) {
                int cbase = jt * 64 + ni * 8 + 2 * q;
#pragma unroll
                for (int e = 0; e < 4; e++) {
                    int row = rbase + (e >= 2 ? 8 : 0);
                    int col = cbase + (e & 1);
                    if (col > row) s[ni][e] = -1e30f;
                }
            }
        }

        // ---- online softmax ----
        float mt[2] = {-1e30f, -1e30f};
#pragma unroll
        for (int ni = 0; ni < 8; ni++) {
            mt[0] = fmaxf(mt[0], fmaxf(s[ni][0], s[ni][1]));
            mt[1] = fmaxf(mt[1], fmaxf(s[ni][2], s[ni][3]));
        }
#pragma unroll
        for (int d = 1; d <= 2; d <<= 1) {
            mt[0] = fmaxf(mt[0], __shfl_xor_sync(0xFFFFFFFFu, mt[0], d));
            mt[1] = fmaxf(mt[1], __shfl_xor_sync(0xFFFFFFFFu, mt[1], d));
        }
        float mn[2] = {fmaxf(mrow[0], mt[0]), fmaxf(mrow[1], mt[1])};
        float corr[2] = {__expf(mrow[0] - mn[0]), __expf(mrow[1] - mn[1])};

        float rs[2] = {0.f, 0.f};
#pragma unroll
        for (int ni = 0; ni < 8; ni++) {
#pragma unroll
            for (int e = 0; e < 4; e++) {
                float pv = __expf(s[ni][e] - mn[e >> 1]);
                s[ni][e] = pv;
                rs[e >> 1] += pv;
            }
        }
#pragma unroll
        for (int d = 1; d <= 2; d <<= 1) {
            rs[0] += __shfl_xor_sync(0xFFFFFFFFu, rs[0], d);
            rs[1] += __shfl_xor_sync(0xFFFFFFFFu, rs[1], d);
        }
        lrow[0] = lrow[0] * corr[0] + rs[0];
        lrow[1] = lrow[1] * corr[1] + rs[1];
        mrow[0] = mn[0];
        mrow[1] = mn[1];
#pragma unroll
        for (int ni = 0; ni < 16; ni++) {
            o[ni][0] *= corr[0]; o[ni][1] *= corr[0];
            o[ni][2] *= corr[1]; o[ni][3] *= corr[1];
        }

        // ---- O += P @ V ----
#pragma unroll
        for (int kp = 0; kp < 4; kp++) {
            unsigned ph[4], pl[4];
            split_pair(s[2*kp][0],   s[2*kp][1],   ph[0], pl[0]);
            split_pair(s[2*kp][2],   s[2*kp][3],   ph[1], pl[1]);
            split_pair(s[2*kp+1][0], s[2*kp+1][1], ph[2], pl[2]);
            split_pair(s[2*kp+1][2], s[2*kp+1][3], ph[3], pl[3]);
#pragma unroll
            for (int ni = 0; ni < 16; ni++) {
                int nb = ni * 8 + g;
                unsigned bhf[2], blf[2];
                bhf[0] = VH[(q + kp * 8) * 136 + nb];
                bhf[1] = VH[(q + 4 + kp * 8) * 136 + nb];
                blf[0] = VL[(q + kp * 8) * 136 + nb];
                blf[1] = VL[(q + 4 + kp * 8) * 136 + nb];
                mma_bf16(o[ni], ph, bhf);
                mma_bf16(o[ni], ph, blf);
                mma_bf16(o[ni], pl, bhf);
            }
        }
    }

    float inv[2] = {1.f / lrow[0], 1.f / lrow[1]};
    int rbase = qt * 64 + w * 16 + g;
#pragma unroll
    for (int ni = 0; ni < 16; ni++) {
        int cb = h * DHEAD + ni * 8 + 2 * q;
#pragma unroll
        for (int half = 0; half < 2; half++) {
            int row = rbase + half * 8;
            if (row >= NTOK) continue;
            unsigned hw, lw;
            split_pair(o[ni][half*2] * inv[half], o[ni][half*2+1] * inv[half], hw, lw);
            size_t wi = (size_t)(b * NTOK + row) * (DIMM / 2) + (cb >> 1);
            OH[wi] = hw;
            OL[wi] = lw;
        }
    }
}

// ---------------- small kernels ----------------
__global__ void save_cls_kernel(const float* __restrict__ gx, float* __restrict__ gcls)
{
    int idx = blockIdx.x * blockDim.x + threadIdx.x;
    if (idx >= BATCH * DIMM) return;
    int b = idx / DIMM, d = idx % DIMM;
    gcls[idx] = gx[((size_t)b * NTOK) * DIMM + d];
}

__global__ void write_out_kernel(const float* __restrict__ gx,
                                 const float* __restrict__ gcls,
                                 float* __restrict__ out)
{
    const int totalx = MROWS * DIMM;
    const int totalc = BATCH * DIMM;
    int idx = blockIdx.x * blockDim.x + threadIdx.x;
    if (idx < totalx)               out[idx] = gx[idx];
    else if (idx < totalx + totalc) out[idx] = gcls[idx - totalx];
}

// ---------------- host orchestration ----------------
struct DevPtrs {
    float *gx, *gcls;
    unsigned *xsh, *xsl, *ash, *asl, *hsh, *hsl, *qsh, *qsl;
    unsigned *wqh, *wql, *woh, *wol, *w1h, *w1l, *w2h, *w2l;
};

static void run_layer(int l, const DevPtrs& P,
                      const float* bo, const float* b1, const float* b2)
{
    const int gy = (MROWS + 127) / 128;  // 33
    // qkv = x @ Wqkv  -> split planes only
    tgemm_kernel<false,false,false,false,true><<<dim3(24, gy), 256, SM_TOTAL>>>(
        P.xsh, P.xsl, P.wqh + (size_t)l*WQKV_L, P.wql + (size_t)l*WQKV_L,
        nullptr, nullptr, nullptr, P.qsh, P.qsl, MROWS, DIMM, 3*DIMM);
    // attention -> split att
    fattn_kernel<<<dim3(33, BATCH*NHEADS), 128, ATT_SMEM>>>(P.qsh, P.qsl, P.ash, P.asl);
    // x = x + att @ Wo + bo  (fp32 + split)
    tgemm_kernel<true,true,false,true,true><<<dim3(8, gy), 256, SM_TOTAL>>>(
        P.ash, P.asl, P.woh + (size_t)l*WO_L, P.wol + (size_t)l*WO_L,
        bo, P.gx, P.gx, P.xsh, P.xsl, MROWS, DIMM, DIMM);
    // h = gelu(x @ W1 + b1)  (split only)
    tgemm_kernel<true,false,true,false,true><<<dim3(32, gy), 256, SM_TOTAL>>>(
        P.xsh, P.xsl, P.w1h + (size_t)l*W1_L, P.w1l + (size_t)l*W1_L,
        b1, nullptr, nullptr, P.hsh, P.hsl, MROWS, DIMM, HID);
    // x = x + h @ W2 + b2  (fp32 + split)
    tgemm_kernel<true,true,false,true,true><<<dim3(8, gy), 256, SM_TOTAL>>>(
        P.hsh, P.hsl, P.w2h + (size_t)l*W2_L, P.w2l + (size_t)l*W2_L,
        b2, P.gx, P.gx, P.xsh, P.xsl, MROWS, HID, DIMM);
}

extern "C" void kernel_launch(void* const* d_in, const int* in_sizes, int n_in,
                              void* d_out, int out_size)
{
    const float* x_in = (const float*)d_in[0];
    const float* cls  = (const float*)d_in[1];
    const float* hW[7];
    const float* tW[7];
    for (int i = 0; i < 7; i++) hW[i] = (const float*)d_in[2 + i];
    for (int i = 0; i < 7; i++) tW[i] = (const float*)d_in[9 + i];

    cudaFuncSetAttribute(tgemm_kernel<false,false,false,false,true>,
                         cudaFuncAttributeMaxDynamicSharedMemorySize, SM_TOTAL);
    cudaFuncSetAttribute(tgemm_kernel<true,true,false,true,true>,
                         cudaFuncAttributeMaxDynamicSharedMemorySize, SM_TOTAL);
    cudaFuncSetAttribute(tgemm_kernel<true,false,true,false,true>,
                         cudaFuncAttributeMaxDynamicSharedMemorySize, SM_TOTAL);
    cudaFuncSetAttribute(fattn_kernel,
                         cudaFuncAttributeMaxDynamicSharedMemorySize, ATT_SMEM);

    DevPtrs P;
    cudaGetSymbolAddress((void**)&P.gx,   g_x);
    cudaGetSymbolAddress((void**)&P.gcls, g_cls);
    cudaGetSymbolAddress((void**)&P.xsh,  g_xs_h);
    cudaGetSymbolAddress((void**)&P.xsl,  g_xs_l);
    cudaGetSymbolAddress((void**)&P.ash,  g_as_h);
    cudaGetSymbolAddress((void**)&P.asl,  g_as_l);
    cudaGetSymbolAddress((void**)&P.hsh,  g_hs_h);
    cudaGetSymbolAddress((void**)&P.hsl,  g_hs_l);
    cudaGetSymbolAddress((void**)&P.qsh,  g_qs_h);
    cudaGetSymbolAddress((void**)&P.qsl,  g_qs_l);
    cudaGetSymbolAddress((void**)&P.wqh,  g_wqkv_h);
    cudaGetSymbolAddress((void**)&P.wql,  g_wqkv_l);
    cudaGetSymbolAddress((void**)&P.woh,  g_wo_h);
    cudaGetSymbolAddress((void**)&P.wol,  g_wo_l);
    cudaGetSymbolAddress((void**)&P.w1h,  g_w1_h);
    cudaGetSymbolAddress((void**)&P.w1l,  g_w1_l);
    cudaGetSymbolAddress((void**)&P.w2h,  g_w2_h);
    cudaGetSymbolAddress((void**)&P.w2l,  g_w2_l);

    split_w_kernel<<<dim3((WQKV_L + 255)/256, 8), 256>>>(hW[0], tW[0], P.wqh, P.wql, WQKV_L, 3*DIMM);
    split_w_kernel<<<dim3((WO_L   + 255)/256, 8), 256>>>(hW[1], tW[1], P.woh, P.wol, WO_L,   DIMM);
    split_w_kernel<<<dim3((W1_L   + 255)/256, 8), 256>>>(hW[3], tW[3], P.w1h, P.w1l, W1_L,   HID);
    split_w_kernel<<<dim3((W2_L   + 255)/256, 8), 256>>>(hW[5], tW[5], P.w2h, P.w2l, W2_L,   DIMM);

    {
        int total = MROWS * DIMM / 2;
        concat_kernel<<<(total + 255) / 256, 256>>>(x_in, cls, P.gx, P.xsh, P.xsl);
    }

    for (int l = 0; l < L_HEAD; l++)
        run_layer(l, P, hW[2] + (size_t)l*DIMM, hW[4] + (size_t)l*HID, hW[6] + (size_t)l*DIMM);

    save_cls_kernel<<<(BATCH*DIMM + 255)/256, 256>>>(P.gx, P.gcls);

    for (int l = 0; l < L_TAIL; l++)
        run_layer(4 + l, P, tW[2] + (size_t)l*DIMM, tW[4] + (size_t)l*HID, tW[6] + (size_t)l*DIMM);

    {
        int total = MROWS * DIMM + BATCH * DIMM;
        write_out_kernel<<<(total + 255)/256, 256>>>(P.gx, P.gcls, (float*)d_out);
    }
}

// round 13
// speedup vs baseline: 4.4454x; 1.0581x over previous
#include <cuda_runtime.h>
#include <cuda_bf16.h>
#include <math.h>
#include <stdint.h>

// ---------------- problem constants ----------------
#define DIMM   1024
#define NHEADS 8
#define DHEAD  128
#define NTOK   2049
#define BATCH  2
#define MROWS  (BATCH*NTOK)  // 4098
#define HID    4096
#define L_HEAD 4
#define L_TAIL 4

// ---------------- scratch (device globals) ----------------
__device__ __align__(16) float g_x  [(size_t)MROWS*DIMM];
__device__ __align__(16) float g_cls[(size_t)BATCH*DIMM];

__device__ __align__(16) unsigned g_xs_h[(size_t)MROWS*DIMM/2];
__device__ __align__(16) unsigned g_xs_l[(size_t)MROWS*DIMM/2];
__device__ __align__(16) unsigned g_as_h[(size_t)MROWS*DIMM/2];
__device__ __align__(16) unsigned g_as_l[(size_t)MROWS*DIMM/2];
__device__ __align__(16) unsigned g_hs_h[(size_t)MROWS*HID/2];
__device__ __align__(16) unsigned g_hs_l[(size_t)MROWS*HID/2];
__device__ __align__(16) unsigned g_qs_h[(size_t)MROWS*3*DIMM/2];
__device__ __align__(16) unsigned g_qs_l[(size_t)MROWS*3*DIMM/2];

#define WQKV_L (512*3072)
#define WO_L   (512*1024)
#define W1_L   (512*4096)
#define W2_L   (2048*1024)
__device__ __align__(16) unsigned g_wqkv_h[8*(size_t)WQKV_L];
__device__ __align__(16) unsigned g_wqkv_l[8*(size_t)WQKV_L];
__device__ __align__(16) unsigned g_wo_h[8*(size_t)WO_L];
__device__ __align__(16) unsigned g_wo_l[8*(size_t)WO_L];
__device__ __align__(16) unsigned g_w1_h[8*(size_t)W1_L];
__device__ __align__(16) unsigned g_w1_l[8*(size_t)W1_L];
__device__ __align__(16) unsigned g_w2_h[8*(size_t)W2_L];
__device__ __align__(16) unsigned g_w2_l[8*(size_t)W2_L];

// ---------------- bf16 helpers ----------------
__device__ __forceinline__ unsigned short f2bf(float x) {
    __nv_bfloat16 h = __float2bfloat16(x);
    return *reinterpret_cast<unsigned short*>(&h);
}
__device__ __forceinline__ float bf2f(unsigned short s) {
    __nv_bfloat16 h = *reinterpret_cast<__nv_bfloat16*>(&s);
    return __bfloat162float(h);
}
__device__ __forceinline__ void split_bf16(float x, unsigned short& hi, unsigned short& lo) {
    hi = f2bf(x);
    lo = f2bf(x - bf2f(hi));
}
__device__ __forceinline__ void split_pair(float a, float b, unsigned& hw, unsigned& lw) {
    unsigned short ah, al, bh, bl;
    split_bf16(a, ah, al);
    split_bf16(b, bh, bl);
    hw = (unsigned)ah | ((unsigned)bh << 16);
    lw = (unsigned)al | ((unsigned)bl << 16);
}

__device__ __forceinline__ void mma_bf16(float* c, const unsigned* a, const unsigned* b) {
    asm("mma.sync.aligned.m16n8k16.row.col.f32.bf16.bf16.f32 "
        "{%0,%1,%2,%3}, {%4,%5,%6,%7}, {%8,%9}, {%0,%1,%2,%3};"
        : "+f"(c[0]), "+f"(c[1]), "+f"(c[2]), "+f"(c[3])
        : "r"(a[0]), "r"(a[1]), "r"(a[2]), "r"(a[3]),
          "r"(b[0]), "r"(b[1]));
}

__device__ __forceinline__ void ldsm4(unsigned* r, const void* p) {
    unsigned a = (unsigned)__cvta_generic_to_shared(p);
    asm volatile("ldmatrix.sync.aligned.m8n8.x4.shared.b16 {%0,%1,%2,%3}, [%4];"
        : "=r"(r[0]), "=r"(r[1]), "=r"(r[2]), "=r"(r[3]) : "r"(a));
}

__device__ __forceinline__ void cpa16(void* dst, const void* src, int sz) {
    unsigned d = (unsigned)__cvta_generic_to_shared(dst);
    asm volatile("cp.async.cg.shared.global [%0], [%1], 16, %2;" :: "r"(d), "l"(src), "r"(sz));
}
__device__ __forceinline__ void cp_commit() { asm volatile("cp.async.commit_group;"); }
template<int N> __device__ __forceinline__ void cp_wait() {
    asm volatile("cp.async.wait_group %0;" :: "n"(N));
}

// ---------------- weight pre-split kernel ----------------
__global__ void split_w_kernel(const float* __restrict__ Wh, const float* __restrict__ Wt,
                               unsigned* __restrict__ oH, unsigned* __restrict__ oL,
                               int npairs, int N)
{
    int l = blockIdx.y;
    const float* W = (l < 4) ? (Wh + (size_t)l * npairs * 2)
                             : (Wt + (size_t)(l - 4) * npairs * 2);
    int idx = blockIdx.x * blockDim.x + threadIdx.x;
    if (idx >= npairs) return;
    int k2 = idx / N, n = idx % N;
    float a = W[(size_t)(2 * k2) * N + n];
    float b = W[(size_t)(2 * k2 + 1) * N + n];
    unsigned hw, lw;
    split_pair(a, b, hw, lw);
    size_t o = (size_t)l * npairs + idx;
    oH[o] = hw;
    oL[o] = lw;
}

// ---------------- concat cls + x ----------------
__global__ void concat_kernel(const float* __restrict__ x, const float* __restrict__ cls,
                              float* __restrict__ gx,
                              unsigned* __restrict__ xh, unsigned* __restrict__ xl)
{
    int idx = blockIdx.x * blockDim.x + threadIdx.x;
    int total = MROWS * DIMM / 2;
    if (idx >= total) return;
    int c2  = idx % (DIMM / 2);
    int row = idx / (DIMM / 2);
    int n = row % NTOK, b = row / NTOK;
    float v0, v1;
    if (n == 0) { v0 = cls[c2 * 2]; v1 = cls[c2 * 2 + 1]; }
    else {
        const float* p = x + ((size_t)b * (NTOK - 1) + (n - 1)) * DIMM + c2 * 2;
        v0 = p[0]; v1 = p[1];
    }
    gx[idx * 2] = v0; gx[idx * 2 + 1] = v1;
    unsigned hw, lw;
    split_pair(v0, v1, hw, lw);
    xh[idx] = hw; xl[idx] = lw;
}

// ---------------- tensor-core GEMM: 3-stage, early-issue, 2 CTAs/SM ----------
#define AST_B 80
#define STG_A (128*AST_B)
#define BROW  136
#define STG_B (16*BROW*4)
#define STG_BYTES (2*STG_A + 2*STG_B)   // 37888
#define NSTAGE 3
#define SM_TOTAL (NSTAGE*STG_BYTES)     // 113664

template<bool BIAS, bool RESID, bool DOGELU, bool W32, bool WS>
__global__ __launch_bounds__(256, 2)
void tgemm_kernel(const unsigned* __restrict__ AH, const unsigned* __restrict__ AL,
                  const unsigned* __restrict__ BH, const unsigned* __restrict__ BL,
                  const float* __restrict__ bias, const float* __restrict__ R,
                  float* __restrict__ C,
                  unsigned* __restrict__ OH, unsigned* __restrict__ OL,
                  int M, int K, int N)
{
    extern __shared__ char smem[];

    const int t    = threadIdx.x;
    const int warp = t >> 5;
    const int lane = t & 31;
    const int g    = lane >> 2;
    const int q    = lane & 3;
    const int wm   = warp & 1;
    const int wn   = warp >> 1;
    const int bm   = blockIdx.y * 128;
    const int bn   = blockIdx.x * 128;
    const int steps = K >> 5;

    float acc[4][4][4];
#pragma unroll
    for (int i = 0; i < 4; i++)
#pragma unroll
        for (int j = 0; j < 4; j++)
#pragma unroll
            for (int e = 0; e < 4; e++) acc[i][j][e] = 0.f;

    const int ar0 = t >> 2,  ac0 = (t & 3);
    const int ar1 = (t + 256) >> 2, ac1 = (t & 3);
    const int br0 = t >> 5,  bc0 = (t & 31);
    const int br1 = (t + 256) >> 5, bc1 = (t & 31);

    const unsigned short* AHg = (const unsigned short*)AH;
    const unsigned short* ALg = (const unsigned short*)AL;

    auto issue = [&](int s) {
        char* buf = smem + (s % NSTAGE) * STG_BYTES;
        char* AHs = buf;
        char* ALs = buf + STG_A;
        char* BHs = buf + 2 * STG_A;
        char* BLs = buf + 2 * STG_A + STG_B;
        int k0 = s * 32;
        {
            int gr = bm + ar0;
            int sz = (gr < M) ? 16 : 0;
            size_t so = (size_t)(gr < M ? gr : 0) * K + k0 + ac0 * 8;
            cpa16(AHs + ar0 * AST_B + ac0 * 16, AHg + so, sz);
            cpa16(ALs + ar0 * AST_B + ac0 * 16, ALg + so, sz);
            gr = bm + ar1;
            sz = (gr < M) ? 16 : 0;
            so = (size_t)(gr < M ? gr : 0) * K + k0 + ac1 * 8;
            cpa16(AHs + ar1 * AST_B + ac1 * 16, AHg + so, sz);
            cpa16(ALs + ar1 * AST_B + ac1 * 16, ALg + so, sz);
        }
        {
            size_t gw = ((size_t)(k0 / 2 + br0)) * N + bn;
            cpa16(BHs + br0 * (BROW * 4) + bc0 * 16, (const char*)BH + gw * 4 + bc0 * 16, 16);
            cpa16(BLs + br0 * (BROW * 4) + bc0 * 16, (const char*)BL + gw * 4 + bc0 * 16, 16);
            gw = ((size_t)(k0 / 2 + br1)) * N + bn;
            cpa16(BHs + br1 * (BROW * 4) + bc1 * 16, (const char*)BH + gw * 4 + bc1 * 16, 16);
            cpa16(BLs + br1 * (BROW * 4) + bc1 * 16, (const char*)BL + gw * 4 + bc1 * 16, 16);
        }
        cp_commit();
    };

    issue(0);
    if (steps > 1) issue(1);

    const int lanebase = (wm * 64 + (lane & 7) + ((lane >> 3) & 1) * 8) * AST_B + (lane >> 4) * 16;

    for (int s = 0; s < steps; s++) {
        if (s + 1 < steps) cp_wait<1>();
        else               cp_wait<0>();
        __syncthreads();

        // early issue: buffer (s+2)%3 was last read by compute(s-1), done at barrier
        if (s + 2 < steps) issue(s + 2);

        const char* buf = smem + (s % NSTAGE) * STG_BYTES;
        const char* AHs = buf;
        const char* ALs = buf + STG_A;
        const unsigned* BHw = (const unsigned*)(buf + 2 * STG_A);
        const unsigned* BLw = (const unsigned*)(buf + 2 * STG_A + STG_B);

#pragma unroll
        for (int ko = 0; ko < 2; ko++) {
            unsigned bh[4][2], bl[4][2];
#pragma unroll
            for (int ni = 0; ni < 4; ni++) {
                int nb = wn * 32 + g + ni * 8;
                bh[ni][0] = BHw[(q + ko * 8) * BROW + nb];
                bh[ni][1] = BHw[(q + 4 + ko * 8) * BROW + nb];
                bl[ni][0] = BLw[(q + ko * 8) * BROW + nb];
                bl[ni][1] = BLw[(q + 4 + ko * 8) * BROW + nb];
            }
#pragma unroll
            for (int mi = 0; mi < 4; mi++) {
                unsigned ah[4], al[4];
                ldsm4(ah, AHs + lanebase + mi * (16 * AST_B) + ko * 32);
                ldsm4(al, ALs + lanebase + mi * (16 * AST_B) + ko * 32);
#pragma unroll
                for (int ni = 0; ni < 4; ni++) {
                    mma_bf16(acc[mi][ni], ah, bh[ni]);
                    mma_bf16(acc[mi][ni], ah, bl[ni]);
                    mma_bf16(acc[mi][ni], al, bh[ni]);
                }
            }
        }
    }

    // ---- epilogue ----
    const int Nw = N >> 1;
#pragma unroll
    for (int mi = 0; mi < 4; mi++) {
        int r0 = bm + wm * 64 + mi * 16 + g;
#pragma unroll
        for (int ni = 0; ni < 4; ni++) {
            int cb = bn + wn * 32 + ni * 8 + 2 * q;
            float v[4];
#pragma unroll
            for (int e = 0; e < 4; e++) {
                v[e] = acc[mi][ni][e];
                if (BIAS) v[e] += bias[cb + (e & 1)];
                if (DOGELU) v[e] = 0.5f * v[e] * (1.f + erff(v[e] * 0.70710678118f));
            }
#pragma unroll
            for (int half = 0; half < 2; half++) {
                int gr = r0 + half * 8;
                if (gr >= M) continue;
                float a = v[half * 2], b = v[half * 2 + 1];
                if (RESID) {
                    a += R[(size_t)gr * N + cb];
                    b += R[(size_t)gr * N + cb + 1];
                }
                if (W32) {
                    C[(size_t)gr * N + cb]     = a;
                    C[(size_t)gr * N + cb + 1] = b;
                }
                if (WS) {
                    unsigned hw, lw;
                    split_pair(a, b, hw, lw);
                    size_t wi = (size_t)gr * Nw + (cb >> 1);
                    OH[wi] = hw;
                    OL[wi] = lw;
                }
            }
        }
    }
}

// ---------------- flash attention: double-buffered K (cp.async) + V (reg prefetch) -------
// smem words: QH 4352 | QL 4352 | KH 2x4352 | KL 2x4352 | VH 2x4352 | VL 2x4352
// K layout: [key][68 words] (c2 = dh-pair), direct copy of global words; frag read
//   addr = key*68 + c2 -> banks 4g+q+8ko distinct: conflict-free.
#define ATT_PW 4352
#define ATT_SMEM (10*ATT_PW*4)   // 174080 bytes

__global__ __launch_bounds__(128, 1)
void fattn_kernel(const unsigned* __restrict__ QVH, const unsigned* __restrict__ QVL,
                  unsigned* __restrict__ OH, unsigned* __restrict__ OL)
{
    extern __shared__ unsigned smw[];
    unsigned* QH = smw;
    unsigned* QL = QH + ATT_PW;
    unsigned* KH = QL + ATT_PW;        // 2 buffers
    unsigned* KL = KH + 2*ATT_PW;
    unsigned* VH = KL + 2*ATT_PW;      // 2 buffers
    unsigned* VL = VH + 2*ATT_PW;

    const int t    = threadIdx.x;
    const int lane = t & 31;
    const int w    = t >> 5;
    const int g    = lane >> 2;
    const int q    = lane & 3;
    const int qt   = 32 - blockIdx.x;
    const int bh   = blockIdx.y;
    const int h    = bh & 7;
    const int b    = bh >> 3;
    const float scale = 0.03125f;

    const unsigned* bHp = QVH + (size_t)b * NTOK * 1536;
    const unsigned* bLp = QVL + (size_t)b * NTOK * 1536;

    unsigned vpre[8][8];

    auto stageK = [&](int jt, int p) {
        unsigned* KHp = KH + p * ATT_PW;
        unsigned* KLp = KL + p * ATT_PW;
#pragma unroll
        for (int i = 0; i < 8; i++) {
            int idx = i * 128 + t;
            int key = idx >> 4;
            int c4w = (idx & 15) * 4;
            int gkey = jt * 64 + key;
            int sz = (gkey < NTOK) ? 16 : 0;
            size_t gw = (size_t)(gkey < NTOK ? gkey : 0) * 1536 + 512 + h * 64 + c4w;
            cpa16(KHp + key * 68 + c4w, bHp + gw, sz);
            cpa16(KLp + key * 68 + c4w, bLp + gw, sz);
        }
        cp_commit();
    };

    auto loadV = [&](int jt) {
#pragma unroll
        for (int i = 0; i < 8; i++) {
            int idx = i * 128 + t;
            int kp = idx >> 5;
            int cg = idx & 31;
            int k0g = jt * 64 + 2 * kp;
            uint2 wh = make_uint2(0,0), uh = make_uint2(0,0);
            uint2 wl = make_uint2(0,0), ul = make_uint2(0,0);
            if (k0g < NTOK) {
                size_t gw = (size_t)k0g * 1536 + 1024 + h * 64 + 2 * cg;
                wh = *(const uint2*)(bHp + gw);
                wl = *(const uint2*)(bLp + gw);
            }
            if (k0g + 1 < NTOK) {
                size_t gw = (size_t)(k0g + 1) * 1536 + 1024 + h * 64 + 2 * cg;
                uh = *(const uint2*)(bHp + gw);
                ul = *(const uint2*)(bLp + gw);
            }
            vpre[i][0] = wh.x; vpre[i][1] = wh.y; vpre[i][2] = uh.x; vpre[i][3] = uh.y;
            vpre[i][4] = wl.x; vpre[i][5] = wl.y; vpre[i][6] = ul.x; vpre[i][7] = ul.y;
        }
    };

    auto stsV = [&](int p) {
        unsigned* VHp = VH + p * ATT_PW;
        unsigned* VLp = VL + p * ATT_PW;
#pragma unroll
        for (int i = 0; i < 8; i++) {
            int idx = i * 128 + t;
            int kp = idx >> 5;
            int cg = idx & 31;
            int wb = kp * 136 + 4 * cg;
            VHp[wb + 0] = __byte_perm(vpre[i][0], vpre[i][2], 0x5410);
            VHp[wb + 1] = __byte_perm(vpre[i][0], vpre[i][2], 0x7632);
            VHp[wb + 2] = __byte_perm(vpre[i][1], vpre[i][3], 0x5410);
            VHp[wb + 3] = __byte_perm(vpre[i][1], vpre[i][3], 0x7632);
            VLp[wb + 0] = __byte_perm(vpre[i][4], vpre[i][6], 0x5410);
            VLp[wb + 1] = __byte_perm(vpre[i][4], vpre[i][6], 0x7632);
            VLp[wb + 2] = __byte_perm(vpre[i][5], vpre[i][7], 0x5410);
            VLp[wb + 3] = __byte_perm(vpre[i][5], vpre[i][7], 0x7632);
        }
    };

    // ---- prologue: stage tile 0 + Q ----
    stageK(0, 0);
    loadV(0);
    // stage Q (direct word copy, layout QH[row*68 + c2])
#pragma unroll
    for (int i = 0; i < 8; i++) {
        int idx = i * 128 + t;
        int row = idx >> 4;
        int c4w = (idx & 15) * 4;
        int grow = qt * 64 + row;
        uint4 vh = make_uint4(0,0,0,0), vl = make_uint4(0,0,0,0);
        if (grow < NTOK) {
            size_t gw = (size_t)grow * 1536 + h * 64 + c4w;
            vh = *(const uint4*)(bHp + gw);
            vl = *(const uint4*)(bLp + gw);
        }
        *(uint4*)(QH + row * 68 + c4w) = vh;
        *(uint4*)(QL + row * 68 + c4w) = vl;
    }
    stsV(0);
    cp_wait<0>();
    __syncthreads();

    float o[16][4];
#pragma unroll
    for (int ni = 0; ni < 16; ni++)
#pragma unroll
        for (int e = 0; e < 4; e++) o[ni][e] = 0.f;
    float mrow[2] = {-1e30f, -1e30f};
    float lrow[2] = {0.f, 0.f};

    for (int jt = 0; jt <= qt; jt++) {
        const int p = jt & 1;
        const bool more = jt < qt;
        if (more) {
            stageK(jt + 1, p ^ 1);
            loadV(jt + 1);
        }

        const unsigned* KHp = KH + p * ATT_PW;
        const unsigned* KLp = KL + p * ATT_PW;
        const unsigned* VHp = VH + p * ATT_PW;
        const unsigned* VLp = VL + p * ATT_PW;

        // ---- S = Q @ K^T (3-pass split) ----
        float s[8][4];
#pragma unroll
        for (int ni = 0; ni < 8; ni++)
#pragma unroll
            for (int e = 0; e < 4; e++) s[ni][e] = 0.f;

        const int r0 = w * 16 + g;
#pragma unroll
        for (int ko = 0; ko < 8; ko++) {
            unsigned qh[4], ql[4];
            int w0 = r0 * 68 + q + ko * 8;
            int w1 = (r0 + 8) * 68 + q + ko * 8;
            qh[0] = QH[w0];     qh[1] = QH[w1];
            qh[2] = QH[w0 + 4]; qh[3] = QH[w1 + 4];
            ql[0] = QL[w0];     ql[1] = QL[w1];
            ql[2] = QL[w0 + 4]; ql[3] = QL[w1 + 4];
#pragma unroll
            for (int ni = 0; ni < 8; ni++) {
                int nb = ni * 8 + g;
                unsigned bhf[2], blf[2];
                bhf[0] = KHp[nb * 68 + q + ko * 8];
                bhf[1] = KHp[nb * 68 + q + 4 + ko * 8];
                blf[0] = KLp[nb * 68 + q + ko * 8];
                blf[1] = KLp[nb * 68 + q + 4 + ko * 8];
                mma_bf16(s[ni], qh, bhf);
                mma_bf16(s[ni], qh, blf);
                mma_bf16(s[ni], ql, bhf);
            }
        }

        // ---- scale (exact power-of-2) ----
#pragma unroll
        for (int ni = 0; ni < 8; ni++)
#pragma unroll
            for (int e = 0; e < 4; e++) s[ni][e] *= scale;

        // ---- causal mask on diagonal tile (also kills OOB zero-K keys) ----
        if (jt == qt) {
            int rbase = qt * 64 + w * 16 + g;
#pragma unroll
            for (int ni = 0; ni < 8; ni++) {
                int cbase = jt * 64 + ni * 8 + 2 * q;
#pragma unroll
                for (int e = 0; e < 4; e++) {
                    int row = rbase + (e >= 2 ? 8 : 0);
                    int col = cbase + (e & 1);
                    if (col > row) s[ni][e] = -1e30f;
                }
            }
        }

        // ---- online softmax ----
        float mt[2] = {-1e30f, -1e30f};
#pragma unroll
        for (int ni = 0; ni < 8; ni++) {
            mt[0] = fmaxf(mt[0], fmaxf(s[ni][0], s[ni][1]));
            mt[1] = fmaxf(mt[1], fmaxf(s[ni][2], s[ni][3]));
        }
#pragma unroll
        for (int d = 1; d <= 2; d <<= 1) {
            mt[0] = fmaxf(mt[0], __shfl_xor_sync(0xFFFFFFFFu, mt[0], d));
            mt[1] = fmaxf(mt[1], __shfl_xor_sync(0xFFFFFFFFu, mt[1], d));
        }
        float mn[2] = {fmaxf(mrow[0], mt[0]), fmaxf(mrow[1], mt[1])};
        float corr[2] = {__expf(mrow[0] - mn[0]), __expf(mrow[1] - mn[1])};

        float rs[2] = {0.f, 0.f};
#pragma unroll
        for (int ni = 0; ni < 8; ni++) {
#pragma unroll
            for (int e = 0; e < 4; e++) {
                float pv = __expf(s[ni][e] - mn[e >> 1]);
                s[ni][e] = pv;
                rs[e >> 1] += pv;
            }
        }
#pragma unroll
        for (int d = 1; d <= 2; d <<= 1) {
            rs[0] += __shfl_xor_sync(0xFFFFFFFFu, rs[0], d);
            rs[1] += __shfl_xor_sync(0xFFFFFFFFu, rs[1], d);
        }
        lrow[0] = lrow[0] * corr[0] + rs[0];
        lrow[1] = lrow[1] * corr[1] + rs[1];
        mrow[0] = mn[0];
        mrow[1] = mn[1];
#pragma unroll
        for (int ni = 0; ni < 16; ni++) {
            o[ni][0] *= corr[0]; o[ni][1] *= corr[0];
            o[ni][2] *= corr[1]; o[ni][3] *= corr[1];
        }

        // ---- O += P @ V ----
#pragma unroll
        for (int kp = 0; kp < 4; kp++) {
            unsigned ph[4], pl[4];
            split_pair(s[2*kp][0],   s[2*kp][1],   ph[0], pl[0]);
            split_pair(s[2*kp][2],   s[2*kp][3],   ph[1], pl[1]);
            split_pair(s[2*kp+1][0], s[2*kp+1][1], ph[2], pl[2]);
            split_pair(s[2*kp+1][2], s[2*kp+1][3], ph[3], pl[3]);
#pragma unroll
            for (int ni = 0; ni < 16; ni++) {
                int nb = ni * 8 + g;
                unsigned bhf[2], blf[2];
                bhf[0] = VHp[(q + kp * 8) * 136 + nb];
                bhf[1] = VHp[(q + 4 + kp * 8) * 136 + nb];
                blf[0] = VLp[(q + kp * 8) * 136 + nb];
                blf[1] = VLp[(q + 4 + kp * 8) * 136 + nb];
                mma_bf16(o[ni], ph, bhf);
                mma_bf16(o[ni], ph, blf);
                mma_bf16(o[ni], pl, bhf);
            }
        }

        if (more) {
            stsV(p ^ 1);
            cp_wait<0>();
        }
        __syncthreads();
    }

    float inv[2] = {1.f / lrow[0], 1.f / lrow[1]};
    int rbase = qt * 64 + w * 16 + g;
#pragma unroll
    for (int ni = 0; ni < 16; ni++) {
        int cb = h * DHEAD + ni * 8 + 2 * q;
#pragma unroll
        for (int half = 0; half < 2; half++) {
            int row = rbase + half * 8;
            if (row >= NTOK) continue;
            unsigned hw, lw;
            split_pair(o[ni][half*2] * inv[half], o[ni][half*2+1] * inv[half], hw, lw);
            size_t wi = (size_t)(b * NTOK + row) * (DIMM / 2) + (cb >> 1);
            OH[wi] = hw;
            OL[wi] = lw;
        }
    }
}

// ---------------- small kernels ----------------
__global__ void save_cls_kernel(const float* __restrict__ gx, float* __restrict__ gcls)
{
    int idx = blockIdx.x * blockDim.x + threadIdx.x;
    if (idx >= BATCH * DIMM) return;
    int b = idx / DIMM, d = idx % DIMM;
    gcls[idx] = gx[((size_t)b * NTOK) * DIMM + d];
}

__global__ void write_out_kernel(const float* __restrict__ gx,
                                 const float* __restrict__ gcls,
                                 float* __restrict__ out)
{
    const int totalx = MROWS * DIMM;
    const int totalc = BATCH * DIMM;
    int idx = blockIdx.x * blockDim.x + threadIdx.x;
    if (idx < totalx)               out[idx] = gx[idx];
    else if (idx < totalx + totalc) out[idx] = gcls[idx - totalx];
}

// ---------------- host orchestration ----------------
struct DevPtrs {
    float *gx, *gcls;
    unsigned *xsh, *xsl, *ash, *asl, *hsh, *hsl, *qsh, *qsl;
    unsigned *wqh, *wql, *woh, *wol, *w1h, *w1l, *w2h, *w2l;
};

static void run_layer(int l, const DevPtrs& P,
                      const float* bo, const float* b1, const float* b2)
{
    const int gy = (MROWS + 127) / 128;  // 33
    tgemm_kernel<false,false,false,false,true><<<dim3(24, gy), 256, SM_TOTAL>>>(
        P.xsh, P.xsl, P.wqh + (size_t)l*WQKV_L, P.wql + (size_t)l*WQKV_L,
        nullptr, nullptr, nullptr, P.qsh, P.qsl, MROWS, DIMM, 3*DIMM);
    fattn_kernel<<<dim3(33, BATCH*NHEADS), 128, ATT_SMEM>>>(P.qsh, P.qsl, P.ash, P.asl);
    tgemm_kernel<true,true,false,true,true><<<dim3(8, gy), 256, SM_TOTAL>>>(
        P.ash, P.asl, P.woh + (size_t)l*WO_L, P.wol + (size_t)l*WO_L,
        bo, P.gx, P.gx, P.xsh, P.xsl, MROWS, DIMM, DIMM);
    tgemm_kernel<true,false,true,false,true><<<dim3(32, gy), 256, SM_TOTAL>>>(
        P.xsh, P.xsl, P.w1h + (size_t)l*W1_L, P.w1l + (size_t)l*W1_L,
        b1, nullptr, nullptr, P.hsh, P.hsl, MROWS, DIMM, HID);
    tgemm_kernel<true,true,false,true,true><<<dim3(8, gy), 256, SM_TOTAL>>>(
        P.hsh, P.hsl, P.w2h + (size_t)l*W2_L, P.w2l + (size_t)l*W2_L,
        b2, P.gx, P.gx, P.xsh, P.xsl, MROWS, HID, DIMM);
}

extern "C" void kernel_launch(void* const* d_in, const int* in_sizes, int n_in,
                              void* d_out, int out_size)
{
    const float* x_in = (const float*)d_in[0];
    const float* cls  = (const float*)d_in[1];
    const float* hW[7];
    const float* tW[7];
    for (int i = 0; i < 7; i++) hW[i] = (const float*)d_in[2 + i];
    for (int i = 0; i < 7; i++) tW[i] = (const float*)d_in[9 + i];

    cudaFuncSetAttribute(tgemm_kernel<false,false,false,false,true>,
                         cudaFuncAttributeMaxDynamicSharedMemorySize, SM_TOTAL);
    cudaFuncSetAttribute(tgemm_kernel<true,true,false,true,true>,
                         cudaFuncAttributeMaxDynamicSharedMemorySize, SM_TOTAL);
    cudaFuncSetAttribute(tgemm_kernel<true,false,true,false,true>,
                         cudaFuncAttributeMaxDynamicSharedMemorySize, SM_TOTAL);
    cudaFuncSetAttribute(fattn_kernel,
                         cudaFuncAttributeMaxDynamicSharedMemorySize, ATT_SMEM);

    DevPtrs P;
    cudaGetSymbolAddress((void**)&P.gx,   g_x);
    cudaGetSymbolAddress((void**)&P.gcls, g_cls);
    cudaGetSymbolAddress((void**)&P.xsh,  g_xs_h);
    cudaGetSymbolAddress((void**)&P.xsl,  g_xs_l);
    cudaGetSymbolAddress((void**)&P.ash,  g_as_h);
    cudaGetSymbolAddress((void**)&P.asl,  g_as_l);
    cudaGetSymbolAddress((void**)&P.hsh,  g_hs_h);
    cudaGetSymbolAddress((void**)&P.hsl,  g_hs_l);
    cudaGetSymbolAddress((void**)&P.qsh,  g_qs_h);
    cudaGetSymbolAddress((void**)&P.qsl,  g_qs_l);
    cudaGetSymbolAddress((void**)&P.wqh,  g_wqkv_h);
    cudaGetSymbolAddress((void**)&P.wql,  g_wqkv_l);
    cudaGetSymbolAddress((void**)&P.woh,  g_wo_h);
    cudaGetSymbolAddress((void**)&P.wol,  g_wo_l);
    cudaGetSymbolAddress((void**)&P.w1h,  g_w1_h);
    cudaGetSymbolAddress((void**)&P.w1l,  g_w1_l);
    cudaGetSymbolAddress((void**)&P.w2h,  g_w2_h);
    cudaGetSymbolAddress((void**)&P.w2l,  g_w2_l);

    split_w_kernel<<<dim3((WQKV_L + 255)/256, 8), 256>>>(hW[0], tW[0], P.wqh, P.wql, WQKV_L, 3*DIMM);
    split_w_kernel<<<dim3((WO_L   + 255)/256, 8), 256>>>(hW[1], tW[1], P.woh, P.wol, WO_L,   DIMM);
    split_w_kernel<<<dim3((W1_L   + 255)/256, 8), 256>>>(hW[3], tW[3], P.w1h, P.w1l, W1_L,   HID);
    split_w_kernel<<<dim3((W2_L   + 255)/256, 8), 256>>>(hW[5], tW[5], P.w2h, P.w2l, W2_L,   DIMM);

    {
        int total = MROWS * DIMM / 2;
        concat_kernel<<<(total + 255) / 256, 256>>>(x_in, cls, P.gx, P.xsh, P.xsl);
    }

    for (int l = 0; l < L_HEAD; l++)
        run_layer(l, P, hW[2] + (size_t)l*DIMM, hW[4] + (size_t)l*HID, hW[6] + (size_t)l*DIMM);

    save_cls_kernel<<<(BATCH*DIMM + 255)/256, 256>>>(P.gx, P.gcls);

    for (int l = 0; l < L_TAIL; l++)
        run_layer(4 + l, P, tW[2] + (size_t)l*DIMM, tW[4] + (size_t)l*HID, tW[6] + (size_t)l*DIMM);

    {
        int total = MROWS * DIMM + BATCH * DIMM;
        write_out_kernel<<<(total + 255)/256, 256>>>(P.gx, P.gcls, (float*)d_out);
    }
}

// round 14
// speedup vs baseline: 4.5420x; 1.0217x over previous
#include <cuda_runtime.h>
#include <cuda_bf16.h>
#include <math.h>
#include <stdint.h>

// ---------------- problem constants ----------------
#define DIMM   1024
#define NHEADS 8
#define DHEAD  128
#define NTOK   2049
#define BATCH  2
#define MROWS  (BATCH*NTOK)  // 4098
#define HID    4096
#define L_HEAD 4
#define L_TAIL 4

// ---------------- scratch (device globals) ----------------
__device__ __align__(16) float g_x  [(size_t)MROWS*DIMM];
__device__ __align__(16) float g_cls[(size_t)BATCH*DIMM];

__device__ __align__(16) unsigned g_xs_h[(size_t)MROWS*DIMM/2];
__device__ __align__(16) unsigned g_xs_l[(size_t)MROWS*DIMM/2];
__device__ __align__(16) unsigned g_as_h[(size_t)MROWS*DIMM/2];
__device__ __align__(16) unsigned g_as_l[(size_t)MROWS*DIMM/2];
__device__ __align__(16) unsigned g_hs_h[(size_t)MROWS*HID/2];
__device__ __align__(16) unsigned g_hs_l[(size_t)MROWS*HID/2];
__device__ __align__(16) unsigned g_qs_h[(size_t)MROWS*3*DIMM/2];
__device__ __align__(16) unsigned g_qs_l[(size_t)MROWS*3*DIMM/2];

// weight splits, frag-pair layout:
//   word offset (per layer) = (g8*N + n)*8 + q*2 + h,  k2 = 8*g8 + q + 4*h
//   (so LDS.64 at q*2 yields the mma B frag pair k2 = {8ko+q, 8ko+q+4})
#define WQKV_L (512*3072)
#define WO_L   (512*1024)
#define W1_L   (512*4096)
#define W2_L   (2048*1024)
__device__ __align__(16) unsigned g_wqkv_h[8*(size_t)WQKV_L];
__device__ __align__(16) unsigned g_wqkv_l[8*(size_t)WQKV_L];
__device__ __align__(16) unsigned g_wo_h[8*(size_t)WO_L];
__device__ __align__(16) unsigned g_wo_l[8*(size_t)WO_L];
__device__ __align__(16) unsigned g_w1_h[8*(size_t)W1_L];
__device__ __align__(16) unsigned g_w1_l[8*(size_t)W1_L];
__device__ __align__(16) unsigned g_w2_h[8*(size_t)W2_L];
__device__ __align__(16) unsigned g_w2_l[8*(size_t)W2_L];

// ---------------- bf16 helpers ----------------
__device__ __forceinline__ unsigned short f2bf(float x) {
    __nv_bfloat16 h = __float2bfloat16(x);
    return *reinterpret_cast<unsigned short*>(&h);
}
__device__ __forceinline__ float bf2f(unsigned short s) {
    __nv_bfloat16 h = *reinterpret_cast<__nv_bfloat16*>(&s);
    return __bfloat162float(h);
}
__device__ __forceinline__ void split_bf16(float x, unsigned short& hi, unsigned short& lo) {
    hi = f2bf(x);
    lo = f2bf(x - bf2f(hi));
}
__device__ __forceinline__ void split_pair(float a, float b, unsigned& hw, unsigned& lw) {
    unsigned short ah, al, bh, bl;
    split_bf16(a, ah, al);
    split_bf16(b, bh, bl);
    hw = (unsigned)ah | ((unsigned)bh << 16);
    lw = (unsigned)al | ((unsigned)bl << 16);
}

__device__ __forceinline__ void mma_bf16(float* c, const unsigned* a, const unsigned* b) {
    asm("mma.sync.aligned.m16n8k16.row.col.f32.bf16.bf16.f32 "
        "{%0,%1,%2,%3}, {%4,%5,%6,%7}, {%8,%9}, {%0,%1,%2,%3};"
        : "+f"(c[0]), "+f"(c[1]), "+f"(c[2]), "+f"(c[3])
        : "r"(a[0]), "r"(a[1]), "r"(a[2]), "r"(a[3]),
          "r"(b[0]), "r"(b[1]));
}

__device__ __forceinline__ void ldsm4(unsigned* r, const void* p) {
    unsigned a = (unsigned)__cvta_generic_to_shared(p);
    asm volatile("ldmatrix.sync.aligned.m8n8.x4.shared.b16 {%0,%1,%2,%3}, [%4];"
        : "=r"(r[0]), "=r"(r[1]), "=r"(r[2]), "=r"(r[3]) : "r"(a));
}

__device__ __forceinline__ void cpa16(void* dst, const void* src, int sz) {
    unsigned d = (unsigned)__cvta_generic_to_shared(dst);
    asm volatile("cp.async.cg.shared.global [%0], [%1], 16, %2;" :: "r"(d), "l"(src), "r"(sz));
}
__device__ __forceinline__ void cp_commit() { asm volatile("cp.async.commit_group;"); }
template<int N> __device__ __forceinline__ void cp_wait() {
    asm volatile("cp.async.wait_group %0;" :: "n"(N));
}

// ---------------- weight pre-split kernel (frag-pair layout, tiled/coalesced) ----------
// grid: (N/256, K/16, 8 layers), block 256
__global__ void split_w2_kernel(const float* __restrict__ Wh, const float* __restrict__ Wt,
                                unsigned* __restrict__ oH, unsigned* __restrict__ oL,
                                int K, int N)
{
    __shared__ unsigned smh[8][257], sml[8][257];
    int l = blockIdx.z;
    const float* W = (l < 4) ? (Wh + (size_t)l * K * N) : (Wt + (size_t)(l - 4) * K * N);
    int g8 = blockIdx.y;
    int n0 = blockIdx.x * 256;
    int tx = threadIdx.x;
#pragma unroll
    for (int r = 0; r < 8; r++) {
        int k2 = g8 * 8 + r;
        float a = W[(size_t)(2 * k2) * N + n0 + tx];
        float b = W[(size_t)(2 * k2 + 1) * N + n0 + tx];
        unsigned hw, lw;
        split_pair(a, b, hw, lw);
        smh[r][tx] = hw;
        sml[r][tx] = lw;
    }
    __syncthreads();
    size_t base = (size_t)l * ((size_t)K * N / 2) + ((size_t)g8 * N + n0 + tx) * 8;
    unsigned vh[8], vl[8];
#pragma unroll
    for (int j = 0; j < 8; j++) {
        int r = (j >> 1) + 4 * (j & 1);    // word j = q*2+h  ->  k2r = q + 4h
        vh[j] = smh[r][tx];
        vl[j] = sml[r][tx];
    }
    *(uint4*)(oH + base)     = make_uint4(vh[0], vh[1], vh[2], vh[3]);
    *(uint4*)(oH + base + 4) = make_uint4(vh[4], vh[5], vh[6], vh[7]);
    *(uint4*)(oL + base)     = make_uint4(vl[0], vl[1], vl[2], vl[3]);
    *(uint4*)(oL + base + 4) = make_uint4(vl[4], vl[5], vl[6], vl[7]);
}

// ---------------- concat cls + x ----------------
__global__ void concat_kernel(const float* __restrict__ x, const float* __restrict__ cls,
                              float* __restrict__ gx,
                              unsigned* __restrict__ xh, unsigned* __restrict__ xl)
{
    int idx = blockIdx.x * blockDim.x + threadIdx.x;
    int total = MROWS * DIMM / 2;
    if (idx >= total) return;
    int c2  = idx % (DIMM / 2);
    int row = idx / (DIMM / 2);
    int n = row % NTOK, b = row / NTOK;
    float v0, v1;
    if (n == 0) { v0 = cls[c2 * 2]; v1 = cls[c2 * 2 + 1]; }
    else {
        const float* p = x + ((size_t)b * (NTOK - 1) + (n - 1)) * DIMM + c2 * 2;
        v0 = p[0]; v1 = p[1];
    }
    gx[idx * 2] = v0; gx[idx * 2 + 1] = v1;
    unsigned hw, lw;
    split_pair(v0, v1, hw, lw);
    xh[idx] = hw; xl[idx] = lw;
}

// ---------------- tensor-core GEMM: 3-stage, early-issue, LDS.64 B frags, 2 CTAs/SM -----
#define AST_B 80
#define STG_A (128*AST_B)               // 10240 per A plane
#define BGRP  1032                      // words per k-group (1024 data + 8 pad)
#define STG_B4 (2*BGRP*4)               // 8256 bytes per B plane
#define STG_BYTES (2*STG_A + 2*STG_B4)  // 36992
#define NSTAGE 3
#define SM_TOTAL (NSTAGE*STG_BYTES)     // 110976

template<bool BIAS, bool RESID, bool DOGELU, bool W32, bool WS>
__global__ __launch_bounds__(256, 2)
void tgemm_kernel(const unsigned* __restrict__ AH, const unsigned* __restrict__ AL,
                  const unsigned* __restrict__ BH, const unsigned* __restrict__ BL,
                  const float* __restrict__ bias, const float* __restrict__ R,
                  float* __restrict__ C,
                  unsigned* __restrict__ OH, unsigned* __restrict__ OL,
                  int M, int K, int N)
{
    extern __shared__ char smem[];

    const int t    = threadIdx.x;
    const int warp = t >> 5;
    const int lane = t & 31;
    const int g    = lane >> 2;
    const int q    = lane & 3;
    const int wm   = warp & 1;
    const int wn   = warp >> 1;
    const int bm   = blockIdx.y * 128;
    const int bn   = blockIdx.x * 128;
    const int steps = K >> 5;

    float acc[4][4][4];
#pragma unroll
    for (int i = 0; i < 4; i++)
#pragma unroll
        for (int j = 0; j < 4; j++)
#pragma unroll
            for (int e = 0; e < 4; e++) acc[i][j][e] = 0.f;

    const int ar0 = t >> 2,  ac0 = (t & 3);
    const int ar1 = (t + 256) >> 2, ac1 = (t & 3);

    const unsigned short* AHg = (const unsigned short*)AH;
    const unsigned short* ALg = (const unsigned short*)AL;

    auto issue = [&](int s) {
        char* buf = smem + (s % NSTAGE) * STG_BYTES;
        char* AHs = buf;
        char* ALs = buf + STG_A;
        char* BHs = buf + 2 * STG_A;
        char* BLs = buf + 2 * STG_A + STG_B4;
        int k0 = s * 32;
        {
            int gr = bm + ar0;
            int sz = (gr < M) ? 16 : 0;
            size_t so = (size_t)(gr < M ? gr : 0) * K + k0 + ac0 * 8;
            cpa16(AHs + ar0 * AST_B + ac0 * 16, AHg + so, sz);
            cpa16(ALs + ar0 * AST_B + ac0 * 16, ALg + so, sz);
            gr = bm + ar1;
            sz = (gr < M) ? 16 : 0;
            so = (size_t)(gr < M ? gr : 0) * K + k0 + ac1 * 8;
            cpa16(AHs + ar1 * AST_B + ac1 * 16, AHg + so, sz);
            cpa16(ALs + ar1 * AST_B + ac1 * 16, ALg + so, sz);
        }
        {
            // B frag-pair layout: stage covers k-groups sgrp, sgrp+1; each 1024 contiguous words
            int sgrp = s * 2;
            size_t src0 = ((size_t)sgrp * N + bn) * 8 + t * 4;
            size_t src1 = ((size_t)(sgrp + 1) * N + bn) * 8 + t * 4;
            int d0 = t * 4;
            int d1 = BGRP + t * 4;
            cpa16(BHs + d0 * 4, BH + src0, 16);
            cpa16(BLs + d0 * 4, BL + src0, 16);
            cpa16(BHs + d1 * 4, BH + src1, 16);
            cpa16(BLs + d1 * 4, BL + src1, 16);
        }
        cp_commit();
    };

    issue(0);
    if (steps > 1) issue(1);

    const int lanebase = (wm * 64 + (lane & 7) + ((lane >> 3) & 1) * 8) * AST_B + (lane >> 4) * 16;

    for (int s = 0; s < steps; s++) {
        if (s + 1 < steps) cp_wait<1>();
        else               cp_wait<0>();
        __syncthreads();

        if (s + 2 < steps) issue(s + 2);

        const char* buf = smem + (s % NSTAGE) * STG_BYTES;
        const char* AHs = buf;
        const char* ALs = buf + STG_A;
        const unsigned* BHw = (const unsigned*)(buf + 2 * STG_A);
        const unsigned* BLw = (const unsigned*)(buf + 2 * STG_A + STG_B4);

#pragma unroll
        for (int ko = 0; ko < 2; ko++) {
            unsigned bh[4][2], bl[4][2];
#pragma unroll
            for (int ni = 0; ni < 4; ni++) {
                int ad = ko * BGRP + (wn * 32 + g + ni * 8) * 8 + q * 2;
                uint2 vh2 = *(const uint2*)(BHw + ad);
                uint2 vl2 = *(const uint2*)(BLw + ad);
                bh[ni][0] = vh2.x; bh[ni][1] = vh2.y;
                bl[ni][0] = vl2.x; bl[ni][1] = vl2.y;
            }
#pragma unroll
            for (int mi = 0; mi < 4; mi++) {
                unsigned ah[4], al[4];
                ldsm4(ah, AHs + lanebase + mi * (16 * AST_B) + ko * 32);
                ldsm4(al, ALs + lanebase + mi * (16 * AST_B) + ko * 32);
#pragma unroll
                for (int ni = 0; ni < 4; ni++) {
                    mma_bf16(acc[mi][ni], ah, bh[ni]);
                    mma_bf16(acc[mi][ni], ah, bl[ni]);
                    mma_bf16(acc[mi][ni], al, bh[ni]);
                }
            }
        }
    }

    // ---- epilogue ----
    const int Nw = N >> 1;
#pragma unroll
    for (int mi = 0; mi < 4; mi++) {
        int r0 = bm + wm * 64 + mi * 16 + g;
#pragma unroll
        for (int ni = 0; ni < 4; ni++) {
            int cb = bn + wn * 32 + ni * 8 + 2 * q;
            float v[4];
#pragma unroll
            for (int e = 0; e < 4; e++) {
                v[e] = acc[mi][ni][e];
                if (BIAS) v[e] += bias[cb + (e & 1)];
                if (DOGELU) v[e] = 0.5f * v[e] * (1.f + erff(v[e] * 0.70710678118f));
            }
#pragma unroll
            for (int half = 0; half < 2; half++) {
                int gr = r0 + half * 8;
                if (gr >= M) continue;
                float a = v[half * 2], b = v[half * 2 + 1];
                if (RESID) {
                    a += R[(size_t)gr * N + cb];
                    b += R[(size_t)gr * N + cb + 1];
                }
                if (W32) {
                    C[(size_t)gr * N + cb]     = a;
                    C[(size_t)gr * N + cb + 1] = b;
                }
                if (WS) {
                    unsigned hw, lw;
                    split_pair(a, b, hw, lw);
                    size_t wi = (size_t)gr * Nw + (cb >> 1);
                    OH[wi] = hw;
                    OL[wi] = lw;
                }
            }
        }
    }
}

// ---------------- flash attention: double-buffered K (cp.async) + V (reg prefetch) -------
#define ATT_PW 4352
#define ATT_SMEM (10*ATT_PW*4)   // 174080 bytes

__global__ __launch_bounds__(128, 1)
void fattn_kernel(const unsigned* __restrict__ QVH, const unsigned* __restrict__ QVL,
                  unsigned* __restrict__ OH, unsigned* __restrict__ OL)
{
    extern __shared__ unsigned smw[];
    unsigned* QH = smw;
    unsigned* QL = QH + ATT_PW;
    unsigned* KH = QL + ATT_PW;
    unsigned* KL = KH + 2*ATT_PW;
    unsigned* VH = KL + 2*ATT_PW;
    unsigned* VL = VH + 2*ATT_PW;

    const int t    = threadIdx.x;
    const int lane = t & 31;
    const int w    = t >> 5;
    const int g    = lane >> 2;
    const int q    = lane & 3;
    const int qt   = 32 - blockIdx.x;
    const int bh   = blockIdx.y;
    const int h    = bh & 7;
    const int b    = bh >> 3;
    const float scale = 0.03125f;

    const unsigned* bHp = QVH + (size_t)b * NTOK * 1536;
    const unsigned* bLp = QVL + (size_t)b * NTOK * 1536;

    unsigned vpre[8][8];

    auto stageK = [&](int jt, int p) {
        unsigned* KHp = KH + p * ATT_PW;
        unsigned* KLp = KL + p * ATT_PW;
#pragma unroll
        for (int i = 0; i < 8; i++) {
            int idx = i * 128 + t;
            int key = idx >> 4;
            int c4w = (idx & 15) * 4;
            int gkey = jt * 64 + key;
            int sz = (gkey < NTOK) ? 16 : 0;
            size_t gw = (size_t)(gkey < NTOK ? gkey : 0) * 1536 + 512 + h * 64 + c4w;
            cpa16(KHp + key * 68 + c4w, bHp + gw, sz);
            cpa16(KLp + key * 68 + c4w, bLp + gw, sz);
        }
        cp_commit();
    };

    auto loadV = [&](int jt) {
#pragma unroll
        for (int i = 0; i < 8; i++) {
            int idx = i * 128 + t;
            int kp = idx >> 5;
            int cg = idx & 31;
            int k0g = jt * 64 + 2 * kp;
            uint2 wh = make_uint2(0,0), uh = make_uint2(0,0);
            uint2 wl = make_uint2(0,0), ul = make_uint2(0,0);
            if (k0g < NTOK) {
                size_t gw = (size_t)k0g * 1536 + 1024 + h * 64 + 2 * cg;
                wh = *(const uint2*)(bHp + gw);
                wl = *(const uint2*)(bLp + gw);
            }
            if (k0g + 1 < NTOK) {
                size_t gw = (size_t)(k0g + 1) * 1536 + 1024 + h * 64 + 2 * cg;
                uh = *(const uint2*)(bHp + gw);
                ul = *(const uint2*)(bLp + gw);
            }
            vpre[i][0] = wh.x; vpre[i][1] = wh.y; vpre[i][2] = uh.x; vpre[i][3] = uh.y;
            vpre[i][4] = wl.x; vpre[i][5] = wl.y; vpre[i][6] = ul.x; vpre[i][7] = ul.y;
        }
    };

    auto stsV = [&](int p) {
        unsigned* VHp = VH + p * ATT_PW;
        unsigned* VLp = VL + p * ATT_PW;
#pragma unroll
        for (int i = 0; i < 8; i++) {
            int idx = i * 128 + t;
            int kp = idx >> 5;
            int cg = idx & 31;
            int wb = kp * 136 + 4 * cg;
            VHp[wb + 0] = __byte_perm(vpre[i][0], vpre[i][2], 0x5410);
            VHp[wb + 1] = __byte_perm(vpre[i][0], vpre[i][2], 0x7632);
            VHp[wb + 2] = __byte_perm(vpre[i][1], vpre[i][3], 0x5410);
            VHp[wb + 3] = __byte_perm(vpre[i][1], vpre[i][3], 0x7632);
            VLp[wb + 0] = __byte_perm(vpre[i][4], vpre[i][6], 0x5410);
            VLp[wb + 1] = __byte_perm(vpre[i][4], vpre[i][6], 0x7632);
            VLp[wb + 2] = __byte_perm(vpre[i][5], vpre[i][7], 0x5410);
            VLp[wb + 3] = __byte_perm(vpre[i][5], vpre[i][7], 0x7632);
        }
    };

    stageK(0, 0);
    loadV(0);
#pragma unroll
    for (int i = 0; i < 8; i++) {
        int idx = i * 128 + t;
        int row = idx >> 4;
        int c4w = (idx & 15) * 4;
        int grow = qt * 64 + row;
        uint4 vh = make_uint4(0,0,0,0), vl = make_uint4(0,0,0,0);
        if (grow < NTOK) {
            size_t gw = (size_t)grow * 1536 + h * 64 + c4w;
            vh = *(const uint4*)(bHp + gw);
            vl = *(const uint4*)(bLp + gw);
        }
        *(uint4*)(QH + row * 68 + c4w) = vh;
        *(uint4*)(QL + row * 68 + c4w) = vl;
    }
    stsV(0);
    cp_wait<0>();
    __syncthreads();

    float o[16][4];
#pragma unroll
    for (int ni = 0; ni < 16; ni++)
#pragma unroll
        for (int e = 0; e < 4; e++) o[ni][e] = 0.f;
    float mrow[2] = {-1e30f, -1e30f};
    float lrow[2] = {0.f, 0.f};

    for (int jt = 0; jt <= qt; jt++) {
        const int p = jt & 1;
        const bool more = jt < qt;
        if (more) {
            stageK(jt + 1, p ^ 1);
            loadV(jt + 1);
        }

        const unsigned* KHp = KH + p * ATT_PW;
        const unsigned* KLp = KL + p * ATT_PW;
        const unsigned* VHp = VH + p * ATT_PW;
        const unsigned* VLp = VL + p * ATT_PW;

        float s[8][4];
#pragma unroll
        for (int ni = 0; ni < 8; ni++)
#pragma unroll
            for (int e = 0; e < 4; e++) s[ni][e] = 0.f;

        const int r0 = w * 16 + g;
#pragma unroll
        for (int ko = 0; ko < 8; ko++) {
            unsigned qh[4], ql[4];
            int w0 = r0 * 68 + q + ko * 8;
            int w1 = (r0 + 8) * 68 + q + ko * 8;
            qh[0] = QH[w0];     qh[1] = QH[w1];
            qh[2] = QH[w0 + 4]; qh[3] = QH[w1 + 4];
            ql[0] = QL[w0];     ql[1] = QL[w1];
            ql[2] = QL[w0 + 4]; ql[3] = QL[w1 + 4];
#pragma unroll
            for (int ni = 0; ni < 8; ni++) {
                int nb = ni * 8 + g;
                unsigned bhf[2], blf[2];
                bhf[0] = KHp[nb * 68 + q + ko * 8];
                bhf[1] = KHp[nb * 68 + q + 4 + ko * 8];
                blf[0] = KLp[nb * 68 + q + ko * 8];
                blf[1] = KLp[nb * 68 + q + 4 + ko * 8];
                mma_bf16(s[ni], qh, bhf);
                mma_bf16(s[ni], qh, blf);
                mma_bf16(s[ni], ql, bhf);
            }
        }

#pragma unroll
        for (int ni = 0; ni < 8; ni++)
#pragma unroll
            for (int e = 0; e < 4; e++) s[ni][e] *= scale;

        if (jt == qt) {
            int rbase = qt * 64 + w * 16 + g;
#pragma unroll
            for (int ni = 0; ni < 8; ni++) {
                int cbase = jt * 64 + ni * 8 + 2 * q;
#pragma unroll
                for (int e = 0; e < 4; e++) {
                    int row = rbase + (e >= 2 ? 8 : 0);
                    int col = cbase + (e & 1);
                    if (col > row) s[ni][e] = -1e30f;
                }
            }
        }

        float mt[2] = {-1e30f, -1e30f};
#pragma unroll
        for (int ni = 0; ni < 8; ni++) {
            mt[0] = fmaxf(mt[0], fmaxf(s[ni][0], s[ni][1]));
            mt[1] = fmaxf(mt[1], fmaxf(s[ni][2], s[ni][3]));
        }
#pragma unroll
        for (int d = 1; d <= 2; d <<= 1) {
            mt[0] = fmaxf(mt[0], __shfl_xor_sync(0xFFFFFFFFu, mt[0], d));
            mt[1] = fmaxf(mt[1], __shfl_xor_sync(0xFFFFFFFFu, mt[1], d));
        }
        float mn[2] = {fmaxf(mrow[0], mt[0]), fmaxf(mrow[1], mt[1])};
        float corr[2] = {__expf(mrow[0] - mn[0]), __expf(mrow[1] - mn[1])};

        float rs[2] = {0.f, 0.f};
#pragma unroll
        for (int ni = 0; ni < 8; ni++) {
#pragma unroll
            for (int e = 0; e < 4; e++) {
                float pv = __expf(s[ni][e] - mn[e >> 1]);
                s[ni][e] = pv;
                rs[e >> 1] += pv;
            }
        }
#pragma unroll
        for (int d = 1; d <= 2; d <<= 1) {
            rs[0] += __shfl_xor_sync(0xFFFFFFFFu, rs[0], d);
            rs[1] += __shfl_xor_sync(0xFFFFFFFFu, rs[1], d);
        }
        lrow[0] = lrow[0] * corr[0] + rs[0];
        lrow[1] = lrow[1] * corr[1] + rs[1];
        mrow[0] = mn[0];
        mrow[1] = mn[1];
#pragma unroll
        for (int ni = 0; ni < 16; ni++) {
            o[ni][0] *= corr[0]; o[ni][1] *= corr[0];
            o[ni][2] *= corr[1]; o[ni][3] *= corr[1];
        }

#pragma unroll
        for (int kp = 0; kp < 4; kp++) {
            unsigned ph[4], pl[4];
            split_pair(s[2*kp][0],   s[2*kp][1],   ph[0], pl[0]);
            split_pair(s[2*kp][2],   s[2*kp][3],   ph[1], pl[1]);
            split_pair(s[2*kp+1][0], s[2*kp+1][1], ph[2], pl[2]);
            split_pair(s[2*kp+1][2], s[2*kp+1][3], ph[3], pl[3]);
#pragma unroll
            for (int ni = 0; ni < 16; ni++) {
                int nb = ni * 8 + g;
                unsigned bhf[2], blf[2];
                bhf[0] = VHp[(q + kp * 8) * 136 + nb];
                bhf[1] = VHp[(q + 4 + kp * 8) * 136 + nb];
                blf[0] = VLp[(q + kp * 8) * 136 + nb];
                blf[1] = VLp[(q + 4 + kp * 8) * 136 + nb];
                mma_bf16(o[ni], ph, bhf);
                mma_bf16(o[ni], ph, blf);
                mma_bf16(o[ni], pl, bhf);
            }
        }

        if (more) {
            stsV(p ^ 1);
            cp_wait<0>();
        }
        __syncthreads();
    }

    float inv[2] = {1.f / lrow[0], 1.f / lrow[1]};
    int rbase = qt * 64 + w * 16 + g;
#pragma unroll
    for (int ni = 0; ni < 16; ni++) {
        int cb = h * DHEAD + ni * 8 + 2 * q;
#pragma unroll
        for (int half = 0; half < 2; half++) {
            int row = rbase + half * 8;
            if (row >= NTOK) continue;
            unsigned hw, lw;
            split_pair(o[ni][half*2] * inv[half], o[ni][half*2+1] * inv[half], hw, lw);
            size_t wi = (size_t)(b * NTOK + row) * (DIMM / 2) + (cb >> 1);
            OH[wi] = hw;
            OL[wi] = lw;
        }
    }
}

// ---------------- small kernels ----------------
__global__ void save_cls_kernel(const float* __restrict__ gx, float* __restrict__ gcls)
{
    int idx = blockIdx.x * blockDim.x + threadIdx.x;
    if (idx >= BATCH * DIMM) return;
    int b = idx / DIMM, d = idx % DIMM;
    gcls[idx] = gx[((size_t)b * NTOK) * DIMM + d];
}

__global__ void write_out_kernel(const float* __restrict__ gx,
                                 const float* __restrict__ gcls,
                                 float* __restrict__ out)
{
    const int totalx = MROWS * DIMM;
    const int totalc = BATCH * DIMM;
    int idx = blockIdx.x * blockDim.x + threadIdx.x;
    if (idx < totalx)               out[idx] = gx[idx];
    else if (idx < totalx + totalc) out[idx] = gcls[idx - totalx];
}

// ---------------- host orchestration ----------------
struct DevPtrs {
    float *gx, *gcls;
    unsigned *xsh, *xsl, *ash, *asl, *hsh, *hsl, *qsh, *qsl;
    unsigned *wqh, *wql, *woh, *wol, *w1h, *w1l, *w2h, *w2l;
};

static void run_layer(int l, const DevPtrs& P,
                      const float* bo, const float* b1, const float* b2)
{
    const int gy = (MROWS + 127) / 128;  // 33
    tgemm_kernel<false,false,false,false,true><<<dim3(24, gy), 256, SM_TOTAL>>>(
        P.xsh, P.xsl, P.wqh + (size_t)l*WQKV_L, P.wql + (size_t)l*WQKV_L,
        nullptr, nullptr, nullptr, P.qsh, P.qsl, MROWS, DIMM, 3*DIMM);
    fattn_kernel<<<dim3(33, BATCH*NHEADS), 128, ATT_SMEM>>>(P.qsh, P.qsl, P.ash, P.asl);
    tgemm_kernel<true,true,false,true,true><<<dim3(8, gy), 256, SM_TOTAL>>>(
        P.ash, P.asl, P.woh + (size_t)l*WO_L, P.wol + (size_t)l*WO_L,
        bo, P.gx, P.gx, P.xsh, P.xsl, MROWS, DIMM, DIMM);
    tgemm_kernel<true,false,true,false,true><<<dim3(32, gy), 256, SM_TOTAL>>>(
        P.xsh, P.xsl, P.w1h + (size_t)l*W1_L, P.w1l + (size_t)l*W1_L,
        b1, nullptr, nullptr, P.hsh, P.hsl, MROWS, DIMM, HID);
    tgemm_kernel<true,true,false,true,true><<<dim3(8, gy), 256, SM_TOTAL>>>(
        P.hsh, P.hsl, P.w2h + (size_t)l*W2_L, P.w2l + (size_t)l*W2_L,
        b2, P.gx, P.gx, P.xsh, P.xsl, MROWS, HID, DIMM);
}

extern "C" void kernel_launch(void* const* d_in, const int* in_sizes, int n_in,
                              void* d_out, int out_size)
{
    const float* x_in = (const float*)d_in[0];
    const float* cls  = (const float*)d_in[1];
    const float* hW[7];
    const float* tW[7];
    for (int i = 0; i < 7; i++) hW[i] = (const float*)d_in[2 + i];
    for (int i = 0; i < 7; i++) tW[i] = (const float*)d_in[9 + i];

    cudaFuncSetAttribute(tgemm_kernel<false,false,false,false,true>,
                         cudaFuncAttributeMaxDynamicSharedMemorySize, SM_TOTAL);
    cudaFuncSetAttribute(tgemm_kernel<true,true,false,true,true>,
                         cudaFuncAttributeMaxDynamicSharedMemorySize, SM_TOTAL);
    cudaFuncSetAttribute(tgemm_kernel<true,false,true,false,true>,
                         cudaFuncAttributeMaxDynamicSharedMemorySize, SM_TOTAL);
    cudaFuncSetAttribute(fattn_kernel,
                         cudaFuncAttributeMaxDynamicSharedMemorySize, ATT_SMEM);

    DevPtrs P;
    cudaGetSymbolAddress((void**)&P.gx,   g_x);
    cudaGetSymbolAddress((void**)&P.gcls, g_cls);
    cudaGetSymbolAddress((void**)&P.xsh,  g_xs_h);
    cudaGetSymbolAddress((void**)&P.xsl,  g_xs_l);
    cudaGetSymbolAddress((void**)&P.ash,  g_as_h);
    cudaGetSymbolAddress((void**)&P.asl,  g_as_l);
    cudaGetSymbolAddress((void**)&P.hsh,  g_hs_h);
    cudaGetSymbolAddress((void**)&P.hsl,  g_hs_l);
    cudaGetSymbolAddress((void**)&P.qsh,  g_qs_h);
    cudaGetSymbolAddress((void**)&P.qsl,  g_qs_l);
    cudaGetSymbolAddress((void**)&P.wqh,  g_wqkv_h);
    cudaGetSymbolAddress((void**)&P.wql,  g_wqkv_l);
    cudaGetSymbolAddress((void**)&P.woh,  g_wo_h);
    cudaGetSymbolAddress((void**)&P.wol,  g_wo_l);
    cudaGetSymbolAddress((void**)&P.w1h,  g_w1_h);
    cudaGetSymbolAddress((void**)&P.w1l,  g_w1_l);
    cudaGetSymbolAddress((void**)&P.w2h,  g_w2_h);
    cudaGetSymbolAddress((void**)&P.w2l,  g_w2_l);

    // pre-split all weights into frag-pair layout (once per launch)
    split_w2_kernel<<<dim3(3072/256, 1024/16, 8), 256>>>(hW[0], tW[0], P.wqh, P.wql, 1024, 3072);
    split_w2_kernel<<<dim3(1024/256, 1024/16, 8), 256>>>(hW[1], tW[1], P.woh, P.wol, 1024, 1024);
    split_w2_kernel<<<dim3(4096/256, 1024/16, 8), 256>>>(hW[3], tW[3], P.w1h, P.w1l, 1024, 4096);
    split_w2_kernel<<<dim3(1024/256, 4096/16, 8), 256>>>(hW[5], tW[5], P.w2h, P.w2l, 4096, 1024);

    {
        int total = MROWS * DIMM / 2;
        concat_kernel<<<(total + 255) / 256, 256>>>(x_in, cls, P.gx, P.xsh, P.xsl);
    }

    for (int l = 0; l < L_HEAD; l++)
        run_layer(l, P, hW[2] + (size_t)l*DIMM, hW[4] + (size_t)l*HID, hW[6] + (size_t)l*DIMM);

    save_cls_kernel<<<(BATCH*DIMM + 255)/256, 256>>>(P.gx, P.gcls);

    for (int l = 0; l < L_TAIL; l++)
        run_layer(4 + l, P, tW[2] + (size_t)l*DIMM, tW[4] + (size_t)l*HID, tW[6] + (size_t)l*DIMM);

    {
        int total = MROWS * DIMM + BATCH * DIMM;
        write_out_kernel<<<(total + 255)/256, 256>>>(P.gx, P.gcls, (float*)d_out);
    }
}